// round 3
// baseline (speedup 1.0000x reference)
#include <cuda_runtime.h>
#include <math.h>
#include <stdint.h>

// Problem constants
#define BB   4
#define NQ   1024     // N
#define MM   512      // M (context len)
#define DD   512      // D
#define PP   256      // P
#define HH   8
#define DH   64
#define LL   6
#define FFI  2048
#define RR   (BB*NQ)        // 4096 rows of x
#define CR   (BB*MM)        // 2048 rows of context
#define SLD  1028           // scores row stride (>= 1025, mult of 4)

// ---------------- scratch (static device globals; no allocation) ----------
__device__ float g_x   [RR*DD];
__device__ float g_xn  [RR*DD];
__device__ float g_ctxn[CR*PP];
__device__ float g_q   [RR*DD];
__device__ float g_kv  [RR*128];
__device__ float g_k   [BB*(NQ+1)*DH];
__device__ float g_v   [BB*(NQ+1)*DH];
__device__ float g_att [RR*DD];
__device__ float g_hh  [(size_t)RR*FFI];
__device__ float g_hg  [(size_t)RR*2*FFI];
__device__ float g_sc  [(size_t)BB*HH*NQ*SLD];

// ---------------- reductions (blockDim == 256) -----------------------------
__device__ __forceinline__ float warpSum(float v){
    #pragma unroll
    for (int o=16;o;o>>=1) v += __shfl_xor_sync(0xffffffffu, v, o);
    return v;
}
__device__ __forceinline__ float warpMax(float v){
    #pragma unroll
    for (int o=16;o;o>>=1) v = fmaxf(v, __shfl_xor_sync(0xffffffffu, v, o));
    return v;
}
__device__ float blockSum(float v){
    __shared__ float sh[8];
    int lane = threadIdx.x & 31, w = threadIdx.x >> 5;
    v = warpSum(v);
    if (lane == 0) sh[w] = v;
    __syncthreads();
    v = (threadIdx.x < 8) ? sh[threadIdx.x] : 0.f;
    v = warpSum(v);
    if (threadIdx.x == 0) sh[0] = v;
    __syncthreads();
    float r = sh[0];
    __syncthreads();
    return r;
}
__device__ float blockMax(float v){
    __shared__ float sh[8];
    int lane = threadIdx.x & 31, w = threadIdx.x >> 5;
    v = warpMax(v);
    if (lane == 0) sh[w] = v;
    __syncthreads();
    v = (threadIdx.x < 8) ? sh[threadIdx.x] : -3.4e38f;
    v = warpMax(v);
    if (threadIdx.x == 0) sh[0] = v;
    __syncthreads();
    float r = sh[0];
    __syncthreads();
    return r;
}

// ---------------- elementwise kernels --------------------------------------
__global__ void copy_kernel(const float* __restrict__ in, float* __restrict__ out, int n){
    for (int i = blockIdx.x*blockDim.x + threadIdx.x; i < n; i += gridDim.x*blockDim.x)
        out[i] = in[i];
}
__global__ void add_kernel(float* __restrict__ x, const float* __restrict__ y, int n){
    for (int i = blockIdx.x*blockDim.x + threadIdx.x; i < n; i += gridDim.x*blockDim.x)
        x[i] += y[i];
}
__global__ void glu_kernel(const float* __restrict__ hg, float* __restrict__ out){
    // hg: [RR, 2*FFI]; out: [RR, FFI]; out = h * silu(gate)
    long total = (long)RR * FFI;
    for (long i = blockIdx.x*(long)blockDim.x + threadIdx.x; i < total; i += gridDim.x*(long)blockDim.x){
        long r = i / FFI; int c = (int)(i - r*FFI);
        float h = hg[r*(2*FFI) + c];
        float g = hg[r*(2*FFI) + FFI + c];
        out[i] = h * (g / (1.f + expf(-g)));
    }
}

// ---------------- layernorm family (1 block / row, 256 thr, cols<=512) -----
__global__ __launch_bounds__(256) void ln_kernel(const float* __restrict__ in,
                                                 const float* __restrict__ g,
                                                 float* __restrict__ out, int cols){
    long ro = (long)blockIdx.x * cols;
    int t = threadIdx.x;
    float v0 = (t       < cols) ? in[ro + t]       : 0.f;
    float v1 = (t + 256 < cols) ? in[ro + t + 256] : 0.f;
    float mu = blockSum(v0 + v1) / (float)cols;
    float d0 = (t       < cols) ? v0 - mu : 0.f;
    float d1 = (t + 256 < cols) ? v1 - mu : 0.f;
    float var = blockSum(d0*d0 + d1*d1) / (float)cols;
    float inv = 1.f / sqrtf(var + 1e-5f);
    if (t       < cols) out[ro + t]       = d0 * inv * g[t];
    if (t + 256 < cols) out[ro + t + 256] = d1 * inv * g[t + 256];
}
__global__ __launch_bounds__(256) void ln_res_kernel(const float* __restrict__ in,
                                                     const float* __restrict__ g,
                                                     float* __restrict__ x, int cols){
    long ro = (long)blockIdx.x * cols;
    int t = threadIdx.x;
    float v0 = (t       < cols) ? in[ro + t]       : 0.f;
    float v1 = (t + 256 < cols) ? in[ro + t + 256] : 0.f;
    float mu = blockSum(v0 + v1) / (float)cols;
    float d0 = (t       < cols) ? v0 - mu : 0.f;
    float d1 = (t + 256 < cols) ? v1 - mu : 0.f;
    float var = blockSum(d0*d0 + d1*d1) / (float)cols;
    float inv = 1.f / sqrtf(var + 1e-5f);
    if (t       < cols) x[ro + t]       += d0 * inv * g[t];
    if (t + 256 < cols) x[ro + t + 256] += d1 * inv * g[t + 256];
}
__global__ __launch_bounds__(256) void final_ln_kernel(const float* __restrict__ in,
                                                       const float* __restrict__ g,
                                                       float* __restrict__ out, int cols){
    long ro = (long)blockIdx.x * cols;
    int t = threadIdx.x;
    float v0 = (t       < cols) ? in[ro + t]       : 0.f;
    float v1 = (t + 256 < cols) ? in[ro + t + 256] : 0.f;
    float m0 = (t       < cols) ? v0 : -3.4e38f;
    float m1 = (t + 256 < cols) ? v1 : -3.4e38f;
    float mx = blockMax(fmaxf(m0, m1));
    v0 /= mx; v1 /= mx;
    float s0 = (t       < cols) ? v0 : 0.f;
    float s1 = (t + 256 < cols) ? v1 : 0.f;
    float mu = blockSum(s0 + s1) / (float)cols;
    float d0 = (t       < cols) ? v0 - mu : 0.f;
    float d1 = (t + 256 < cols) ? v1 - mu : 0.f;
    float var = blockSum(d0*d0 + d1*d1) / (float)cols;
    float inv = 1.f / sqrtf(var + 1e-5f);
    if (t       < cols) out[ro + t]       = d0 * inv * g[t];
    if (t + 256 < cols) out[ro + t + 256] = d1 * inv * g[t + 256];
}

// ---------------- rotary / prep --------------------------------------------
__device__ __forceinline__ float inv_freq(int m){
    // 1 / 10000^(m/16)
    return powf(10000.f, -(float)m * (1.f/16.f));
}
// q: [RR, 512]; scale by DH^-0.5; rotary on first 32 dims of each head
__global__ __launch_bounds__(256) void qprep_kernel(float* __restrict__ q, int n, int use_rot){
    int idx = blockIdx.x * 256 + threadIdx.x;
    int row = idx >> 8;           // 256 work-items per row (8 heads * 32)
    int r   = idx & 255;
    int h = r >> 5, t = r & 31;
    float* p = q + (long)row * DD + h * DH;
    const float sc = 0.125f;      // 64^-0.5
    if (t < 16){
        float a = p[t] * sc, b = p[t+16] * sc;
        if (use_rot){
            float f = (float)(row % n) * inv_freq(t);
            float cf = cosf(f), sf = sinf(f);
            p[t]    = a*cf - b*sf;
            p[t+16] = a*sf + b*cf;
        } else { p[t] = a; p[t+16] = b; }
    } else {
        p[t+16] *= sc;
        p[t+32] *= sc;
    }
}
// kv: [B*nk, 128] -> k/v buffers [B, nk+1, 64] with null at j=0; rotary on k
__global__ __launch_bounds__(64) void kvprep_kernel(const float* __restrict__ kv,
                                                    const float* __restrict__ null_kv,
                                                    float* __restrict__ kbuf, float* __restrict__ vbuf,
                                                    int nk, int use_rot){
    int rblk = blockIdx.x;
    int d = threadIdx.x;
    int nkv = nk + 1;
    int b = rblk / nkv, j = rblk % nkv;
    long doff = ((long)b * nkv + j) * DH + d;
    if (j == 0){
        kbuf[doff] = null_kv[d];
        vbuf[doff] = null_kv[DH + d];
        return;
    }
    int i = j - 1;
    const float* src = kv + ((long)b * nk + i) * 128;
    float kval = src[d];
    float vval = src[DH + d];
    if (use_rot && d < 32){
        int m = d & 15;
        float f = (float)i * inv_freq(m);
        float cf = cosf(f), sf = sinf(f);
        if (d < 16) kval = kval*cf - src[d+16]*sf;
        else        kval = kval*cf + src[d-16]*sf;
    }
    kbuf[doff] = kval;
    vbuf[doff] = vval;
}

// ---------------- TF32x3 tensor-core GEMM ----------------------------------
// C = A(MxK) @ B(KxN), row-major, M%128==0, N%128==0, K%16==0.
// fp32 emulated via hi/lo tf32 split: a*b ~= ah*bh + ah*bl + al*bh.
__device__ __forceinline__ float2 split_tf32(float x){
    unsigned hu, lu;
    asm("cvt.rna.tf32.f32 %0, %1;" : "=r"(hu) : "f"(x));
    float hf = __uint_as_float(hu);
    float lo = x - hf;
    asm("cvt.rna.tf32.f32 %0, %1;" : "=r"(lu) : "f"(lo));
    float2 r; r.x = hf; r.y = __uint_as_float(lu);
    return r;
}
__device__ __forceinline__ void mma_tf32(float* d, unsigned a0, unsigned a1, unsigned a2, unsigned a3,
                                         unsigned b0, unsigned b1){
    asm volatile("mma.sync.aligned.m16n8k8.row.col.f32.tf32.tf32.f32 "
                 "{%0,%1,%2,%3}, {%4,%5,%6,%7}, {%8,%9}, {%0,%1,%2,%3};\n"
                 : "+f"(d[0]), "+f"(d[1]), "+f"(d[2]), "+f"(d[3])
                 : "r"(a0), "r"(a1), "r"(a2), "r"(a3), "r"(b0), "r"(b1));
}

#define LDT 132   // float2 stride per k-row (pad for conflict-free LDS.64)

__global__ __launch_bounds__(256) void tgemm128(const float* __restrict__ A,
                                                const float* __restrict__ Bm,
                                                float* __restrict__ C,
                                                int M, int N, int K){
    __shared__ float2 AsHL[16][LDT];   // [k][m] (hi,lo)
    __shared__ float2 BsHL[16][LDT];   // [k][n] (hi,lo)
    int t    = threadIdx.x;
    int lane = t & 31, warp = t >> 5;
    int wm = (warp >> 2) * 64;        // 2 warp-rows
    int wn = (warp & 3) * 32;         // 4 warp-cols
    int g  = lane >> 2, tg = lane & 3;
    int rowBase = blockIdx.y * 128, colBase = blockIdx.x * 128;

    float d[4][4][4];
    #pragma unroll
    for (int i=0;i<4;i++)
        #pragma unroll
        for (int j=0;j<4;j++)
            #pragma unroll
            for (int e=0;e<4;e++) d[i][j][e] = 0.f;

    float4 ra[2], rb[2];

    // loader: A tile 128x16 (512 float4), B tile 16x128 (512 float4)
    #define LOADG(k0)                                                              \
        {                                                                          \
            _Pragma("unroll")                                                      \
            for (int i=0;i<2;i++){                                                 \
                int f = t*2 + i;                                                   \
                ra[i] = *(const float4*)(A + (long)(rowBase + (f>>2))*K + (k0) + (f&3)*4); \
                rb[i] = *(const float4*)(Bm + (long)((k0) + (f>>5))*N + colBase + (f&31)*4); \
            }                                                                      \
        }
    #define STORES()                                                               \
        {                                                                          \
            _Pragma("unroll")                                                      \
            for (int i=0;i<2;i++){                                                 \
                int f = t*2 + i;                                                   \
                int ar = f>>2, ac = (f&3)*4;                                       \
                AsHL[ac+0][ar] = split_tf32(ra[i].x);                              \
                AsHL[ac+1][ar] = split_tf32(ra[i].y);                              \
                AsHL[ac+2][ar] = split_tf32(ra[i].z);                              \
                AsHL[ac+3][ar] = split_tf32(ra[i].w);                              \
                int br = f>>5, bc = (f&31)*4;                                      \
                BsHL[br][bc+0] = split_tf32(rb[i].x);                              \
                BsHL[br][bc+1] = split_tf32(rb[i].y);                              \
                BsHL[br][bc+2] = split_tf32(rb[i].z);                              \
                BsHL[br][bc+3] = split_tf32(rb[i].w);                              \
            }                                                                      \
        }

    LOADG(0);
    STORES();
    __syncthreads();

    int nk = K >> 4;
    for (int it = 0; it < nk; it++){
        if (it + 1 < nk) LOADG((it+1) << 4);
        #pragma unroll
        for (int kk = 0; kk < 16; kk += 8){
            uint2 af[4][4];
            uint2 bf[4][2];
            #pragma unroll
            for (int mt=0; mt<4; mt++){
                int m = wm + mt*16 + g;
                af[mt][0] = *(const uint2*)&AsHL[kk+tg  ][m  ];
                af[mt][1] = *(const uint2*)&AsHL[kk+tg  ][m+8];
                af[mt][2] = *(const uint2*)&AsHL[kk+tg+4][m  ];
                af[mt][3] = *(const uint2*)&AsHL[kk+tg+4][m+8];
            }
            #pragma unroll
            for (int nt=0; nt<4; nt++){
                int n = wn + nt*8 + g;
                bf[nt][0] = *(const uint2*)&BsHL[kk+tg  ][n];
                bf[nt][1] = *(const uint2*)&BsHL[kk+tg+4][n];
            }
            #pragma unroll
            for (int mt=0; mt<4; mt++){
                #pragma unroll
                for (int nt=0; nt<4; nt++){
                    float* acc = d[mt][nt];
                    // hi*hi
                    mma_tf32(acc, af[mt][0].x, af[mt][1].x, af[mt][2].x, af[mt][3].x,
                             bf[nt][0].x, bf[nt][1].x);
                    // hi*lo
                    mma_tf32(acc, af[mt][0].x, af[mt][1].x, af[mt][2].x, af[mt][3].x,
                             bf[nt][0].y, bf[nt][1].y);
                    // lo*hi
                    mma_tf32(acc, af[mt][0].y, af[mt][1].y, af[mt][2].y, af[mt][3].y,
                             bf[nt][0].x, bf[nt][1].x);
                }
            }
        }
        __syncthreads();
        if (it + 1 < nk){
            STORES();
            __syncthreads();
        }
    }

    // epilogue
    #pragma unroll
    for (int mt=0; mt<4; mt++){
        int r0 = rowBase + wm + mt*16 + g;
        #pragma unroll
        for (int nt=0; nt<4; nt++){
            int c0 = colBase + wn + nt*8 + tg*2;
            float2* p0 = (float2*)(C + (long)r0*N + c0);
            float2* p1 = (float2*)(C + (long)(r0+8)*N + c0);
            float2 v0; v0.x = d[mt][nt][0]; v0.y = d[mt][nt][1];
            float2 v1; v1.x = d[mt][nt][2]; v1.y = d[mt][nt][3];
            *p0 = v0;
            *p1 = v1;
        }
    }
    #undef LOADG
    #undef STORES
}

// ---------------- attention: scores = q@k^T (+bias, mask) ------------------
__global__ __launch_bounds__(256) void scores_kernel(const float* __restrict__ q,
                                                     const float* __restrict__ kbuf,
                                                     const float* __restrict__ rel_emb,
                                                     float* __restrict__ scores,
                                                     int nq, int nkv, int cb){
    __shared__ float Qs[64][64];  // [d][i]
    __shared__ float Ks[64][64];  // [d][j]
    int t  = threadIdx.x;
    int bh = blockIdx.z, b = bh >> 3, h = bh & 7;
    int i0 = blockIdx.y * 64, j0 = blockIdx.x * 64;
    #pragma unroll
    for (int n=0;n<4;n++){
        int fi = t + n*256;
        int r = fi >> 4, c4 = fi & 15;
        float4 v = *(const float4*)(q + ((long)(b*nq + i0 + r))*DD + h*DH + c4*4);
        Qs[c4*4+0][r]=v.x; Qs[c4*4+1][r]=v.y; Qs[c4*4+2][r]=v.z; Qs[c4*4+3][r]=v.w;
        int j = j0 + r;
        float4 w = make_float4(0.f,0.f,0.f,0.f);
        if (j < nkv) w = *(const float4*)(kbuf + ((long)b*nkv + j)*DH + c4*4);
        Ks[c4*4+0][r]=w.x; Ks[c4*4+1][r]=w.y; Ks[c4*4+2][r]=w.z; Ks[c4*4+3][r]=w.w;
    }
    __syncthreads();
    int tx = t & 15, ty = t >> 4;
    float acc[4][4];
    #pragma unroll
    for (int i=0;i<4;i++)
        #pragma unroll
        for (int j=0;j<4;j++) acc[i][j]=0.f;
    #pragma unroll 4
    for (int d=0; d<64; d++){
        float a[4], bb[4];
        *(float4*)a  = *(const float4*)&Qs[d][ty*4];
        *(float4*)bb = *(const float4*)&Ks[d][tx*4];
        #pragma unroll
        for (int i=0;i<4;i++)
            #pragma unroll
            for (int j=0;j<4;j++) acc[i][j] = fmaf(a[i], bb[j], acc[i][j]);
    }
    #pragma unroll
    for (int ii=0;ii<4;ii++){
        int i = i0 + ty*4 + ii;
        #pragma unroll
        for (int jj=0;jj<4;jj++){
            int j = j0 + tx*4 + jj;
            if (j >= nkv) continue;
            float s = acc[ii][jj];
            if (cb){
                int nn = i - j; if (nn < 0) nn = 0;
                int bucket;
                if (nn < 16) bucket = nn;
                else {
                    int large = 16 + (int)(logf((float)nn * 0.0625f) * (16.0f / 2.0794415416798357f));
                    bucket = large < 31 ? large : 31;
                }
                s += rel_emb[bucket*HH + h];
                if (j > i + 1) s = -1e30f;   // causal mask (j <= i+1 allowed)
            }
            scores[((long)bh*nq + i)*SLD + j] = s;
        }
    }
}

// ---------------- softmax over rows of scores -------------------------------
__global__ __launch_bounds__(256) void softmax_kernel(float* __restrict__ scores, int nkv){
    long off = (long)blockIdx.x * SLD;
    int t = threadIdx.x;
    float v[5];
    int cnt = 0;
    float mx = -3.4e38f;
    for (int j = t; j < nkv; j += 256){ v[cnt] = scores[off + j]; mx = fmaxf(mx, v[cnt]); cnt++; }
    mx = blockMax(mx);
    float s = 0.f;
    for (int c=0;c<cnt;c++){ v[c] = expf(v[c] - mx); s += v[c]; }
    s = blockSum(s);
    float inv = 1.f / s;
    cnt = 0;
    for (int j = t; j < nkv; j += 256) scores[off + j] = v[cnt++] * inv;
}

// ---------------- out = attn @ v, scattered into [B*N, 512] ----------------
__global__ __launch_bounds__(256) void av_kernel(const float* __restrict__ scores,
                                                 const float* __restrict__ vbuf,
                                                 float* __restrict__ out,
                                                 int nq, int nkv){
    __shared__ float Ps[16][64];  // [k][i]
    __shared__ float Vs[16][64];  // [k][d]
    int t  = threadIdx.x;
    int bh = blockIdx.z, b = bh >> 3, h = bh & 7;
    int i0 = blockIdx.y * 64;
    int tx = t & 15, ty = t >> 4;
    const float* srow = scores + (long)bh * nq * SLD;
    float acc[4][4];
    #pragma unroll
    for (int i=0;i<4;i++)
        #pragma unroll
        for (int j=0;j<4;j++) acc[i][j]=0.f;
    for (int k0 = 0; k0 < nkv; k0 += 16){
        int pr = t >> 2, pc = (t & 3)*4;
        #pragma unroll
        for (int e=0;e<4;e++){
            int kk = k0 + pc + e;
            Ps[pc+e][pr] = (kk < nkv) ? srow[(long)(i0 + pr)*SLD + kk] : 0.f;
        }
        int vr = t >> 4, vc4 = t & 15;
        int kk2 = k0 + vr;
        float4 w = make_float4(0.f,0.f,0.f,0.f);
        if (kk2 < nkv) w = *(const float4*)(vbuf + ((long)b*nkv + kk2)*DH + vc4*4);
        *(float4*)&Vs[vr][vc4*4] = w;
        __syncthreads();
        #pragma unroll
        for (int kk=0;kk<16;kk++){
            float a[4], bb[4];
            *(float4*)a  = *(const float4*)&Ps[kk][ty*4];
            *(float4*)bb = *(const float4*)&Vs[kk][tx*4];
            #pragma unroll
            for (int i=0;i<4;i++)
                #pragma unroll
                for (int j=0;j<4;j++) acc[i][j] = fmaf(a[i], bb[j], acc[i][j]);
        }
        __syncthreads();
    }
    #pragma unroll
    for (int ii=0;ii<4;ii++)
        #pragma unroll
        for (int jj=0;jj<4;jj++)
            out[((long)(b*nq + i0 + ty*4 + ii))*DD + h*DH + tx*4 + jj] = acc[ii][jj];
}

// ---------------- orchestration --------------------------------------------
extern "C" void kernel_launch(void* const* d_in, const int* in_sizes, int n_in,
                              void* d_out, int out_size){
    const float* x_in    = (const float*)d_in[0];
    const float* ctx     = (const float*)d_in[1];
    const float* rel_emb = (const float*)d_in[2];
    const float* sa_ng   = (const float*)d_in[3];
    const float* sa_wq   = (const float*)d_in[4];
    const float* sa_wkv  = (const float*)d_in[5];
    const float* sa_null = (const float*)d_in[6];
    const float* sa_wo   = (const float*)d_in[7];
    const float* sa_og   = (const float*)d_in[8];
    const float* ca_ng   = (const float*)d_in[9];
    const float* ca_cg   = (const float*)d_in[10];
    const float* ca_wq   = (const float*)d_in[11];
    const float* ca_wkv  = (const float*)d_in[12];
    const float* ca_null = (const float*)d_in[13];
    const float* ca_wo   = (const float*)d_in[14];
    const float* ca_og   = (const float*)d_in[15];
    const float* ff_ng   = (const float*)d_in[16];
    const float* ff_w1   = (const float*)d_in[17];
    const float* ff_w2   = (const float*)d_in[18];
    const float* normg   = (const float*)d_in[19];
    float* out = (float*)d_out;

    float *X,*XN,*CTXN,*Q,*KV,*K_,*V_,*ATT,*HHp,*HG,*SC;
    cudaGetSymbolAddress((void**)&X,    g_x);
    cudaGetSymbolAddress((void**)&XN,   g_xn);
    cudaGetSymbolAddress((void**)&CTXN, g_ctxn);
    cudaGetSymbolAddress((void**)&Q,    g_q);
    cudaGetSymbolAddress((void**)&KV,   g_kv);
    cudaGetSymbolAddress((void**)&K_,   g_k);
    cudaGetSymbolAddress((void**)&V_,   g_v);
    cudaGetSymbolAddress((void**)&ATT,  g_att);
    cudaGetSymbolAddress((void**)&HHp,  g_hh);
    cudaGetSymbolAddress((void**)&HG,   g_hg);
    cudaGetSymbolAddress((void**)&SC,   g_sc);

    copy_kernel<<<512, 256>>>(x_in, X, RR*DD);

    for (int l = 0; l < LL; l++){
        // ---------------- self-attention ----------------
        ln_kernel<<<RR, 256>>>(X, sa_ng + l*DD, XN, DD);
        tgemm128<<<dim3(DD/128, RR/128), 256>>>(XN, sa_wq + (size_t)l*DD*DD, Q, RR, DD, DD);
        tgemm128<<<dim3(1, RR/128), 256>>>(XN, sa_wkv + (size_t)l*DD*128, KV, RR, 128, DD);
        qprep_kernel<<<RR, 256>>>(Q, NQ, 1);
        kvprep_kernel<<<BB*(NQ+1), 64>>>(KV, sa_null + l*128, K_, V_, NQ, 1);
        scores_kernel<<<dim3((NQ+1+63)/64, NQ/64, BB*HH), 256>>>(Q, K_, rel_emb, SC, NQ, NQ+1, 1);
        softmax_kernel<<<BB*HH*NQ, 256>>>(SC, NQ+1);
        av_kernel<<<dim3(1, NQ/64, BB*HH), 256>>>(SC, V_, ATT, NQ, NQ+1);
        tgemm128<<<dim3(DD/128, RR/128), 256>>>(ATT, sa_wo + (size_t)l*DD*DD, Q, RR, DD, DD);
        ln_res_kernel<<<RR, 256>>>(Q, sa_og + l*DD, X, DD);

        // ---------------- cross-attention ----------------
        ln_kernel<<<RR, 256>>>(X, ca_ng + l*DD, XN, DD);
        ln_kernel<<<CR, 256>>>(ctx, ca_cg + l*PP, CTXN, PP);
        tgemm128<<<dim3(DD/128, RR/128), 256>>>(XN, ca_wq + (size_t)l*DD*DD, Q, RR, DD, DD);
        tgemm128<<<dim3(1, CR/128), 256>>>(CTXN, ca_wkv + (size_t)l*PP*128, KV, CR, 128, PP);
        qprep_kernel<<<RR, 256>>>(Q, NQ, 0);
        kvprep_kernel<<<BB*(MM+1), 64>>>(KV, ca_null + l*128, K_, V_, MM, 0);
        scores_kernel<<<dim3((MM+1+63)/64, NQ/64, BB*HH), 256>>>(Q, K_, rel_emb, SC, NQ, MM+1, 0);
        softmax_kernel<<<BB*HH*NQ, 256>>>(SC, MM+1);
        av_kernel<<<dim3(1, NQ/64, BB*HH), 256>>>(SC, V_, ATT, NQ, MM+1);
        tgemm128<<<dim3(DD/128, RR/128), 256>>>(ATT, ca_wo + (size_t)l*DD*DD, Q, RR, DD, DD);
        ln_res_kernel<<<RR, 256>>>(Q, ca_og + l*DD, X, DD);

        // ---------------- feed-forward (SwiGLU) ----------------
        ln_kernel<<<RR, 256>>>(X, ff_ng + l*DD, XN, DD);
        tgemm128<<<dim3((2*FFI)/128, RR/128), 256>>>(XN, ff_w1 + (size_t)l*DD*2*FFI, HG, RR, 2*FFI, DD);
        glu_kernel<<<2048, 256>>>(HG, HHp);
        tgemm128<<<dim3(DD/128, RR/128), 256>>>(HHp, ff_w2 + (size_t)l*FFI*DD, Q, RR, DD, FFI);
        add_kernel<<<1024, 256>>>(X, Q, RR*DD);
    }

    final_ln_kernel<<<RR, 256>>>(X, normg, out, DD);
}

// round 5
// speedup vs baseline: 1.4539x; 1.4539x over previous
#include <cuda_runtime.h>
#include <cuda_bf16.h>
#include <math.h>
#include <stdint.h>

// Problem constants
#define BB   4
#define NQ   1024
#define MM   512
#define DD   512
#define PP   256
#define HH   8
#define DH   64
#define LL   6
#define FFI  2048
#define RR   (BB*NQ)        // 4096
#define CR   (BB*MM)        // 2048
#define SLD  1028

// ---------------- scratch (static device globals; no allocation) ----------
__device__ float g_x   [RR*DD];
__device__ float g_xn  [RR*DD];
__device__ float g_ctxn[CR*PP];
__device__ float g_q   [RR*DD];
__device__ float g_kv  [RR*128];
__device__ float g_k   [BB*(NQ+1)*DH];
__device__ float g_v   [BB*(NQ+1)*DH];
__device__ float g_att [RR*DD];
__device__ float g_hh  [(size_t)RR*FFI];
__device__ float g_hg  [(size_t)RR*2*FFI];
__device__ float g_sc  [(size_t)BB*HH*NQ*SLD];
// bf16 split scratch
__device__ __nv_bfloat16 g_AH[(size_t)RR*FFI];   // 8M elems
__device__ __nv_bfloat16 g_AL[(size_t)RR*FFI];
__device__ __nv_bfloat16 g_BH[(size_t)2*1024*1024];
__device__ __nv_bfloat16 g_BL[(size_t)2*1024*1024];

// ---------------- reductions ------------------------------------------------
__device__ __forceinline__ float warpSum(float v){
    #pragma unroll
    for (int o=16;o;o>>=1) v += __shfl_xor_sync(0xffffffffu, v, o);
    return v;
}
__device__ __forceinline__ float warpMax(float v){
    #pragma unroll
    for (int o=16;o;o>>=1) v = fmaxf(v, __shfl_xor_sync(0xffffffffu, v, o));
    return v;
}
__device__ float blockSum(float v){
    __shared__ float sh[8];
    int lane = threadIdx.x & 31, w = threadIdx.x >> 5;
    v = warpSum(v);
    if (lane == 0) sh[w] = v;
    __syncthreads();
    v = (threadIdx.x < 8) ? sh[threadIdx.x] : 0.f;
    v = warpSum(v);
    if (threadIdx.x == 0) sh[0] = v;
    __syncthreads();
    float r = sh[0];
    __syncthreads();
    return r;
}
__device__ float blockMax(float v){
    __shared__ float sh[8];
    int lane = threadIdx.x & 31, w = threadIdx.x >> 5;
    v = warpMax(v);
    if (lane == 0) sh[w] = v;
    __syncthreads();
    v = (threadIdx.x < 8) ? sh[threadIdx.x] : -3.4e38f;
    v = warpMax(v);
    if (threadIdx.x == 0) sh[0] = v;
    __syncthreads();
    float r = sh[0];
    __syncthreads();
    return r;
}

// ---------------- elementwise ----------------------------------------------
__global__ void copy_kernel(const float* __restrict__ in, float* __restrict__ out, int n){
    for (int i = blockIdx.x*blockDim.x + threadIdx.x; i < n; i += gridDim.x*blockDim.x)
        out[i] = in[i];
}
__global__ void add_kernel(float* __restrict__ x, const float* __restrict__ y, int n){
    for (int i = blockIdx.x*blockDim.x + threadIdx.x; i < n; i += gridDim.x*blockDim.x)
        x[i] += y[i];
}
__global__ void glu_kernel(const float* __restrict__ hg, float* __restrict__ out){
    long total = (long)RR * FFI;
    for (long i = blockIdx.x*(long)blockDim.x + threadIdx.x; i < total; i += gridDim.x*(long)blockDim.x){
        long r = i / FFI; int c = (int)(i - r*FFI);
        float h = hg[r*(2*FFI) + c];
        float g = hg[r*(2*FFI) + FFI + c];
        out[i] = h * (g / (1.f + expf(-g)));
    }
}

// ---------------- bf16 split conversions -----------------------------------
__device__ __forceinline__ void split_bf16(float x, unsigned short& h, unsigned short& l){
    __nv_bfloat16 hb = __float2bfloat16_rn(x);
    __nv_bfloat16 lb = __float2bfloat16_rn(x - __bfloat162float(hb));
    h = __bfloat16_as_ushort(hb);
    l = __bfloat16_as_ushort(lb);
}
// A: fp32 [n4*4] -> hi/lo bf16 same layout
__global__ void convA(const float* __restrict__ in, __nv_bfloat16* __restrict__ hi,
                      __nv_bfloat16* __restrict__ lo, int n4){
    for (int i = blockIdx.x*blockDim.x + threadIdx.x; i < n4; i += gridDim.x*blockDim.x){
        float4 v = ((const float4*)in)[i];
        unsigned short h0,h1,h2,h3,l0,l1,l2,l3;
        split_bf16(v.x,h0,l0); split_bf16(v.y,h1,l1);
        split_bf16(v.z,h2,l2); split_bf16(v.w,h3,l3);
        uint2 ph, pl;
        ph.x = (uint32_t)h0 | ((uint32_t)h1 << 16);
        ph.y = (uint32_t)h2 | ((uint32_t)h3 << 16);
        pl.x = (uint32_t)l0 | ((uint32_t)l1 << 16);
        pl.y = (uint32_t)l2 | ((uint32_t)l3 << 16);
        ((uint2*)hi)[i] = ph;
        ((uint2*)lo)[i] = pl;
    }
}
// B: fp32 [K][N] -> hi/lo bf16 transposed [N][K]
__global__ __launch_bounds__(256) void convBT(const float* __restrict__ Bm,
                                              __nv_bfloat16* __restrict__ hi,
                                              __nv_bfloat16* __restrict__ lo,
                                              int K, int N){
    __shared__ float tile[32][33];
    int tx = threadIdx.x & 31, ty = threadIdx.x >> 5;
    int n0 = blockIdx.x*32, k0 = blockIdx.y*32;
    #pragma unroll
    for (int i = 0; i < 4; i++)
        tile[ty + 8*i][tx] = Bm[(long)(k0 + ty + 8*i)*N + n0 + tx];
    __syncthreads();
    #pragma unroll
    for (int i = 0; i < 4; i++){
        int n = ty + 8*i;
        float v = tile[tx][n];
        unsigned short h, l;
        split_bf16(v, h, l);
        long off = (long)(n0 + n)*K + k0 + tx;
        hi[off] = __ushort_as_bfloat16(h);
        lo[off] = __ushort_as_bfloat16(l);
    }
}

// ---------------- layernorm family -----------------------------------------
__global__ __launch_bounds__(256) void ln_kernel(const float* __restrict__ in,
                                                 const float* __restrict__ g,
                                                 float* __restrict__ out, int cols){
    long ro = (long)blockIdx.x * cols;
    int t = threadIdx.x;
    float v0 = (t       < cols) ? in[ro + t]       : 0.f;
    float v1 = (t + 256 < cols) ? in[ro + t + 256] : 0.f;
    float mu = blockSum(v0 + v1) / (float)cols;
    float d0 = (t       < cols) ? v0 - mu : 0.f;
    float d1 = (t + 256 < cols) ? v1 - mu : 0.f;
    float var = blockSum(d0*d0 + d1*d1) / (float)cols;
    float inv = 1.f / sqrtf(var + 1e-5f);
    if (t       < cols) out[ro + t]       = d0 * inv * g[t];
    if (t + 256 < cols) out[ro + t + 256] = d1 * inv * g[t + 256];
}
__global__ __launch_bounds__(256) void ln_res_kernel(const float* __restrict__ in,
                                                     const float* __restrict__ g,
                                                     float* __restrict__ x, int cols){
    long ro = (long)blockIdx.x * cols;
    int t = threadIdx.x;
    float v0 = (t       < cols) ? in[ro + t]       : 0.f;
    float v1 = (t + 256 < cols) ? in[ro + t + 256] : 0.f;
    float mu = blockSum(v0 + v1) / (float)cols;
    float d0 = (t       < cols) ? v0 - mu : 0.f;
    float d1 = (t + 256 < cols) ? v1 - mu : 0.f;
    float var = blockSum(d0*d0 + d1*d1) / (float)cols;
    float inv = 1.f / sqrtf(var + 1e-5f);
    if (t       < cols) x[ro + t]       += d0 * inv * g[t];
    if (t + 256 < cols) x[ro + t + 256] += d1 * inv * g[t + 256];
}
__global__ __launch_bounds__(256) void final_ln_kernel(const float* __restrict__ in,
                                                       const float* __restrict__ g,
                                                       float* __restrict__ out, int cols){
    long ro = (long)blockIdx.x * cols;
    int t = threadIdx.x;
    float v0 = (t       < cols) ? in[ro + t]       : 0.f;
    float v1 = (t + 256 < cols) ? in[ro + t + 256] : 0.f;
    float m0 = (t       < cols) ? v0 : -3.4e38f;
    float m1 = (t + 256 < cols) ? v1 : -3.4e38f;
    float mx = blockMax(fmaxf(m0, m1));
    v0 /= mx; v1 /= mx;
    float s0 = (t       < cols) ? v0 : 0.f;
    float s1 = (t + 256 < cols) ? v1 : 0.f;
    float mu = blockSum(s0 + s1) / (float)cols;
    float d0 = (t       < cols) ? v0 - mu : 0.f;
    float d1 = (t + 256 < cols) ? v1 - mu : 0.f;
    float var = blockSum(d0*d0 + d1*d1) / (float)cols;
    float inv = 1.f / sqrtf(var + 1e-5f);
    if (t       < cols) out[ro + t]       = d0 * inv * g[t];
    if (t + 256 < cols) out[ro + t + 256] = d1 * inv * g[t + 256];
}

// ---------------- rotary / prep --------------------------------------------
__device__ __forceinline__ float inv_freq(int m){
    return powf(10000.f, -(float)m * (1.f/16.f));
}
__global__ __launch_bounds__(256) void qprep_kernel(float* __restrict__ q, int n, int use_rot){
    int idx = blockIdx.x * 256 + threadIdx.x;
    int row = idx >> 8;
    int r   = idx & 255;
    int h = r >> 5, t = r & 31;
    float* p = q + (long)row * DD + h * DH;
    const float sc = 0.125f;
    if (t < 16){
        float a = p[t] * sc, b = p[t+16] * sc;
        if (use_rot){
            float f = (float)(row % n) * inv_freq(t);
            float cf = cosf(f), sf = sinf(f);
            p[t]    = a*cf - b*sf;
            p[t+16] = a*sf + b*cf;
        } else { p[t] = a; p[t+16] = b; }
    } else {
        p[t+16] *= sc;
        p[t+32] *= sc;
    }
}
__global__ __launch_bounds__(64) void kvprep_kernel(const float* __restrict__ kv,
                                                    const float* __restrict__ null_kv,
                                                    float* __restrict__ kbuf, float* __restrict__ vbuf,
                                                    int nk, int use_rot){
    int rblk = blockIdx.x;
    int d = threadIdx.x;
    int nkv = nk + 1;
    int b = rblk / nkv, j = rblk % nkv;
    long doff = ((long)b * nkv + j) * DH + d;
    if (j == 0){
        kbuf[doff] = null_kv[d];
        vbuf[doff] = null_kv[DH + d];
        return;
    }
    int i = j - 1;
    const float* src = kv + ((long)b * nk + i) * 128;
    float kval = src[d];
    float vval = src[DH + d];
    if (use_rot && d < 32){
        int m = d & 15;
        float f = (float)i * inv_freq(m);
        float cf = cosf(f), sf = sinf(f);
        if (d < 16) kval = kval*cf - src[d+16]*sf;
        else        kval = kval*cf + src[d-16]*sf;
    }
    kbuf[doff] = kval;
    vbuf[doff] = vval;
}

// ============================================================================
//     bf16x3 tensor-core GEMM via mma.sync.m16n8k16
//     C = A[MxK] @ B[KxN]; inputs pre-split: Ah/Al row-major [M][K] bf16,
//     Bh/Bl transposed [N][K] bf16.
// ============================================================================
__device__ __forceinline__ uint32_t smem_u32(const void* p){
    uint32_t a;
    asm("{ .reg .u64 t; cvta.to.shared.u64 t, %1; cvt.u32.u64 %0, t; }" : "=r"(a) : "l"(p));
    return a;
}
__device__ __forceinline__ void ldsm4(uint32_t* r, uint32_t addr){
    asm volatile("ldmatrix.sync.aligned.m8n8.x4.shared.b16 {%0,%1,%2,%3}, [%4];"
        : "=r"(r[0]),"=r"(r[1]),"=r"(r[2]),"=r"(r[3]) : "r"(addr));
}
__device__ __forceinline__ void mma16816(float* d, const uint32_t* a, uint32_t b0, uint32_t b1){
    asm volatile("mma.sync.aligned.m16n8k16.row.col.f32.bf16.bf16.f32 "
        "{%0,%1,%2,%3}, {%4,%5,%6,%7}, {%8,%9}, {%0,%1,%2,%3};"
        : "+f"(d[0]),"+f"(d[1]),"+f"(d[2]),"+f"(d[3])
        : "r"(a[0]),"r"(a[1]),"r"(a[2]),"r"(a[3]), "r"(b0),"r"(b1));
}
// swizzled 16B-chunk offset within one 128x32 bf16 tile: row r (0..127), chunk c (0..3)
#define SWOFF(r,c) ((((r)*4 + ((c) ^ (((r)>>1)&3)))) << 4)

__global__ __launch_bounds__(256, 2) void tgemm3(const __nv_bfloat16* __restrict__ Ah,
                                                 const __nv_bfloat16* __restrict__ Al,
                                                 const __nv_bfloat16* __restrict__ Bh,
                                                 const __nv_bfloat16* __restrict__ Bl,
                                                 float* __restrict__ C,
                                                 int M, int N, int K){
    __shared__ __align__(16) char sm[4*8192];   // Ah | Al | Bh | Bl tiles (128x32 bf16 each)
    uint32_t sb = smem_u32(sm);
    int t = threadIdx.x, lane = t & 31, warp = t >> 5;
    int wm = (warp >> 2) * 64, wn = (warp & 3) * 32;
    long rowBase = (long)blockIdx.y * 128;
    long colBase = (long)blockIdx.x * 128;

    float acc[4][4][4];
    #pragma unroll
    for (int i=0;i<4;i++)
        #pragma unroll
        for (int j=0;j<4;j++)
            #pragma unroll
            for (int e=0;e<4;e++) acc[i][j][e] = 0.f;

    const __nv_bfloat16* srcs[4] = { Ah + rowBase*K, Al + rowBase*K,
                                     Bh + colBase*K, Bl + colBase*K };
    int lr = t >> 2, lc = t & 3;   // loader row/chunk (rows lr, lr+64)

    for (int k0 = 0; k0 < K; k0 += 32){
        // ---- fill 4 tiles ----
        #pragma unroll
        for (int tt = 0; tt < 4; tt++){
            const __nv_bfloat16* s = srcs[tt] + k0;
            #pragma unroll
            for (int hf = 0; hf < 2; hf++){
                int r = lr + hf*64;
                uint4 v = *(const uint4*)(s + (long)r*K + lc*8);
                *(uint4*)(sm + tt*8192 + SWOFF(r, lc)) = v;
            }
        }
        __syncthreads();

        // ---- compute 2 k16 steps ----
        #pragma unroll
        for (int s = 0; s < 2; s++){
            uint32_t ah[4][4], al[4][4], bh[4][2], bl[4][2];
            #pragma unroll
            for (int mt = 0; mt < 4; mt++){
                int r = wm + mt*16 + (lane & 15);
                int cl = 2*s + (lane >> 4);
                uint32_t addr = sb + SWOFF(r, cl);
                ldsm4(ah[mt], addr);
                ldsm4(al[mt], addr + 8192);
            }
            #pragma unroll
            for (int g = 0; g < 2; g++){
                int r = wn + g*16 + (lane & 7) + ((lane >> 4) << 3);
                int cl = 2*s + ((lane >> 3) & 1);
                uint32_t addr = sb + 2*8192 + SWOFF(r, cl);
                uint32_t tmp[4];
                ldsm4(tmp, addr);
                bh[2*g][0]=tmp[0]; bh[2*g][1]=tmp[1]; bh[2*g+1][0]=tmp[2]; bh[2*g+1][1]=tmp[3];
                ldsm4(tmp, addr + 8192);
                bl[2*g][0]=tmp[0]; bl[2*g][1]=tmp[1]; bl[2*g+1][0]=tmp[2]; bl[2*g+1][1]=tmp[3];
            }
            #pragma unroll
            for (int mt = 0; mt < 4; mt++){
                #pragma unroll
                for (int nt = 0; nt < 4; nt++){
                    mma16816(acc[mt][nt], ah[mt], bh[nt][0], bh[nt][1]);
                    mma16816(acc[mt][nt], ah[mt], bl[nt][0], bl[nt][1]);
                    mma16816(acc[mt][nt], al[mt], bh[nt][0], bh[nt][1]);
                }
            }
        }
        __syncthreads();
    }

    // ---- epilogue ----
    #pragma unroll
    for (int mt = 0; mt < 4; mt++){
        long r = rowBase + wm + mt*16 + (lane >> 2);
        #pragma unroll
        for (int nt = 0; nt < 4; nt++){
            long cc = colBase + wn + nt*8 + 2*(lane & 3);
            float2 v0; v0.x = acc[mt][nt][0]; v0.y = acc[mt][nt][1];
            float2 v1; v1.x = acc[mt][nt][2]; v1.y = acc[mt][nt][3];
            *(float2*)(C + r*N + cc)     = v0;
            *(float2*)(C + (r+8)*N + cc) = v1;
        }
    }
}

// ---------------- attention: scores = q@k^T (+bias, mask) ------------------
__global__ __launch_bounds__(256) void scores_kernel(const float* __restrict__ q,
                                                     const float* __restrict__ kbuf,
                                                     const float* __restrict__ rel_emb,
                                                     float* __restrict__ scores,
                                                     int nq, int nkv, int cb){
    __shared__ float Qs[64][64];
    __shared__ float Ks[64][64];
    int t  = threadIdx.x;
    int bh = blockIdx.z, b = bh >> 3, h = bh & 7;
    int i0 = blockIdx.y * 64, j0 = blockIdx.x * 64;
    #pragma unroll
    for (int n=0;n<4;n++){
        int fi = t + n*256;
        int r = fi >> 4, c4 = fi & 15;
        float4 v = *(const float4*)(q + ((long)(b*nq + i0 + r))*DD + h*DH + c4*4);
        Qs[c4*4+0][r]=v.x; Qs[c4*4+1][r]=v.y; Qs[c4*4+2][r]=v.z; Qs[c4*4+3][r]=v.w;
        int j = j0 + r;
        float4 w = make_float4(0.f,0.f,0.f,0.f);
        if (j < nkv) w = *(const float4*)(kbuf + ((long)b*nkv + j)*DH + c4*4);
        Ks[c4*4+0][r]=w.x; Ks[c4*4+1][r]=w.y; Ks[c4*4+2][r]=w.z; Ks[c4*4+3][r]=w.w;
    }
    __syncthreads();
    int tx = t & 15, ty = t >> 4;
    float acc[4][4];
    #pragma unroll
    for (int i=0;i<4;i++)
        #pragma unroll
        for (int j=0;j<4;j++) acc[i][j]=0.f;
    #pragma unroll 4
    for (int d=0; d<64; d++){
        float a[4], bb[4];
        *(float4*)a  = *(const float4*)&Qs[d][ty*4];
        *(float4*)bb = *(const float4*)&Ks[d][tx*4];
        #pragma unroll
        for (int i=0;i<4;i++)
            #pragma unroll
            for (int j=0;j<4;j++) acc[i][j] = fmaf(a[i], bb[j], acc[i][j]);
    }
    #pragma unroll
    for (int ii=0;ii<4;ii++){
        int i = i0 + ty*4 + ii;
        #pragma unroll
        for (int jj=0;jj<4;jj++){
            int j = j0 + tx*4 + jj;
            if (j >= nkv) continue;
            float s = acc[ii][jj];
            if (cb){
                int nn = i - j; if (nn < 0) nn = 0;
                int bucket;
                if (nn < 16) bucket = nn;
                else {
                    int large = 16 + (int)(logf((float)nn * 0.0625f) * (16.0f / 2.0794415416798357f));
                    bucket = large < 31 ? large : 31;
                }
                s += rel_emb[bucket*HH + h];
                if (j > i + 1) s = -1e30f;
            }
            scores[((long)bh*nq + i)*SLD + j] = s;
        }
    }
}

// ---------------- softmax ---------------------------------------------------
__global__ __launch_bounds__(256) void softmax_kernel(float* __restrict__ scores, int nkv){
    long off = (long)blockIdx.x * SLD;
    int t = threadIdx.x;
    float v[5];
    int cnt = 0;
    float mx = -3.4e38f;
    for (int j = t; j < nkv; j += 256){ v[cnt] = scores[off + j]; mx = fmaxf(mx, v[cnt]); cnt++; }
    mx = blockMax(mx);
    float s = 0.f;
    for (int c=0;c<cnt;c++){ v[c] = expf(v[c] - mx); s += v[c]; }
    s = blockSum(s);
    float inv = 1.f / s;
    cnt = 0;
    for (int j = t; j < nkv; j += 256) scores[off + j] = v[cnt++] * inv;
}

// ---------------- out = attn @ v -------------------------------------------
__global__ __launch_bounds__(256) void av_kernel(const float* __restrict__ scores,
                                                 const float* __restrict__ vbuf,
                                                 float* __restrict__ out,
                                                 int nq, int nkv){
    __shared__ float Ps[16][64];
    __shared__ float Vs[16][64];
    int t  = threadIdx.x;
    int bh = blockIdx.z, b = bh >> 3, h = bh & 7;
    int i0 = blockIdx.y * 64;
    int tx = t & 15, ty = t >> 4;
    const float* srow = scores + (long)bh * nq * SLD;
    float acc[4][4];
    #pragma unroll
    for (int i=0;i<4;i++)
        #pragma unroll
        for (int j=0;j<4;j++) acc[i][j]=0.f;
    for (int k0 = 0; k0 < nkv; k0 += 16){
        int pr = t >> 2, pc = (t & 3)*4;
        #pragma unroll
        for (int e=0;e<4;e++){
            int kk = k0 + pc + e;
            Ps[pc+e][pr] = (kk < nkv) ? srow[(long)(i0 + pr)*SLD + kk] : 0.f;
        }
        int vr = t >> 4, vc4 = t & 15;
        int kk2 = k0 + vr;
        float4 w = make_float4(0.f,0.f,0.f,0.f);
        if (kk2 < nkv) w = *(const float4*)(vbuf + ((long)b*nkv + kk2)*DH + vc4*4);
        *(float4*)&Vs[vr][vc4*4] = w;
        __syncthreads();
        #pragma unroll
        for (int kk=0;kk<16;kk++){
            float a[4], bb[4];
            *(float4*)a  = *(const float4*)&Ps[kk][ty*4];
            *(float4*)bb = *(const float4*)&Vs[kk][tx*4];
            #pragma unroll
            for (int i=0;i<4;i++)
                #pragma unroll
                for (int j=0;j<4;j++) acc[i][j] = fmaf(a[i], bb[j], acc[i][j]);
        }
        __syncthreads();
    }
    #pragma unroll
    for (int ii=0;ii<4;ii++)
        #pragma unroll
        for (int jj=0;jj<4;jj++)
            out[((long)(b*nq + i0 + ty*4 + ii))*DD + h*DH + tx*4 + jj] = acc[ii][jj];
}

// ---------------- orchestration --------------------------------------------
extern "C" void kernel_launch(void* const* d_in, const int* in_sizes, int n_in,
                              void* d_out, int out_size){
    const float* x_in    = (const float*)d_in[0];
    const float* ctx     = (const float*)d_in[1];
    const float* rel_emb = (const float*)d_in[2];
    const float* sa_ng   = (const float*)d_in[3];
    const float* sa_wq   = (const float*)d_in[4];
    const float* sa_wkv  = (const float*)d_in[5];
    const float* sa_null = (const float*)d_in[6];
    const float* sa_wo   = (const float*)d_in[7];
    const float* sa_og   = (const float*)d_in[8];
    const float* ca_ng   = (const float*)d_in[9];
    const float* ca_cg   = (const float*)d_in[10];
    const float* ca_wq   = (const float*)d_in[11];
    const float* ca_wkv  = (const float*)d_in[12];
    const float* ca_null = (const float*)d_in[13];
    const float* ca_wo   = (const float*)d_in[14];
    const float* ca_og   = (const float*)d_in[15];
    const float* ff_ng   = (const float*)d_in[16];
    const float* ff_w1   = (const float*)d_in[17];
    const float* ff_w2   = (const float*)d_in[18];
    const float* normg   = (const float*)d_in[19];
    float* out = (float*)d_out;

    float *X,*XN,*CTXN,*Q,*KV,*K_,*V_,*ATT,*HHp,*HG,*SC;
    __nv_bfloat16 *AH,*AL,*BH,*BL;
    cudaGetSymbolAddress((void**)&X,    g_x);
    cudaGetSymbolAddress((void**)&XN,   g_xn);
    cudaGetSymbolAddress((void**)&CTXN, g_ctxn);
    cudaGetSymbolAddress((void**)&Q,    g_q);
    cudaGetSymbolAddress((void**)&KV,   g_kv);
    cudaGetSymbolAddress((void**)&K_,   g_k);
    cudaGetSymbolAddress((void**)&V_,   g_v);
    cudaGetSymbolAddress((void**)&ATT,  g_att);
    cudaGetSymbolAddress((void**)&HHp,  g_hh);
    cudaGetSymbolAddress((void**)&HG,   g_hg);
    cudaGetSymbolAddress((void**)&SC,   g_sc);
    cudaGetSymbolAddress((void**)&AH,   g_AH);
    cudaGetSymbolAddress((void**)&AL,   g_AL);
    cudaGetSymbolAddress((void**)&BH,   g_BH);
    cudaGetSymbolAddress((void**)&BL,   g_BL);
    __nv_bfloat16 *AH2 = AH + (size_t)4*1024*1024;   // second A region (ctx)
    __nv_bfloat16 *AL2 = AL + (size_t)4*1024*1024;

    copy_kernel<<<512, 256>>>(x_in, X, RR*DD);

    for (int l = 0; l < LL; l++){
        // ---------------- self-attention ----------------
        ln_kernel<<<RR, 256>>>(X, sa_ng + l*DD, XN, DD);
        convA<<<512, 256>>>(XN, AH, AL, RR*DD/4);
        convBT<<<dim3(DD/32, DD/32), 256>>>(sa_wq + (size_t)l*DD*DD, BH, BL, DD, DD);
        tgemm3<<<dim3(DD/128, RR/128), 256>>>(AH, AL, BH, BL, Q, RR, DD, DD);
        convBT<<<dim3(128/32, DD/32), 256>>>(sa_wkv + (size_t)l*DD*128, BH, BL, DD, 128);
        tgemm3<<<dim3(1, RR/128), 256>>>(AH, AL, BH, BL, KV, RR, 128, DD);
        qprep_kernel<<<RR, 256>>>(Q, NQ, 1);
        kvprep_kernel<<<BB*(NQ+1), 64>>>(KV, sa_null + l*128, K_, V_, NQ, 1);
        scores_kernel<<<dim3((NQ+1+63)/64, NQ/64, BB*HH), 256>>>(Q, K_, rel_emb, SC, NQ, NQ+1, 1);
        softmax_kernel<<<BB*HH*NQ, 256>>>(SC, NQ+1);
        av_kernel<<<dim3(1, NQ/64, BB*HH), 256>>>(SC, V_, ATT, NQ, NQ+1);
        convA<<<512, 256>>>(ATT, AH, AL, RR*DD/4);
        convBT<<<dim3(DD/32, DD/32), 256>>>(sa_wo + (size_t)l*DD*DD, BH, BL, DD, DD);
        tgemm3<<<dim3(DD/128, RR/128), 256>>>(AH, AL, BH, BL, Q, RR, DD, DD);
        ln_res_kernel<<<RR, 256>>>(Q, sa_og + l*DD, X, DD);

        // ---------------- cross-attention ----------------
        ln_kernel<<<RR, 256>>>(X, ca_ng + l*DD, XN, DD);
        ln_kernel<<<CR, 256>>>(ctx, ca_cg + l*PP, CTXN, PP);
        convA<<<512, 256>>>(XN, AH, AL, RR*DD/4);
        convA<<<512, 256>>>(CTXN, AH2, AL2, CR*PP/4);
        convBT<<<dim3(DD/32, DD/32), 256>>>(ca_wq + (size_t)l*DD*DD, BH, BL, DD, DD);
        tgemm3<<<dim3(DD/128, RR/128), 256>>>(AH, AL, BH, BL, Q, RR, DD, DD);
        convBT<<<dim3(128/32, PP/32), 256>>>(ca_wkv + (size_t)l*PP*128, BH, BL, PP, 128);
        tgemm3<<<dim3(1, CR/128), 256>>>(AH2, AL2, BH, BL, KV, CR, 128, PP);
        qprep_kernel<<<RR, 256>>>(Q, NQ, 0);
        kvprep_kernel<<<BB*(MM+1), 64>>>(KV, ca_null + l*128, K_, V_, MM, 0);
        scores_kernel<<<dim3((MM+1+63)/64, NQ/64, BB*HH), 256>>>(Q, K_, rel_emb, SC, NQ, MM+1, 0);
        softmax_kernel<<<BB*HH*NQ, 256>>>(SC, MM+1);
        av_kernel<<<dim3(1, NQ/64, BB*HH), 256>>>(SC, V_, ATT, NQ, MM+1);
        convA<<<512, 256>>>(ATT, AH, AL, RR*DD/4);
        convBT<<<dim3(DD/32, DD/32), 256>>>(ca_wo + (size_t)l*DD*DD, BH, BL, DD, DD);
        tgemm3<<<dim3(DD/128, RR/128), 256>>>(AH, AL, BH, BL, Q, RR, DD, DD);
        ln_res_kernel<<<RR, 256>>>(Q, ca_og + l*DD, X, DD);

        // ---------------- feed-forward (SwiGLU) ----------------
        ln_kernel<<<RR, 256>>>(X, ff_ng + l*DD, XN, DD);
        convA<<<512, 256>>>(XN, AH, AL, RR*DD/4);
        convBT<<<dim3((2*FFI)/32, DD/32), 256>>>(ff_w1 + (size_t)l*DD*2*FFI, BH, BL, DD, 2*FFI);
        tgemm3<<<dim3((2*FFI)/128, RR/128), 256>>>(AH, AL, BH, BL, HG, RR, 2*FFI, DD);
        glu_kernel<<<2048, 256>>>(HG, HHp);
        convA<<<1024, 256>>>(HHp, AH, AL, RR*FFI/4);
        convBT<<<dim3(DD/32, FFI/32), 256>>>(ff_w2 + (size_t)l*FFI*DD, BH, BL, FFI, DD);
        tgemm3<<<dim3(DD/128, RR/128), 256>>>(AH, AL, BH, BL, Q, RR, DD, FFI);
        add_kernel<<<1024, 256>>>(X, Q, RR*DD);
    }

    final_ln_kernel<<<RR, 256>>>(X, normg, out, DD);
}

// round 7
// speedup vs baseline: 1.4745x; 1.0142x over previous
#include <cuda_runtime.h>
#include <cuda_bf16.h>
#include <math.h>
#include <stdint.h>

// Problem constants
#define BB   4
#define NQ   1024
#define MM   512
#define DD   512
#define PP   256
#define HH   8
#define DH   64
#define LL   6
#define FFI  2048
#define RR   (BB*NQ)        // 4096
#define CR   (BB*MM)        // 2048
#define SLD  1028
#define PADS 1152           // padded kv rows (self: 9 tiles); cross uses 640 of it
#define PW   1152           // P buffer row stride

// ---------------- scratch (static device globals) --------------------------
__device__ float g_x   [RR*DD];
__device__ float g_xn  [RR*DD];
__device__ float g_ctxn[CR*PP];
__device__ float g_q   [RR*DD];
__device__ float g_kv  [RR*128];
__device__ float g_att [RR*DD];
__device__ float g_hh  [(size_t)RR*FFI];
__device__ float g_hg  [(size_t)RR*2*FFI];
__device__ float g_sc  [(size_t)BB*HH*NQ*SLD];
__device__ __nv_bfloat16 g_AH[(size_t)RR*FFI];
__device__ __nv_bfloat16 g_AL[(size_t)RR*FFI];
__device__ __nv_bfloat16 g_BH[(size_t)2*1024*1024];
__device__ __nv_bfloat16 g_BL[(size_t)2*1024*1024];
__device__ __nv_bfloat16 g_KH[(size_t)BB*PADS*DH];
__device__ __nv_bfloat16 g_KL[(size_t)BB*PADS*DH];
__device__ __nv_bfloat16 g_VTH[(size_t)BB*DH*PW];
__device__ __nv_bfloat16 g_VTL[(size_t)BB*DH*PW];
__device__ __nv_bfloat16 g_PH[(size_t)BB*HH*NQ*PW];
__device__ __nv_bfloat16 g_PL[(size_t)BB*HH*NQ*PW];

// ---------------- reductions ------------------------------------------------
__device__ __forceinline__ float warpSum(float v){
    #pragma unroll
    for (int o=16;o;o>>=1) v += __shfl_xor_sync(0xffffffffu, v, o);
    return v;
}
__device__ __forceinline__ float warpMax(float v){
    #pragma unroll
    for (int o=16;o;o>>=1) v = fmaxf(v, __shfl_xor_sync(0xffffffffu, v, o));
    return v;
}
__device__ float blockSum(float v){
    __shared__ float sh[8];
    int lane = threadIdx.x & 31, w = threadIdx.x >> 5;
    v = warpSum(v);
    if (lane == 0) sh[w] = v;
    __syncthreads();
    v = (threadIdx.x < 8) ? sh[threadIdx.x] : 0.f;
    v = warpSum(v);
    if (threadIdx.x == 0) sh[0] = v;
    __syncthreads();
    float r = sh[0];
    __syncthreads();
    return r;
}
__device__ float blockMax(float v){
    __shared__ float sh[8];
    int lane = threadIdx.x & 31, w = threadIdx.x >> 5;
    v = warpMax(v);
    if (lane == 0) sh[w] = v;
    __syncthreads();
    v = (threadIdx.x < 8) ? sh[threadIdx.x] : -3.4e38f;
    v = warpMax(v);
    if (threadIdx.x == 0) sh[0] = v;
    __syncthreads();
    float r = sh[0];
    __syncthreads();
    return r;
}

// ---------------- elementwise ----------------------------------------------
__global__ void copy_kernel(const float* __restrict__ in, float* __restrict__ out, int n){
    for (int i = blockIdx.x*blockDim.x + threadIdx.x; i < n; i += gridDim.x*blockDim.x)
        out[i] = in[i];
}
__global__ void add_kernel(float* __restrict__ x, const float* __restrict__ y, int n){
    for (int i = blockIdx.x*blockDim.x + threadIdx.x; i < n; i += gridDim.x*blockDim.x)
        x[i] += y[i];
}
__global__ void glu_kernel(const float* __restrict__ hg, float* __restrict__ out){
    long total = (long)RR * FFI;
    for (long i = blockIdx.x*(long)blockDim.x + threadIdx.x; i < total; i += gridDim.x*(long)blockDim.x){
        long r = i / FFI; int c = (int)(i - r*FFI);
        float h = hg[r*(2*FFI) + c];
        float g = hg[r*(2*FFI) + FFI + c];
        out[i] = h * (g / (1.f + expf(-g)));
    }
}

// ---------------- bf16 split helpers ---------------------------------------
__device__ __forceinline__ void split_bf16(float x, unsigned short& h, unsigned short& l){
    __nv_bfloat16 hb = __float2bfloat16_rn(x);
    __nv_bfloat16 lb = __float2bfloat16_rn(x - __bfloat162float(hb));
    h = __bfloat16_as_ushort(hb);
    l = __bfloat16_as_ushort(lb);
}
__global__ void convA(const float* __restrict__ in, __nv_bfloat16* __restrict__ hi,
                      __nv_bfloat16* __restrict__ lo, int n4){
    for (int i = blockIdx.x*blockDim.x + threadIdx.x; i < n4; i += gridDim.x*blockDim.x){
        float4 v = ((const float4*)in)[i];
        unsigned short h0,h1,h2,h3,l0,l1,l2,l3;
        split_bf16(v.x,h0,l0); split_bf16(v.y,h1,l1);
        split_bf16(v.z,h2,l2); split_bf16(v.w,h3,l3);
        uint2 ph, pl;
        ph.x = (uint32_t)h0 | ((uint32_t)h1 << 16);
        ph.y = (uint32_t)h2 | ((uint32_t)h3 << 16);
        pl.x = (uint32_t)l0 | ((uint32_t)l1 << 16);
        pl.y = (uint32_t)l2 | ((uint32_t)l3 << 16);
        ((uint2*)hi)[i] = ph;
        ((uint2*)lo)[i] = pl;
    }
}
// B: fp32 [K][N] -> hi/lo bf16 transposed [N][K]
__global__ __launch_bounds__(256) void convBT(const float* __restrict__ Bm,
                                              __nv_bfloat16* __restrict__ hi,
                                              __nv_bfloat16* __restrict__ lo,
                                              int K, int N){
    __shared__ float tile[32][33];
    int tx = threadIdx.x & 31, ty = threadIdx.x >> 5;
    int n0 = blockIdx.x*32, k0 = blockIdx.y*32;
    #pragma unroll
    for (int i = 0; i < 4; i++)
        tile[ty + 8*i][tx] = Bm[(long)(k0 + ty + 8*i)*N + n0 + tx];
    __syncthreads();
    #pragma unroll
    for (int i = 0; i < 4; i++){
        int n = ty + 8*i;
        float v = tile[tx][n];
        unsigned short h, l;
        split_bf16(v, h, l);
        long off = (long)(n0 + n)*K + k0 + tx;
        hi[off] = __ushort_as_bfloat16(h);
        lo[off] = __ushort_as_bfloat16(l);
    }
}

// ---------------- layernorm family -----------------------------------------
__global__ __launch_bounds__(256) void ln_kernel(const float* __restrict__ in,
                                                 const float* __restrict__ g,
                                                 float* __restrict__ out, int cols){
    long ro = (long)blockIdx.x * cols;
    int t = threadIdx.x;
    float v0 = (t       < cols) ? in[ro + t]       : 0.f;
    float v1 = (t + 256 < cols) ? in[ro + t + 256] : 0.f;
    float mu = blockSum(v0 + v1) / (float)cols;
    float d0 = (t       < cols) ? v0 - mu : 0.f;
    float d1 = (t + 256 < cols) ? v1 - mu : 0.f;
    float var = blockSum(d0*d0 + d1*d1) / (float)cols;
    float inv = 1.f / sqrtf(var + 1e-5f);
    if (t       < cols) out[ro + t]       = d0 * inv * g[t];
    if (t + 256 < cols) out[ro + t + 256] = d1 * inv * g[t + 256];
}
__global__ __launch_bounds__(256) void ln_res_kernel(const float* __restrict__ in,
                                                     const float* __restrict__ g,
                                                     float* __restrict__ x, int cols){
    long ro = (long)blockIdx.x * cols;
    int t = threadIdx.x;
    float v0 = (t       < cols) ? in[ro + t]       : 0.f;
    float v1 = (t + 256 < cols) ? in[ro + t + 256] : 0.f;
    float mu = blockSum(v0 + v1) / (float)cols;
    float d0 = (t       < cols) ? v0 - mu : 0.f;
    float d1 = (t + 256 < cols) ? v1 - mu : 0.f;
    float var = blockSum(d0*d0 + d1*d1) / (float)cols;
    float inv = 1.f / sqrtf(var + 1e-5f);
    if (t       < cols) x[ro + t]       += d0 * inv * g[t];
    if (t + 256 < cols) x[ro + t + 256] += d1 * inv * g[t + 256];
}
__global__ __launch_bounds__(256) void final_ln_kernel(const float* __restrict__ in,
                                                       const float* __restrict__ g,
                                                       float* __restrict__ out, int cols){
    long ro = (long)blockIdx.x * cols;
    int t = threadIdx.x;
    float v0 = (t       < cols) ? in[ro + t]       : 0.f;
    float v1 = (t + 256 < cols) ? in[ro + t + 256] : 0.f;
    float m0 = (t       < cols) ? v0 : -3.4e38f;
    float m1 = (t + 256 < cols) ? v1 : -3.4e38f;
    float mx = blockMax(fmaxf(m0, m1));
    v0 /= mx; v1 /= mx;
    float s0 = (t       < cols) ? v0 : 0.f;
    float s1 = (t + 256 < cols) ? v1 : 0.f;
    float mu = blockSum(s0 + s1) / (float)cols;
    float d0 = (t       < cols) ? v0 - mu : 0.f;
    float d1 = (t + 256 < cols) ? v1 - mu : 0.f;
    float var = blockSum(d0*d0 + d1*d1) / (float)cols;
    float inv = 1.f / sqrtf(var + 1e-5f);
    if (t       < cols) out[ro + t]       = d0 * inv * g[t];
    if (t + 256 < cols) out[ro + t + 256] = d1 * inv * g[t + 256];
}

// ---------------- rotary / prep --------------------------------------------
__device__ __forceinline__ float inv_freq(int m){
    return powf(10000.f, -(float)m * (1.f/16.f));
}
__global__ __launch_bounds__(256) void qprep_kernel(float* __restrict__ q, int n, int use_rot){
    int idx = blockIdx.x * 256 + threadIdx.x;
    int row = idx >> 8;
    int r   = idx & 255;
    int h = r >> 5, t = r & 31;
    float* p = q + (long)row * DD + h * DH;
    const float sc = 0.125f;
    if (t < 16){
        float a = p[t] * sc, b = p[t+16] * sc;
        if (use_rot){
            float f = (float)(row % n) * inv_freq(t);
            float cf = cosf(f), sf = sinf(f);
            p[t]    = a*cf - b*sf;
            p[t+16] = a*sf + b*cf;
        } else { p[t] = a; p[t+16] = b; }
    } else {
        p[t+16] *= sc;
        p[t+32] *= sc;
    }
}
// kv: [B*nk,128] -> split bf16 K [b][j][d] (padded rows zeroed) and V^T [b][d][j]
__global__ __launch_bounds__(64) void kvprep2(const float* __restrict__ kv,
                                              const float* __restrict__ null_kv,
                                              __nv_bfloat16* __restrict__ KH, __nv_bfloat16* __restrict__ KL,
                                              __nv_bfloat16* __restrict__ VTH, __nv_bfloat16* __restrict__ VTL,
                                              int nk, int use_rot, int padK){
    int rblk = blockIdx.x;
    int d = threadIdx.x;
    int nkv = nk + 1;
    int b = rblk / padK, j = rblk % padK;
    long koff = ((long)b * PADS + j) * DH + d;
    long voff = ((long)b * DH + d) * PW + j;
    if (j >= nkv){
        KH[koff] = __ushort_as_bfloat16(0); KL[koff] = __ushort_as_bfloat16(0);
        VTH[voff] = __ushort_as_bfloat16(0); VTL[voff] = __ushort_as_bfloat16(0);
        return;
    }
    float kval, vval;
    if (j == 0){
        kval = null_kv[d];
        vval = null_kv[DH + d];
    } else {
        int i = j - 1;
        const float* src = kv + ((long)b * nk + i) * 128;
        kval = src[d];
        vval = src[DH + d];
        if (use_rot && d < 32){
            int m = d & 15;
            float f = (float)i * inv_freq(m);
            float cf = cosf(f), sf = sinf(f);
            if (d < 16) kval = kval*cf - src[d+16]*sf;
            else        kval = kval*cf + src[d-16]*sf;
        }
    }
    unsigned short h, l;
    split_bf16(kval, h, l);
    KH[koff] = __ushort_as_bfloat16(h); KL[koff] = __ushort_as_bfloat16(l);
    split_bf16(vval, h, l);
    VTH[voff] = __ushort_as_bfloat16(h); VTL[voff] = __ushort_as_bfloat16(l);
}

// ============================================================================
//  mma helpers
// ============================================================================
__device__ __forceinline__ uint32_t smem_u32(const void* p){
    uint32_t a;
    asm("{ .reg .u64 t; cvta.to.shared.u64 t, %1; cvt.u32.u64 %0, t; }" : "=r"(a) : "l"(p));
    return a;
}
__device__ __forceinline__ void cpa(uint32_t sm, const void* g){
    asm volatile("cp.async.ca.shared.global [%0], [%1], 16;" :: "r"(sm), "l"(g));
}
#define CP_COMMIT() asm volatile("cp.async.commit_group;" ::: "memory")
#define CP_WAIT1()  asm volatile("cp.async.wait_group 1;" ::: "memory")
#define CP_WAIT0()  asm volatile("cp.async.wait_group 0;" ::: "memory")
__device__ __forceinline__ void ldsm4(uint32_t* r, uint32_t addr){
    asm volatile("ldmatrix.sync.aligned.m8n8.x4.shared.b16 {%0,%1,%2,%3}, [%4];"
        : "=r"(r[0]),"=r"(r[1]),"=r"(r[2]),"=r"(r[3]) : "r"(addr));
}
__device__ __forceinline__ void mma16816(float* d, const uint32_t* a, uint32_t b0, uint32_t b1){
    asm volatile("mma.sync.aligned.m16n8k16.row.col.f32.bf16.bf16.f32 "
        "{%0,%1,%2,%3}, {%4,%5,%6,%7}, {%8,%9}, {%0,%1,%2,%3};"
        : "+f"(d[0]),"+f"(d[1]),"+f"(d[2]),"+f"(d[3])
        : "r"(a[0]),"r"(a[1]),"r"(a[2]),"r"(a[3]), "r"(b0),"r"(b1));
}
#define SWOFF(r,c) ((((r)*4 + ((c) ^ (((r)>>1)&3)))) << 4)

// inner compute for a 128x128 tile stage (8 warps 2x4, wm 64, wn 32)
#define COMPUTE_128x128(ss)                                                        \
    _Pragma("unroll")                                                              \
    for (int s = 0; s < 2; s++){                                                   \
        uint32_t ah[4][4], al[4][4], bhf[4][2], blf[4][2];                         \
        _Pragma("unroll")                                                          \
        for (int mt = 0; mt < 4; mt++){                                            \
            int r = wm + mt*16 + (lane & 15);                                      \
            int cl = 2*s + (lane >> 4);                                            \
            uint32_t addr = (ss) + SWOFF(r, cl);                                   \
            ldsm4(ah[mt], addr);                                                   \
            ldsm4(al[mt], addr + 8192);                                            \
        }                                                                          \
        _Pragma("unroll")                                                          \
        for (int g = 0; g < 2; g++){                                               \
            int r = wn + g*16 + (lane & 7) + ((lane >> 4) << 3);                   \
            int cl = 2*s + ((lane >> 3) & 1);                                      \
            uint32_t addr = (ss) + 16384 + SWOFF(r, cl);                           \
            uint32_t tmp[4];                                                       \
            ldsm4(tmp, addr);                                                      \
            bhf[2*g][0]=tmp[0]; bhf[2*g][1]=tmp[1]; bhf[2*g+1][0]=tmp[2]; bhf[2*g+1][1]=tmp[3]; \
            ldsm4(tmp, addr + 8192);                                               \
            blf[2*g][0]=tmp[0]; blf[2*g][1]=tmp[1]; blf[2*g+1][0]=tmp[2]; blf[2*g+1][1]=tmp[3]; \
        }                                                                          \
        _Pragma("unroll")                                                          \
        for (int mt = 0; mt < 4; mt++)                                             \
            _Pragma("unroll")                                                      \
            for (int nt = 0; nt < 4; nt++){                                        \
                mma16816(acc[mt][nt], ah[mt], bhf[nt][0], bhf[nt][1]);             \
                mma16816(acc[mt][nt], ah[mt], blf[nt][0], blf[nt][1]);             \
                mma16816(acc[mt][nt], al[mt], bhf[nt][0], bhf[nt][1]);             \
            }                                                                      \
    }

// ---------------- dense GEMM: C = A[MxK] @ B'[NxK]^T -----------------------
__global__ __launch_bounds__(256, 2) void tgemm3(const __nv_bfloat16* __restrict__ Ah,
                                                 const __nv_bfloat16* __restrict__ Al,
                                                 const __nv_bfloat16* __restrict__ Bh,
                                                 const __nv_bfloat16* __restrict__ Bl,
                                                 float* __restrict__ C,
                                                 int M, int N, int K){
    extern __shared__ __align__(16) char sm[];   // 2 stages * 32768
    uint32_t sb = smem_u32(sm);
    int t = threadIdx.x, lane = t & 31, warp = t >> 5;
    int wm = (warp >> 2) * 64, wn = (warp & 3) * 32;
    long rowBase = (long)blockIdx.y * 128;
    long colBase = (long)blockIdx.x * 128;
    const __nv_bfloat16* srcs[4] = { Ah + rowBase*K, Al + rowBase*K,
                                     Bh + colBase*K, Bl + colBase*K };
    int lr = t >> 2, lc = t & 3;

    float acc[4][4][4];
    #pragma unroll
    for (int i=0;i<4;i++)
        #pragma unroll
        for (int j=0;j<4;j++)
            #pragma unroll
            for (int e=0;e<4;e++) acc[i][j][e] = 0.f;

    #define DLOAD(st, k0) do {                                                  \
        _Pragma("unroll")                                                       \
        for (int tt = 0; tt < 4; tt++){                                         \
            const __nv_bfloat16* s = srcs[tt] + (k0);                           \
            uint32_t so = sb + (st)*32768 + tt*8192;                            \
            cpa(so + SWOFF(lr, lc),      s + (long)lr*K + lc*8);                \
            cpa(so + SWOFF(lr+64, lc),   s + (long)(lr+64)*K + lc*8);           \
        }                                                                       \
        CP_COMMIT(); } while(0)

    int nch = K >> 5;
    DLOAD(0, 0);
    for (int c = 0; c < nch; c++){
        int st = c & 1;
        if (c + 1 < nch){ DLOAD((c+1)&1, (c+1)*32); CP_WAIT1(); }
        else CP_WAIT0();
        __syncthreads();
        uint32_t ss = sb + st*32768;
        COMPUTE_128x128(ss);
        __syncthreads();
    }
    #undef DLOAD

    #pragma unroll
    for (int mt = 0; mt < 4; mt++){
        long r = rowBase + wm + mt*16 + (lane >> 2);
        #pragma unroll
        for (int nt = 0; nt < 4; nt++){
            long cc = colBase + wn + nt*8 + 2*(lane & 3);
            float2 v0; v0.x = acc[mt][nt][0]; v0.y = acc[mt][nt][1];
            float2 v1; v1.x = acc[mt][nt][2]; v1.y = acc[mt][nt][3];
            *(float2*)(C + r*N + cc)     = v0;
            *(float2*)(C + (r+8)*N + cc) = v1;
        }
    }
}

// ---------------- scores mma: SC = Q@K^T (+bias+mask) ----------------------
__global__ __launch_bounds__(256, 2) void scores_mma(const __nv_bfloat16* __restrict__ Qh,
                                                     const __nv_bfloat16* __restrict__ Ql,
                                                     const __nv_bfloat16* __restrict__ KHp,
                                                     const __nv_bfloat16* __restrict__ KLp,
                                                     const float* __restrict__ rel_emb,
                                                     float* __restrict__ scores,
                                                     int nkv, int cb){
    extern __shared__ __align__(16) char sm[];   // 2 stages * 32768
    uint32_t sb = smem_u32(sm);
    int t = threadIdx.x, lane = t & 31, warp = t >> 5;
    int wm = (warp >> 2) * 64, wn = (warp & 3) * 32;
    int bh = blockIdx.z, b = bh >> 3, h = bh & 7;
    int i0 = blockIdx.y * 128, j0 = blockIdx.x * 128;
    const __nv_bfloat16* srcs[4] = {
        Qh + ((long)(b*NQ + i0))*DD + h*DH,
        Ql + ((long)(b*NQ + i0))*DD + h*DH,
        KHp + (long)b*PADS*DH + (long)j0*DH,
        KLp + (long)b*PADS*DH + (long)j0*DH };
    const int lds_[4] = { DD, DD, DH, DH };
    int lr = t >> 2, lc = t & 3;

    float acc[4][4][4];
    #pragma unroll
    for (int i=0;i<4;i++)
        #pragma unroll
        for (int j=0;j<4;j++)
            #pragma unroll
            for (int e=0;e<4;e++) acc[i][j][e] = 0.f;

    #define SLOAD(st, k0) do {                                                  \
        _Pragma("unroll")                                                       \
        for (int tt = 0; tt < 4; tt++){                                         \
            const __nv_bfloat16* s = srcs[tt] + (k0);                           \
            int ld = lds_[tt];                                                  \
            uint32_t so = sb + (st)*32768 + tt*8192;                            \
            cpa(so + SWOFF(lr, lc),      s + (long)lr*ld + lc*8);               \
            cpa(so + SWOFF(lr+64, lc),   s + (long)(lr+64)*ld + lc*8);          \
        }                                                                       \
        CP_COMMIT(); } while(0)

    SLOAD(0, 0);
    #pragma unroll
    for (int c = 0; c < 2; c++){
        if (c == 0){ SLOAD(1, 32); CP_WAIT1(); }
        else CP_WAIT0();
        __syncthreads();
        uint32_t ss = sb + c*32768;
        COMPUTE_128x128(ss);
        __syncthreads();
    }
    #undef SLOAD

    // epilogue: bias + mask + guarded store
    #pragma unroll
    for (int mt = 0; mt < 4; mt++){
        int rl = wm + mt*16 + (lane >> 2);
        #pragma unroll
        for (int nt = 0; nt < 4; nt++){
            int cbase = j0 + wn + nt*8 + 2*(lane & 3);
            #pragma unroll
            for (int e = 0; e < 4; e++){
                int i = i0 + rl + (e >> 1)*8;
                int j = cbase + (e & 1);
                if (j >= nkv) continue;
                float s = acc[mt][nt][e];
                if (cb){
                    int nn = i - j; if (nn < 0) nn = 0;
                    int bucket;
                    if (nn < 16) bucket = nn;
                    else {
                        int large = 16 + (int)(logf((float)nn * 0.0625f) * (16.0f / 2.0794415416798357f));
                        bucket = large < 31 ? large : 31;
                    }
                    s += rel_emb[bucket*HH + h];
                    if (j > i + 1) s = -1e30f;
                }
                scores[((long)bh*NQ + i)*SLD + j] = s;
            }
        }
    }
}

// ---------------- softmax + bf16 split of P --------------------------------
__global__ __launch_bounds__(256) void softmax_split(const float* __restrict__ scores,
                                                     __nv_bfloat16* __restrict__ PH,
                                                     __nv_bfloat16* __restrict__ PL,
                                                     int nkv){
    long row = blockIdx.x;
    long off = row * SLD;
    int t = threadIdx.x;
    float v[5];
    int cnt = 0;
    float mx = -3.4e38f;
    for (int j = t; j < nkv; j += 256){ v[cnt] = scores[off + j]; mx = fmaxf(mx, v[cnt]); cnt++; }
    mx = blockMax(mx);
    float s = 0.f;
    for (int c=0;c<cnt;c++){ v[c] = expf(v[c] - mx); s += v[c]; }
    s = blockSum(s);
    float inv = 1.f / s;
    long po = row * PW;
    cnt = 0;
    for (int j = t; j < PW; j += 256){
        float p = 0.f;
        if (j < nkv){ p = v[cnt] * inv; cnt++; }
        unsigned short h, l;
        split_bf16(p, h, l);
        PH[po + j] = __ushort_as_bfloat16(h);
        PL[po + j] = __ushort_as_bfloat16(l);
    }
}

// ---------------- av mma: ATT = P @ V --------------------------------------
__global__ __launch_bounds__(256, 2) void av_mma(const __nv_bfloat16* __restrict__ PHp,
                                                 const __nv_bfloat16* __restrict__ PLp,
                                                 const __nv_bfloat16* __restrict__ VTHp,
                                                 const __nv_bfloat16* __restrict__ VTLp,
                                                 float* __restrict__ out,
                                                 int Kav){
    extern __shared__ __align__(16) char sm[];   // 2 stages * 24576
    uint32_t sb = smem_u32(sm);
    int t = threadIdx.x, lane = t & 31, warp = t >> 5;
    int wm = (warp >> 1) * 32, wn = (warp & 1) * 32;
    int bh = blockIdx.z, b = bh >> 3, h = bh & 7;
    int i0 = blockIdx.y * 128;
    const __nv_bfloat16* srcA[2] = { PHp + ((long)bh*NQ + i0)*PW,
                                     PLp + ((long)bh*NQ + i0)*PW };
    const __nv_bfloat16* srcB[2] = { VTHp + (long)b*DH*PW,
                                     VTLp + (long)b*DH*PW };
    int lr = t >> 2, lc = t & 3;

    float acc[2][4][4];
    #pragma unroll
    for (int i=0;i<2;i++)
        #pragma unroll
        for (int j=0;j<4;j++)
            #pragma unroll
            for (int e=0;e<4;e++) acc[i][j][e] = 0.f;

    #define VLOAD(st, k0) do {                                                  \
        _Pragma("unroll")                                                       \
        for (int tt = 0; tt < 2; tt++){                                         \
            const __nv_bfloat16* s = srcA[tt] + (k0);                           \
            uint32_t so = sb + (st)*24576 + tt*8192;                            \
            cpa(so + SWOFF(lr, lc),      s + (long)lr*PW + lc*8);               \
            cpa(so + SWOFF(lr+64, lc),   s + (long)(lr+64)*PW + lc*8);          \
        }                                                                       \
        _Pragma("unroll")                                                       \
        for (int tt = 0; tt < 2; tt++){                                         \
            const __nv_bfloat16* s = srcB[tt] + (k0);                           \
            uint32_t so = sb + (st)*24576 + 16384 + tt*4096;                    \
            cpa(so + SWOFF(lr, lc),      s + (long)lr*PW + lc*8);               \
        }                                                                       \
        CP_COMMIT(); } while(0)

    int nch = Kav >> 5;
    VLOAD(0, 0);
    for (int c = 0; c < nch; c++){
        int st = c & 1;
        if (c + 1 < nch){ VLOAD((c+1)&1, (c+1)*32); CP_WAIT1(); }
        else CP_WAIT0();
        __syncthreads();
        uint32_t ss = sb + st*24576;
        #pragma unroll
        for (int s = 0; s < 2; s++){
            uint32_t ah[2][4], al[2][4], bhf[4][2], blf[4][2];
            #pragma unroll
            for (int mt = 0; mt < 2; mt++){
                int r = wm + mt*16 + (lane & 15);
                int cl = 2*s + (lane >> 4);
                uint32_t addr = ss + SWOFF(r, cl);
                ldsm4(ah[mt], addr);
                ldsm4(al[mt], addr + 8192);
            }
            #pragma unroll
            for (int g = 0; g < 2; g++){
                int r = wn + g*16 + (lane & 7) + ((lane >> 4) << 3);
                int cl = 2*s + ((lane >> 3) & 1);
                uint32_t addr = ss + 16384 + SWOFF(r, cl);
                uint32_t tmp[4];
                ldsm4(tmp, addr);
                bhf[2*g][0]=tmp[0]; bhf[2*g][1]=tmp[1]; bhf[2*g+1][0]=tmp[2]; bhf[2*g+1][1]=tmp[3];
                ldsm4(tmp, addr + 4096);
                blf[2*g][0]=tmp[0]; blf[2*g][1]=tmp[1]; blf[2*g+1][0]=tmp[2]; blf[2*g+1][1]=tmp[3];
            }
            #pragma unroll
            for (int mt = 0; mt < 2; mt++)
                #pragma unroll
                for (int nt = 0; nt < 4; nt++){
                    mma16816(acc[mt][nt], ah[mt], bhf[nt][0], bhf[nt][1]);
                    mma16816(acc[mt][nt], ah[mt], blf[nt][0], blf[nt][1]);
                    mma16816(acc[mt][nt], al[mt], bhf[nt][0], bhf[nt][1]);
                }
        }
        __syncthreads();
    }
    #undef VLOAD

    #pragma unroll
    for (int mt = 0; mt < 2; mt++){
        long grow = (long)b*NQ + i0 + wm + mt*16 + (lane >> 2);
        #pragma unroll
        for (int nt = 0; nt < 4; nt++){
            int c = wn + nt*8 + 2*(lane & 3);
            float2 v0; v0.x = acc[mt][nt][0]; v0.y = acc[mt][nt][1];
            float2 v1; v1.x = acc[mt][nt][2]; v1.y = acc[mt][nt][3];
            *(float2*)(out + grow*DD + h*DH + c)     = v0;
            *(float2*)(out + (grow+8)*DD + h*DH + c) = v1;
        }
    }
}

// ---------------- orchestration --------------------------------------------
extern "C" void kernel_launch(void* const* d_in, const int* in_sizes, int n_in,
                              void* d_out, int out_size){
    const float* x_in    = (const float*)d_in[0];
    const float* ctx     = (const float*)d_in[1];
    const float* rel_emb = (const float*)d_in[2];
    const float* sa_ng   = (const float*)d_in[3];
    const float* sa_wq   = (const float*)d_in[4];
    const float* sa_wkv  = (const float*)d_in[5];
    const float* sa_null = (const float*)d_in[6];
    const float* sa_wo   = (const float*)d_in[7];
    const float* sa_og   = (const float*)d_in[8];
    const float* ca_ng   = (const float*)d_in[9];
    const float* ca_cg   = (const float*)d_in[10];
    const float* ca_wq   = (const float*)d_in[11];
    const float* ca_wkv  = (const float*)d_in[12];
    const float* ca_null = (const float*)d_in[13];
    const float* ca_wo   = (const float*)d_in[14];
    const float* ca_og   = (const float*)d_in[15];
    const float* ff_ng   = (const float*)d_in[16];
    const float* ff_w1   = (const float*)d_in[17];
    const float* ff_w2   = (const float*)d_in[18];
    const float* normg   = (const float*)d_in[19];
    float* out = (float*)d_out;

    cudaFuncSetAttribute(tgemm3,     cudaFuncAttributeMaxDynamicSharedMemorySize, 65536);
    cudaFuncSetAttribute(scores_mma, cudaFuncAttributeMaxDynamicSharedMemorySize, 65536);
    cudaFuncSetAttribute(av_mma,     cudaFuncAttributeMaxDynamicSharedMemorySize, 49152);

    float *X,*XN,*CTXN,*Q,*KV,*ATT,*HHp,*HG,*SC;
    __nv_bfloat16 *AH,*AL,*BH,*BL,*KH,*KL,*VTH,*VTL,*PH,*PL;
    cudaGetSymbolAddress((void**)&X,    g_x);
    cudaGetSymbolAddress((void**)&XN,   g_xn);
    cudaGetSymbolAddress((void**)&CTXN, g_ctxn);
    cudaGetSymbolAddress((void**)&Q,    g_q);
    cudaGetSymbolAddress((void**)&KV,   g_kv);
    cudaGetSymbolAddress((void**)&ATT,  g_att);
    cudaGetSymbolAddress((void**)&HHp,  g_hh);
    cudaGetSymbolAddress((void**)&HG,   g_hg);
    cudaGetSymbolAddress((void**)&SC,   g_sc);
    cudaGetSymbolAddress((void**)&AH,   g_AH);
    cudaGetSymbolAddress((void**)&AL,   g_AL);
    cudaGetSymbolAddress((void**)&BH,   g_BH);
    cudaGetSymbolAddress((void**)&BL,   g_BL);
    cudaGetSymbolAddress((void**)&KH,   g_KH);
    cudaGetSymbolAddress((void**)&KL,   g_KL);
    cudaGetSymbolAddress((void**)&VTH,  g_VTH);
    cudaGetSymbolAddress((void**)&VTL,  g_VTL);
    cudaGetSymbolAddress((void**)&PH,   g_PH);
    cudaGetSymbolAddress((void**)&PL,   g_PL);
    __nv_bfloat16 *AH2 = AH + (size_t)4*1024*1024;
    __nv_bfloat16 *AL2 = AL + (size_t)4*1024*1024;

    copy_kernel<<<512, 256>>>(x_in, X, RR*DD);

    for (int l = 0; l < LL; l++){
        // ---------------- self-attention ----------------
        ln_kernel<<<RR, 256>>>(X, sa_ng + l*DD, XN, DD);
        convA<<<512, 256>>>(XN, AH, AL, RR*DD/4);
        convBT<<<dim3(DD/32, DD/32), 256>>>(sa_wq + (size_t)l*DD*DD, BH, BL, DD, DD);
        tgemm3<<<dim3(DD/128, RR/128), 256, 65536>>>(AH, AL, BH, BL, Q, RR, DD, DD);
        convBT<<<dim3(128/32, DD/32), 256>>>(sa_wkv + (size_t)l*DD*128, BH, BL, DD, 128);
        tgemm3<<<dim3(1, RR/128), 256, 65536>>>(AH, AL, BH, BL, KV, RR, 128, DD);
        qprep_kernel<<<RR, 256>>>(Q, NQ, 1);
        kvprep2<<<BB*PADS, 64>>>(KV, sa_null + l*128, KH, KL, VTH, VTL, NQ, 1, PADS);
        convA<<<512, 256>>>(Q, AH, AL, RR*DD/4);
        scores_mma<<<dim3(PADS/128, NQ/128, BB*HH), 256, 65536>>>(AH, AL, KH, KL, rel_emb, SC, NQ+1, 1);
        softmax_split<<<BB*HH*NQ, 256>>>(SC, PH, PL, NQ+1);
        av_mma<<<dim3(1, NQ/128, BB*HH), 256, 49152>>>(PH, PL, VTH, VTL, ATT, 1056);
        convA<<<512, 256>>>(ATT, AH, AL, RR*DD/4);
        convBT<<<dim3(DD/32, DD/32), 256>>>(sa_wo + (size_t)l*DD*DD, BH, BL, DD, DD);
        tgemm3<<<dim3(DD/128, RR/128), 256, 65536>>>(AH, AL, BH, BL, Q, RR, DD, DD);
        ln_res_kernel<<<RR, 256>>>(Q, sa_og + l*DD, X, DD);

        // ---------------- cross-attention ----------------
        ln_kernel<<<RR, 256>>>(X, ca_ng + l*DD, XN, DD);
        ln_kernel<<<CR, 256>>>(ctx, ca_cg + l*PP, CTXN, PP);
        convA<<<512, 256>>>(XN, AH, AL, RR*DD/4);
        convA<<<512, 256>>>(CTXN, AH2, AL2, CR*PP/4);
        convBT<<<dim3(DD/32, DD/32), 256>>>(ca_wq + (size_t)l*DD*DD, BH, BL, DD, DD);
        tgemm3<<<dim3(DD/128, RR/128), 256, 65536>>>(AH, AL, BH, BL, Q, RR, DD, DD);
        convBT<<<dim3(128/32, PP/32), 256>>>(ca_wkv + (size_t)l*PP*128, BH, BL, PP, 128);
        tgemm3<<<dim3(1, CR/128), 256, 65536>>>(AH2, AL2, BH, BL, KV, CR, 128, PP);
        qprep_kernel<<<RR, 256>>>(Q, NQ, 0);
        kvprep2<<<BB*640, 64>>>(KV, ca_null + l*128, KH, KL, VTH, VTL, MM, 0, 640);
        convA<<<512, 256>>>(Q, AH, AL, RR*DD/4);
        scores_mma<<<dim3(640/128, NQ/128, BB*HH), 256, 65536>>>(AH, AL, KH, KL, rel_emb, SC, MM+1, 0);
        softmax_split<<<BB*HH*NQ, 256>>>(SC, PH, PL, MM+1);
        av_mma<<<dim3(1, NQ/128, BB*HH), 256, 49152>>>(PH, PL, VTH, VTL, ATT, 544);
        convA<<<512, 256>>>(ATT, AH, AL, RR*DD/4);
        convBT<<<dim3(DD/32, DD/32), 256>>>(ca_wo + (size_t)l*DD*DD, BH, BL, DD, DD);
        tgemm3<<<dim3(DD/128, RR/128), 256, 65536>>>(AH, AL, BH, BL, Q, RR, DD, DD);
        ln_res_kernel<<<RR, 256>>>(Q, ca_og + l*DD, X, DD);

        // ---------------- feed-forward (SwiGLU) ----------------
        ln_kernel<<<RR, 256>>>(X, ff_ng + l*DD, XN, DD);
        convA<<<512, 256>>>(XN, AH, AL, RR*DD/4);
        convBT<<<dim3((2*FFI)/32, DD/32), 256>>>(ff_w1 + (size_t)l*DD*2*FFI, BH, BL, DD, 2*FFI);
        tgemm3<<<dim3((2*FFI)/128, RR/128), 256, 65536>>>(AH, AL, BH, BL, HG, RR, 2*FFI, DD);
        glu_kernel<<<2048, 256>>>(HG, HHp);
        convA<<<1024, 256>>>(HHp, AH, AL, RR*FFI/4);
        convBT<<<dim3(DD/32, FFI/32), 256>>>(ff_w2 + (size_t)l*FFI*DD, BH, BL, FFI, DD);
        tgemm3<<<dim3(DD/128, RR/128), 256, 65536>>>(AH, AL, BH, BL, Q, RR, DD, FFI);
        add_kernel<<<1024, 256>>>(X, Q, RR*DD);
    }

    final_ln_kernel<<<RR, 256>>>(X, normg, out, DD);
}

// round 8
// speedup vs baseline: 2.1601x; 1.4649x over previous
#include <cuda_runtime.h>
#include <cuda_bf16.h>
#include <math.h>
#include <stdint.h>

// Problem constants
#define BB   4
#define NQ   1024
#define MM   512
#define DD   512
#define PP   256
#define HH   8
#define DH   64
#define LL   6
#define FFI  2048
#define RR   (BB*NQ)        // 4096
#define CR   (BB*MM)        // 2048
#define PADS 1152           // padded kv rows
#define PW   1152           // V^T row stride

// ---------------- scratch (static device globals) --------------------------
__device__ float g_x   [RR*DD];
__device__ float g_xn  [RR*DD];
__device__ float g_ctxn[CR*PP];
__device__ float g_q   [RR*DD];
__device__ float g_kv  [RR*128];
__device__ float g_att [RR*DD];
__device__ float g_hh  [(size_t)RR*FFI];
__device__ float g_hg  [(size_t)RR*2*FFI];
__device__ float g_bias[HH*1024];
__device__ __nv_bfloat16 g_AH[(size_t)RR*FFI];
__device__ __nv_bfloat16 g_AL[(size_t)RR*FFI];
__device__ __nv_bfloat16 g_BH[(size_t)2*1024*1024];
__device__ __nv_bfloat16 g_BL[(size_t)2*1024*1024];
__device__ __nv_bfloat16 g_KH[(size_t)BB*PADS*DH];
__device__ __nv_bfloat16 g_KL[(size_t)BB*PADS*DH];
__device__ __nv_bfloat16 g_VTH[(size_t)BB*DH*PW];
__device__ __nv_bfloat16 g_VTL[(size_t)BB*DH*PW];

// ---------------- reductions ------------------------------------------------
__device__ __forceinline__ float warpSum(float v){
    #pragma unroll
    for (int o=16;o;o>>=1) v += __shfl_xor_sync(0xffffffffu, v, o);
    return v;
}
__device__ __forceinline__ float warpMax(float v){
    #pragma unroll
    for (int o=16;o;o>>=1) v = fmaxf(v, __shfl_xor_sync(0xffffffffu, v, o));
    return v;
}
__device__ float blockSum(float v){
    __shared__ float sh[8];
    int lane = threadIdx.x & 31, w = threadIdx.x >> 5;
    v = warpSum(v);
    if (lane == 0) sh[w] = v;
    __syncthreads();
    v = (threadIdx.x < 8) ? sh[threadIdx.x] : 0.f;
    v = warpSum(v);
    if (threadIdx.x == 0) sh[0] = v;
    __syncthreads();
    float r = sh[0];
    __syncthreads();
    return r;
}
__device__ float blockMax(float v){
    __shared__ float sh[8];
    int lane = threadIdx.x & 31, w = threadIdx.x >> 5;
    v = warpMax(v);
    if (lane == 0) sh[w] = v;
    __syncthreads();
    v = (threadIdx.x < 8) ? sh[threadIdx.x] : -3.4e38f;
    v = warpMax(v);
    if (threadIdx.x == 0) sh[0] = v;
    __syncthreads();
    float r = sh[0];
    __syncthreads();
    return r;
}

// ---------------- elementwise ----------------------------------------------
__global__ void copy_kernel(const float* __restrict__ in, float* __restrict__ out, int n){
    for (int i = blockIdx.x*blockDim.x + threadIdx.x; i < n; i += gridDim.x*blockDim.x)
        out[i] = in[i];
}
__global__ void add_kernel(float* __restrict__ x, const float* __restrict__ y, int n){
    for (int i = blockIdx.x*blockDim.x + threadIdx.x; i < n; i += gridDim.x*blockDim.x)
        x[i] += y[i];
}
__global__ void glu_kernel(const float* __restrict__ hg, float* __restrict__ out){
    long total = (long)RR * FFI;
    for (long i = blockIdx.x*(long)blockDim.x + threadIdx.x; i < total; i += gridDim.x*(long)blockDim.x){
        long r = i / FFI; int c = (int)(i - r*FFI);
        float h = hg[r*(2*FFI) + c];
        float g = hg[r*(2*FFI) + FFI + c];
        out[i] = h * (g / (1.f + expf(-g)));
    }
}
// rel-pos bias table: tab[h][n] for n = clamped distance (computed once)
__global__ void bias_tab_kernel(const float* __restrict__ rel_emb, float* __restrict__ tab){
    int n = blockIdx.x*256 + threadIdx.x;
    if (n >= 1024) return;
    int bucket;
    if (n < 16) bucket = n;
    else {
        int large = 16 + (int)(logf((float)n * 0.0625f) * (16.0f / 2.0794415416798357f));
        bucket = large < 31 ? large : 31;
    }
    #pragma unroll
    for (int h = 0; h < HH; h++)
        tab[h*1024 + n] = rel_emb[bucket*HH + h];
}

// ---------------- bf16 split helpers ---------------------------------------
__device__ __forceinline__ void split_bf16(float x, unsigned short& h, unsigned short& l){
    __nv_bfloat16 hb = __float2bfloat16_rn(x);
    __nv_bfloat16 lb = __float2bfloat16_rn(x - __bfloat162float(hb));
    h = __bfloat16_as_ushort(hb);
    l = __bfloat16_as_ushort(lb);
}
__global__ void convA(const float* __restrict__ in, __nv_bfloat16* __restrict__ hi,
                      __nv_bfloat16* __restrict__ lo, int n4){
    for (int i = blockIdx.x*blockDim.x + threadIdx.x; i < n4; i += gridDim.x*blockDim.x){
        float4 v = ((const float4*)in)[i];
        unsigned short h0,h1,h2,h3,l0,l1,l2,l3;
        split_bf16(v.x,h0,l0); split_bf16(v.y,h1,l1);
        split_bf16(v.z,h2,l2); split_bf16(v.w,h3,l3);
        uint2 ph, pl;
        ph.x = (uint32_t)h0 | ((uint32_t)h1 << 16);
        ph.y = (uint32_t)h2 | ((uint32_t)h3 << 16);
        pl.x = (uint32_t)l0 | ((uint32_t)l1 << 16);
        pl.y = (uint32_t)l2 | ((uint32_t)l3 << 16);
        ((uint2*)hi)[i] = ph;
        ((uint2*)lo)[i] = pl;
    }
}
// B: fp32 [K][N] -> hi/lo bf16 transposed [N][K]
__global__ __launch_bounds__(256) void convBT(const float* __restrict__ Bm,
                                              __nv_bfloat16* __restrict__ hi,
                                              __nv_bfloat16* __restrict__ lo,
                                              int K, int N){
    __shared__ float tile[32][33];
    int tx = threadIdx.x & 31, ty = threadIdx.x >> 5;
    int n0 = blockIdx.x*32, k0 = blockIdx.y*32;
    #pragma unroll
    for (int i = 0; i < 4; i++)
        tile[ty + 8*i][tx] = Bm[(long)(k0 + ty + 8*i)*N + n0 + tx];
    __syncthreads();
    #pragma unroll
    for (int i = 0; i < 4; i++){
        int n = ty + 8*i;
        float v = tile[tx][n];
        unsigned short h, l;
        split_bf16(v, h, l);
        long off = (long)(n0 + n)*K + k0 + tx;
        hi[off] = __ushort_as_bfloat16(h);
        lo[off] = __ushort_as_bfloat16(l);
    }
}

// ---------------- layernorm family -----------------------------------------
__global__ __launch_bounds__(256) void ln_kernel(const float* __restrict__ in,
                                                 const float* __restrict__ g,
                                                 float* __restrict__ out, int cols){
    long ro = (long)blockIdx.x * cols;
    int t = threadIdx.x;
    float v0 = (t       < cols) ? in[ro + t]       : 0.f;
    float v1 = (t + 256 < cols) ? in[ro + t + 256] : 0.f;
    float mu = blockSum(v0 + v1) / (float)cols;
    float d0 = (t       < cols) ? v0 - mu : 0.f;
    float d1 = (t + 256 < cols) ? v1 - mu : 0.f;
    float var = blockSum(d0*d0 + d1*d1) / (float)cols;
    float inv = 1.f / sqrtf(var + 1e-5f);
    if (t       < cols) out[ro + t]       = d0 * inv * g[t];
    if (t + 256 < cols) out[ro + t + 256] = d1 * inv * g[t + 256];
}
__global__ __launch_bounds__(256) void ln_res_kernel(const float* __restrict__ in,
                                                     const float* __restrict__ g,
                                                     float* __restrict__ x, int cols){
    long ro = (long)blockIdx.x * cols;
    int t = threadIdx.x;
    float v0 = (t       < cols) ? in[ro + t]       : 0.f;
    float v1 = (t + 256 < cols) ? in[ro + t + 256] : 0.f;
    float mu = blockSum(v0 + v1) / (float)cols;
    float d0 = (t       < cols) ? v0 - mu : 0.f;
    float d1 = (t + 256 < cols) ? v1 - mu : 0.f;
    float var = blockSum(d0*d0 + d1*d1) / (float)cols;
    float inv = 1.f / sqrtf(var + 1e-5f);
    if (t       < cols) x[ro + t]       += d0 * inv * g[t];
    if (t + 256 < cols) x[ro + t + 256] += d1 * inv * g[t + 256];
}
__global__ __launch_bounds__(256) void final_ln_kernel(const float* __restrict__ in,
                                                       const float* __restrict__ g,
                                                       float* __restrict__ out, int cols){
    long ro = (long)blockIdx.x * cols;
    int t = threadIdx.x;
    float v0 = (t       < cols) ? in[ro + t]       : 0.f;
    float v1 = (t + 256 < cols) ? in[ro + t + 256] : 0.f;
    float m0 = (t       < cols) ? v0 : -3.4e38f;
    float m1 = (t + 256 < cols) ? v1 : -3.4e38f;
    float mx = blockMax(fmaxf(m0, m1));
    v0 /= mx; v1 /= mx;
    float s0 = (t       < cols) ? v0 : 0.f;
    float s1 = (t + 256 < cols) ? v1 : 0.f;
    float mu = blockSum(s0 + s1) / (float)cols;
    float d0 = (t       < cols) ? v0 - mu : 0.f;
    float d1 = (t + 256 < cols) ? v1 - mu : 0.f;
    float var = blockSum(d0*d0 + d1*d1) / (float)cols;
    float inv = 1.f / sqrtf(var + 1e-5f);
    if (t       < cols) out[ro + t]       = d0 * inv * g[t];
    if (t + 256 < cols) out[ro + t + 256] = d1 * inv * g[t + 256];
}

// ---------------- rotary / prep --------------------------------------------
__device__ __forceinline__ float inv_freq(int m){
    return powf(10000.f, -(float)m * (1.f/16.f));
}
// q fp32 -> scaled/rotated hi/lo bf16 (same [row][512] layout)
__global__ __launch_bounds__(256) void qprep_split(const float* __restrict__ q,
                                                   __nv_bfloat16* __restrict__ QH,
                                                   __nv_bfloat16* __restrict__ QL,
                                                   int n, int use_rot){
    int row = blockIdx.x;
    int r = threadIdx.x;
    int h = r >> 5, t = r & 31;
    const float* p = q + (long)row * DD + h * DH;
    long ob = (long)row * DD + h * DH;
    const float sc = 0.125f;
    float va, vb; int ia, ib;
    if (t < 16){
        float a = p[t] * sc, b = p[t+16] * sc;
        if (use_rot){
            float f = (float)(row % n) * inv_freq(t);
            float cf = cosf(f), sf = sinf(f);
            va = a*cf - b*sf; vb = a*sf + b*cf;
        } else { va = a; vb = b; }
        ia = t; ib = t + 16;
    } else {
        va = p[t+16] * sc; vb = p[t+32] * sc;
        ia = t + 16; ib = t + 32;
    }
    unsigned short hh, ll;
    split_bf16(va, hh, ll);
    QH[ob+ia] = __ushort_as_bfloat16(hh); QL[ob+ia] = __ushort_as_bfloat16(ll);
    split_bf16(vb, hh, ll);
    QH[ob+ib] = __ushort_as_bfloat16(hh); QL[ob+ib] = __ushort_as_bfloat16(ll);
}
// kv -> split bf16 K [b][j][d] (padded rows zeroed) and V^T [b][d][j]
__global__ __launch_bounds__(64) void kvprep2(const float* __restrict__ kv,
                                              const float* __restrict__ null_kv,
                                              __nv_bfloat16* __restrict__ KH, __nv_bfloat16* __restrict__ KL,
                                              __nv_bfloat16* __restrict__ VTH, __nv_bfloat16* __restrict__ VTL,
                                              int nk, int use_rot, int padK){
    int rblk = blockIdx.x;
    int d = threadIdx.x;
    int nkv = nk + 1;
    int b = rblk / padK, j = rblk % padK;
    long koff = ((long)b * PADS + j) * DH + d;
    long voff = ((long)b * DH + d) * PW + j;
    if (j >= nkv){
        KH[koff] = __ushort_as_bfloat16(0); KL[koff] = __ushort_as_bfloat16(0);
        VTH[voff] = __ushort_as_bfloat16(0); VTL[voff] = __ushort_as_bfloat16(0);
        return;
    }
    float kval, vval;
    if (j == 0){
        kval = null_kv[d];
        vval = null_kv[DH + d];
    } else {
        int i = j - 1;
        const float* src = kv + ((long)b * nk + i) * 128;
        kval = src[d];
        vval = src[DH + d];
        if (use_rot && d < 32){
            int m = d & 15;
            float f = (float)i * inv_freq(m);
            float cf = cosf(f), sf = sinf(f);
            if (d < 16) kval = kval*cf - src[d+16]*sf;
            else        kval = kval*cf + src[d-16]*sf;
        }
    }
    unsigned short h, l;
    split_bf16(kval, h, l);
    KH[koff] = __ushort_as_bfloat16(h); KL[koff] = __ushort_as_bfloat16(l);
    split_bf16(vval, h, l);
    VTH[voff] = __ushort_as_bfloat16(h); VTL[voff] = __ushort_as_bfloat16(l);
}

// ============================================================================
//  mma helpers
// ============================================================================
__device__ __forceinline__ uint32_t smem_u32(const void* p){
    uint32_t a;
    asm("{ .reg .u64 t; cvta.to.shared.u64 t, %1; cvt.u32.u64 %0, t; }" : "=r"(a) : "l"(p));
    return a;
}
__device__ __forceinline__ void cpa(uint32_t sm, const void* g){
    asm volatile("cp.async.ca.shared.global [%0], [%1], 16;" :: "r"(sm), "l"(g));
}
#define CP_COMMIT() asm volatile("cp.async.commit_group;" ::: "memory")
#define CP_WAIT1()  asm volatile("cp.async.wait_group 1;" ::: "memory")
#define CP_WAIT0()  asm volatile("cp.async.wait_group 0;" ::: "memory")
__device__ __forceinline__ void ldsm4(uint32_t* r, uint32_t addr){
    asm volatile("ldmatrix.sync.aligned.m8n8.x4.shared.b16 {%0,%1,%2,%3}, [%4];"
        : "=r"(r[0]),"=r"(r[1]),"=r"(r[2]),"=r"(r[3]) : "r"(addr));
}
__device__ __forceinline__ void mma16816(float* d, const uint32_t* a, uint32_t b0, uint32_t b1){
    asm volatile("mma.sync.aligned.m16n8k16.row.col.f32.bf16.bf16.f32 "
        "{%0,%1,%2,%3}, {%4,%5,%6,%7}, {%8,%9}, {%0,%1,%2,%3};"
        : "+f"(d[0]),"+f"(d[1]),"+f"(d[2]),"+f"(d[3])
        : "r"(a[0]),"r"(a[1]),"r"(a[2]),"r"(a[3]), "r"(b0),"r"(b1));
}
// 32-col tiles (dense gemm): 4 chunks/row
#define SWOFF(r,c)  ((((r)*4 + ((c) ^ (((r)>>1)&3)))) << 4)
// 64-col tiles (flash): 8 chunks/row
#define SWOFF8(r,c) ((((r)*8 + ((c) ^ ((r)&7)))) << 4)

#define COMPUTE_128x128(ss)                                                        \
    _Pragma("unroll")                                                              \
    for (int s = 0; s < 2; s++){                                                   \
        uint32_t ah[4][4], al[4][4], bhf[4][2], blf[4][2];                         \
        _Pragma("unroll")                                                          \
        for (int mt = 0; mt < 4; mt++){                                            \
            int r = wm + mt*16 + (lane & 15);                                      \
            int cl = 2*s + (lane >> 4);                                            \
            uint32_t addr = (ss) + SWOFF(r, cl);                                   \
            ldsm4(ah[mt], addr);                                                   \
            ldsm4(al[mt], addr + 8192);                                            \
        }                                                                          \
        _Pragma("unroll")                                                          \
        for (int g = 0; g < 2; g++){                                               \
            int r = wn + g*16 + (lane & 7) + ((lane >> 4) << 3);                   \
            int cl = 2*s + ((lane >> 3) & 1);                                      \
            uint32_t addr = (ss) + 16384 + SWOFF(r, cl);                           \
            uint32_t tmp[4];                                                       \
            ldsm4(tmp, addr);                                                      \
            bhf[2*g][0]=tmp[0]; bhf[2*g][1]=tmp[1]; bhf[2*g+1][0]=tmp[2]; bhf[2*g+1][1]=tmp[3]; \
            ldsm4(tmp, addr + 8192);                                               \
            blf[2*g][0]=tmp[0]; blf[2*g][1]=tmp[1]; blf[2*g+1][0]=tmp[2]; blf[2*g+1][1]=tmp[3]; \
        }                                                                          \
        _Pragma("unroll")                                                          \
        for (int mt = 0; mt < 4; mt++)                                             \
            _Pragma("unroll")                                                      \
            for (int nt = 0; nt < 4; nt++){                                        \
                mma16816(acc[mt][nt], ah[mt], bhf[nt][0], bhf[nt][1]);             \
                mma16816(acc[mt][nt], ah[mt], blf[nt][0], blf[nt][1]);             \
                mma16816(acc[mt][nt], al[mt], bhf[nt][0], bhf[nt][1]);             \
            }                                                                      \
    }

// ---------------- dense GEMM: C = A[MxK] @ B'[NxK]^T -----------------------
__global__ __launch_bounds__(256, 2) void tgemm3(const __nv_bfloat16* __restrict__ Ah,
                                                 const __nv_bfloat16* __restrict__ Al,
                                                 const __nv_bfloat16* __restrict__ Bh,
                                                 const __nv_bfloat16* __restrict__ Bl,
                                                 float* __restrict__ C,
                                                 int M, int N, int K){
    extern __shared__ __align__(16) char sm[];   // 2 stages * 32768
    uint32_t sb = smem_u32(sm);
    int t = threadIdx.x, lane = t & 31, warp = t >> 5;
    int wm = (warp >> 2) * 64, wn = (warp & 3) * 32;
    long rowBase = (long)blockIdx.y * 128;
    long colBase = (long)blockIdx.x * 128;
    const __nv_bfloat16* srcs[4] = { Ah + rowBase*K, Al + rowBase*K,
                                     Bh + colBase*K, Bl + colBase*K };
    int lr = t >> 2, lc = t & 3;

    float acc[4][4][4];
    #pragma unroll
    for (int i=0;i<4;i++)
        #pragma unroll
        for (int j=0;j<4;j++)
            #pragma unroll
            for (int e=0;e<4;e++) acc[i][j][e] = 0.f;

    #define DLOAD(st, k0) do {                                                  \
        _Pragma("unroll")                                                       \
        for (int tt = 0; tt < 4; tt++){                                         \
            const __nv_bfloat16* s = srcs[tt] + (k0);                           \
            uint32_t so = sb + (st)*32768 + tt*8192;                            \
            cpa(so + SWOFF(lr, lc),      s + (long)lr*K + lc*8);                \
            cpa(so + SWOFF(lr+64, lc),   s + (long)(lr+64)*K + lc*8);           \
        }                                                                       \
        CP_COMMIT(); } while(0)

    int nch = K >> 5;
    DLOAD(0, 0);
    for (int c = 0; c < nch; c++){
        int st = c & 1;
        if (c + 1 < nch){ DLOAD((c+1)&1, (c+1)*32); CP_WAIT1(); }
        else CP_WAIT0();
        __syncthreads();
        uint32_t ss = sb + st*32768;
        COMPUTE_128x128(ss);
        __syncthreads();
    }
    #undef DLOAD

    #pragma unroll
    for (int mt = 0; mt < 4; mt++){
        long r = rowBase + wm + mt*16 + (lane >> 2);
        #pragma unroll
        for (int nt = 0; nt < 4; nt++){
            long cc = colBase + wn + nt*8 + 2*(lane & 3);
            float2 v0; v0.x = acc[mt][nt][0]; v0.y = acc[mt][nt][1];
            float2 v1; v1.x = acc[mt][nt][2]; v1.y = acc[mt][nt][3];
            *(float2*)(C + r*N + cc)     = v0;
            *(float2*)(C + (r+8)*N + cc) = v1;
        }
    }
}

// ============================================================================
//  Fused flash attention: out = softmax(Q K^T + bias, mask) V
//  CTA = 64 q-rows x (b,h); 4 warps x 16 rows; j-tiles of 64.
//  smem: QH 0 | QL 8192 | KH 16384 | KL 24576 | VH 32768 | VL 40960 | bias 49152
// ============================================================================
#define FSM_Q  0
#define FSM_K  16384
#define FSM_V  32768
#define FSM_B  49152
#define FSM_TOT (49152 + 4096)

__global__ __launch_bounds__(128) void flash_attn(const __nv_bfloat16* __restrict__ Qh,
                                                  const __nv_bfloat16* __restrict__ Ql,
                                                  const __nv_bfloat16* __restrict__ KHp,
                                                  const __nv_bfloat16* __restrict__ KLp,
                                                  const __nv_bfloat16* __restrict__ VTHp,
                                                  const __nv_bfloat16* __restrict__ VTLp,
                                                  const float* __restrict__ bias_tab,
                                                  float* __restrict__ out,
                                                  int nkv, int cb){
    extern __shared__ __align__(16) char sm[];
    uint32_t sb = smem_u32(sm);
    int t = threadIdx.x, lane = t & 31, warp = t >> 5;
    int bh = blockIdx.y, b = bh >> 3, h = bh & 7;
    int i0 = blockIdx.x * 64;

    // ---- load Q tile (64 x 64) hi/lo ----
    {
        const __nv_bfloat16* qh = Qh + ((long)(b*NQ + i0))*DD + h*DH;
        const __nv_bfloat16* ql = Ql + ((long)(b*NQ + i0))*DD + h*DH;
        for (int i = t; i < 512; i += 128){
            int r = i >> 3, c = i & 7;
            cpa(sb + FSM_Q        + SWOFF8(r,c), qh + (long)r*DD + c*8);
            cpa(sb + FSM_Q + 8192 + SWOFF8(r,c), ql + (long)r*DD + c*8);
        }
        CP_COMMIT();
    }
    if (cb){
        float* bsm = (float*)(sm + FSM_B);
        for (int i = t; i < 1024; i += 128) bsm[i] = bias_tab[h*1024 + i];
    }
    CP_WAIT0();
    __syncthreads();

    // ---- Q A-fragments in registers ----
    uint32_t qfh[4][4], qfl[4][4];
    #pragma unroll
    for (int s = 0; s < 4; s++){
        int r = warp*16 + (lane & 15);
        int cl = 2*s + (lane >> 4);
        ldsm4(qfh[s], sb + FSM_Q + SWOFF8(r, cl));
        ldsm4(qfl[s], sb + FSM_Q + 8192 + SWOFF8(r, cl));
    }

    float o[8][4];
    #pragma unroll
    for (int i=0;i<8;i++)
        #pragma unroll
        for (int e=0;e<4;e++) o[i][e] = 0.f;
    float mx0 = -3.0e38f, mx1 = -3.0e38f, sum0 = 0.f, sum1 = 0.f;

    int jt_max = (nkv - 1) >> 6;
    if (cb){ int jm = (i0 + 64) >> 6; if (jm < jt_max) jt_max = jm; }
    const __nv_bfloat16* kh = KHp + (long)b*PADS*DH;
    const __nv_bfloat16* kl = KLp + (long)b*PADS*DH;
    const __nv_bfloat16* vh = VTHp + (long)b*DH*PW;
    const __nv_bfloat16* vl = VTLp + (long)b*DH*PW;
    const float* bsm = (const float*)(sm + FSM_B);

    for (int jt = 0; jt <= jt_max; jt++){
        // ---- load K (j x d) and V^T (d x j) tiles ----
        for (int i = t; i < 512; i += 128){
            int r = i >> 3, c = i & 7;
            cpa(sb + FSM_K        + SWOFF8(r,c), kh + ((long)(jt*64 + r))*DH + c*8);
            cpa(sb + FSM_K + 8192 + SWOFF8(r,c), kl + ((long)(jt*64 + r))*DH + c*8);
            cpa(sb + FSM_V        + SWOFF8(r,c), vh + (long)r*PW + jt*64 + c*8);
            cpa(sb + FSM_V + 8192 + SWOFF8(r,c), vl + (long)r*PW + jt*64 + c*8);
        }
        CP_COMMIT(); CP_WAIT0();
        __syncthreads();

        // ---- S = Q K^T (16 rows x 64 j per warp) ----
        float sacc[8][4];
        #pragma unroll
        for (int i=0;i<8;i++)
            #pragma unroll
            for (int e=0;e<4;e++) sacc[i][e] = 0.f;
        #pragma unroll
        for (int s = 0; s < 4; s++){
            uint32_t bhf[8][2], blf[8][2];
            #pragma unroll
            for (int g = 0; g < 4; g++){
                int r = g*16 + (lane & 7) + ((lane >> 4) << 3);
                int cl = 2*s + ((lane >> 3) & 1);
                uint32_t tmp[4];
                ldsm4(tmp, sb + FSM_K + SWOFF8(r, cl));
                bhf[2*g][0]=tmp[0]; bhf[2*g][1]=tmp[1]; bhf[2*g+1][0]=tmp[2]; bhf[2*g+1][1]=tmp[3];
                ldsm4(tmp, sb + FSM_K + 8192 + SWOFF8(r, cl));
                blf[2*g][0]=tmp[0]; blf[2*g][1]=tmp[1]; blf[2*g+1][0]=tmp[2]; blf[2*g+1][1]=tmp[3];
            }
            #pragma unroll
            for (int nt = 0; nt < 8; nt++){
                mma16816(sacc[nt], qfh[s], bhf[nt][0], bhf[nt][1]);
                mma16816(sacc[nt], qfh[s], blf[nt][0], blf[nt][1]);
                mma16816(sacc[nt], qfl[s], bhf[nt][0], bhf[nt][1]);
            }
        }

        // ---- bias + mask + tile max ----
        int ibase = i0 + warp*16 + (lane >> 2);
        int jbase = jt*64 + 2*(lane & 3);
        float tmx0 = -3.0e38f, tmx1 = -3.0e38f;
        #pragma unroll
        for (int nt = 0; nt < 8; nt++){
            #pragma unroll
            for (int e = 0; e < 4; e++){
                int i = ibase + ((e >> 1) << 3);
                int j = jbase + nt*8 + (e & 1);
                float s = sacc[nt][e];
                if (cb){
                    int nn = i - j; if (nn < 0) nn = 0;
                    s += bsm[nn];
                    if (j > i + 1) s = -1e30f;
                }
                if (j >= nkv) s = -1e30f;
                sacc[nt][e] = s;
                if (e < 2) tmx0 = fmaxf(tmx0, s); else tmx1 = fmaxf(tmx1, s);
            }
        }
        tmx0 = fmaxf(tmx0, __shfl_xor_sync(0xffffffffu, tmx0, 1));
        tmx0 = fmaxf(tmx0, __shfl_xor_sync(0xffffffffu, tmx0, 2));
        tmx1 = fmaxf(tmx1, __shfl_xor_sync(0xffffffffu, tmx1, 1));
        tmx1 = fmaxf(tmx1, __shfl_xor_sync(0xffffffffu, tmx1, 2));
        float nmx0 = fmaxf(mx0, tmx0), nmx1 = fmaxf(mx1, tmx1);
        float al0 = expf(mx0 - nmx0), al1 = expf(mx1 - nmx1);
        mx0 = nmx0; mx1 = nmx1;
        sum0 *= al0; sum1 *= al1;
        #pragma unroll
        for (int nt = 0; nt < 8; nt++){
            o[nt][0] *= al0; o[nt][1] *= al0;
            o[nt][2] *= al1; o[nt][3] *= al1;
        }

        // ---- P = exp(S-mx), split, feed O += P V ----
        float ts0 = 0.f, ts1 = 0.f;
        #pragma unroll
        for (int kg = 0; kg < 4; kg++){
            uint32_t phf[4], plf[4];
            #pragma unroll
            for (int half = 0; half < 2; half++){
                int nt = 2*kg + half;
                unsigned short hb[4], lb[4];
                #pragma unroll
                for (int e = 0; e < 4; e++){
                    float pe = expf(sacc[nt][e] - ((e < 2) ? mx0 : mx1));
                    if (e < 2) ts0 += pe; else ts1 += pe;
                    split_bf16(pe, hb[e], lb[e]);
                }
                phf[2*half+0] = (uint32_t)hb[0] | ((uint32_t)hb[1] << 16);
                phf[2*half+1] = (uint32_t)hb[2] | ((uint32_t)hb[3] << 16);
                plf[2*half+0] = (uint32_t)lb[0] | ((uint32_t)lb[1] << 16);
                plf[2*half+1] = (uint32_t)lb[2] | ((uint32_t)lb[3] << 16);
            }
            uint32_t vhf[8][2], vlf[8][2];
            #pragma unroll
            for (int g = 0; g < 4; g++){
                int r = g*16 + (lane & 7) + ((lane >> 4) << 3);
                int cl = 2*kg + ((lane >> 3) & 1);
                uint32_t tmp[4];
                ldsm4(tmp, sb + FSM_V + SWOFF8(r, cl));
                vhf[2*g][0]=tmp[0]; vhf[2*g][1]=tmp[1]; vhf[2*g+1][0]=tmp[2]; vhf[2*g+1][1]=tmp[3];
                ldsm4(tmp, sb + FSM_V + 8192 + SWOFF8(r, cl));
                vlf[2*g][0]=tmp[0]; vlf[2*g][1]=tmp[1]; vlf[2*g+1][0]=tmp[2]; vlf[2*g+1][1]=tmp[3];
            }
            #pragma unroll
            for (int nt = 0; nt < 8; nt++){
                mma16816(o[nt], phf, vhf[nt][0], vhf[nt][1]);
                mma16816(o[nt], phf, vlf[nt][0], vlf[nt][1]);
                mma16816(o[nt], plf, vhf[nt][0], vhf[nt][1]);
            }
        }
        ts0 += __shfl_xor_sync(0xffffffffu, ts0, 1);
        ts0 += __shfl_xor_sync(0xffffffffu, ts0, 2);
        ts1 += __shfl_xor_sync(0xffffffffu, ts1, 1);
        ts1 += __shfl_xor_sync(0xffffffffu, ts1, 2);
        sum0 += ts0; sum1 += ts1;
        __syncthreads();   // protect K/V smem before next tile's loads
    }

    // ---- normalize + write ----
    float inv0 = 1.f / sum0, inv1 = 1.f / sum1;
    long r0 = (long)b*NQ + i0 + warp*16 + (lane >> 2);
    #pragma unroll
    for (int nt = 0; nt < 8; nt++){
        int c = nt*8 + 2*(lane & 3);
        float2 v0; v0.x = o[nt][0]*inv0; v0.y = o[nt][1]*inv0;
        float2 v1; v1.x = o[nt][2]*inv1; v1.y = o[nt][3]*inv1;
        *(float2*)(out + r0*DD + h*DH + c)     = v0;
        *(float2*)(out + (r0+8)*DD + h*DH + c) = v1;
    }
}

// ---------------- orchestration --------------------------------------------
extern "C" void kernel_launch(void* const* d_in, const int* in_sizes, int n_in,
                              void* d_out, int out_size){
    const float* x_in    = (const float*)d_in[0];
    const float* ctx     = (const float*)d_in[1];
    const float* rel_emb = (const float*)d_in[2];
    const float* sa_ng   = (const float*)d_in[3];
    const float* sa_wq   = (const float*)d_in[4];
    const float* sa_wkv  = (const float*)d_in[5];
    const float* sa_null = (const float*)d_in[6];
    const float* sa_wo   = (const float*)d_in[7];
    const float* sa_og   = (const float*)d_in[8];
    const float* ca_ng   = (const float*)d_in[9];
    const float* ca_cg   = (const float*)d_in[10];
    const float* ca_wq   = (const float*)d_in[11];
    const float* ca_wkv  = (const float*)d_in[12];
    const float* ca_null = (const float*)d_in[13];
    const float* ca_wo   = (const float*)d_in[14];
    const float* ca_og   = (const float*)d_in[15];
    const float* ff_ng   = (const float*)d_in[16];
    const float* ff_w1   = (const float*)d_in[17];
    const float* ff_w2   = (const float*)d_in[18];
    const float* normg   = (const float*)d_in[19];
    float* out = (float*)d_out;

    cudaFuncSetAttribute(tgemm3,     cudaFuncAttributeMaxDynamicSharedMemorySize, 65536);
    cudaFuncSetAttribute(flash_attn, cudaFuncAttributeMaxDynamicSharedMemorySize, FSM_TOT);

    float *X,*XN,*CTXN,*Q,*KV,*ATT,*HHp,*HG,*BT;
    __nv_bfloat16 *AH,*AL,*BH,*BL,*KH,*KL,*VTH,*VTL;
    cudaGetSymbolAddress((void**)&X,    g_x);
    cudaGetSymbolAddress((void**)&XN,   g_xn);
    cudaGetSymbolAddress((void**)&CTXN, g_ctxn);
    cudaGetSymbolAddress((void**)&Q,    g_q);
    cudaGetSymbolAddress((void**)&KV,   g_kv);
    cudaGetSymbolAddress((void**)&ATT,  g_att);
    cudaGetSymbolAddress((void**)&HHp,  g_hh);
    cudaGetSymbolAddress((void**)&HG,   g_hg);
    cudaGetSymbolAddress((void**)&BT,   g_bias);
    cudaGetSymbolAddress((void**)&AH,   g_AH);
    cudaGetSymbolAddress((void**)&AL,   g_AL);
    cudaGetSymbolAddress((void**)&BH,   g_BH);
    cudaGetSymbolAddress((void**)&BL,   g_BL);
    cudaGetSymbolAddress((void**)&KH,   g_KH);
    cudaGetSymbolAddress((void**)&KL,   g_KL);
    cudaGetSymbolAddress((void**)&VTH,  g_VTH);
    cudaGetSymbolAddress((void**)&VTL,  g_VTL);
    __nv_bfloat16 *AH2 = AH + (size_t)4*1024*1024;
    __nv_bfloat16 *AL2 = AL + (size_t)4*1024*1024;

    copy_kernel<<<512, 256>>>(x_in, X, RR*DD);
    bias_tab_kernel<<<4, 256>>>(rel_emb, BT);

    for (int l = 0; l < LL; l++){
        // ---------------- self-attention ----------------
        ln_kernel<<<RR, 256>>>(X, sa_ng + l*DD, XN, DD);
        convA<<<512, 256>>>(XN, AH, AL, RR*DD/4);
        convBT<<<dim3(DD/32, DD/32), 256>>>(sa_wq + (size_t)l*DD*DD, BH, BL, DD, DD);
        tgemm3<<<dim3(DD/128, RR/128), 256, 65536>>>(AH, AL, BH, BL, Q, RR, DD, DD);
        convBT<<<dim3(128/32, DD/32), 256>>>(sa_wkv + (size_t)l*DD*128, BH, BL, DD, 128);
        tgemm3<<<dim3(1, RR/128), 256, 65536>>>(AH, AL, BH, BL, KV, RR, 128, DD);
        kvprep2<<<BB*PADS, 64>>>(KV, sa_null + l*128, KH, KL, VTH, VTL, NQ, 1, PADS);
        qprep_split<<<RR, 256>>>(Q, AH, AL, NQ, 1);
        flash_attn<<<dim3(NQ/64, BB*HH), 128, FSM_TOT>>>(AH, AL, KH, KL, VTH, VTL, BT, ATT, NQ+1, 1);
        convA<<<512, 256>>>(ATT, AH, AL, RR*DD/4);
        convBT<<<dim3(DD/32, DD/32), 256>>>(sa_wo + (size_t)l*DD*DD, BH, BL, DD, DD);
        tgemm3<<<dim3(DD/128, RR/128), 256, 65536>>>(AH, AL, BH, BL, Q, RR, DD, DD);
        ln_res_kernel<<<RR, 256>>>(Q, sa_og + l*DD, X, DD);

        // ---------------- cross-attention ----------------
        ln_kernel<<<RR, 256>>>(X, ca_ng + l*DD, XN, DD);
        ln_kernel<<<CR, 256>>>(ctx, ca_cg + l*PP, CTXN, PP);
        convA<<<512, 256>>>(XN, AH, AL, RR*DD/4);
        convA<<<512, 256>>>(CTXN, AH2, AL2, CR*PP/4);
        convBT<<<dim3(DD/32, DD/32), 256>>>(ca_wq + (size_t)l*DD*DD, BH, BL, DD, DD);
        tgemm3<<<dim3(DD/128, RR/128), 256, 65536>>>(AH, AL, BH, BL, Q, RR, DD, DD);
        convBT<<<dim3(128/32, PP/32), 256>>>(ca_wkv + (size_t)l*PP*128, BH, BL, PP, 128);
        tgemm3<<<dim3(1, CR/128), 256, 65536>>>(AH2, AL2, BH, BL, KV, CR, 128, PP);
        kvprep2<<<BB*640, 64>>>(KV, ca_null + l*128, KH, KL, VTH, VTL, MM, 0, 640);
        qprep_split<<<RR, 256>>>(Q, AH, AL, NQ, 0);
        flash_attn<<<dim3(NQ/64, BB*HH), 128, FSM_TOT>>>(AH, AL, KH, KL, VTH, VTL, BT, ATT, MM+1, 0);
        convA<<<512, 256>>>(ATT, AH, AL, RR*DD/4);
        convBT<<<dim3(DD/32, DD/32), 256>>>(ca_wo + (size_t)l*DD*DD, BH, BL, DD, DD);
        tgemm3<<<dim3(DD/128, RR/128), 256, 65536>>>(AH, AL, BH, BL, Q, RR, DD, DD);
        ln_res_kernel<<<RR, 256>>>(Q, ca_og + l*DD, X, DD);

        // ---------------- feed-forward (SwiGLU) ----------------
        ln_kernel<<<RR, 256>>>(X, ff_ng + l*DD, XN, DD);
        convA<<<512, 256>>>(XN, AH, AL, RR*DD/4);
        convBT<<<dim3((2*FFI)/32, DD/32), 256>>>(ff_w1 + (size_t)l*DD*2*FFI, BH, BL, DD, 2*FFI);
        tgemm3<<<dim3((2*FFI)/128, RR/128), 256, 65536>>>(AH, AL, BH, BL, HG, RR, 2*FFI, DD);
        glu_kernel<<<2048, 256>>>(HG, HHp);
        convA<<<1024, 256>>>(HHp, AH, AL, RR*FFI/4);
        convBT<<<dim3(DD/32, FFI/32), 256>>>(ff_w2 + (size_t)l*FFI*DD, BH, BL, FFI, DD);
        tgemm3<<<dim3(DD/128, RR/128), 256, 65536>>>(AH, AL, BH, BL, Q, RR, DD, FFI);
        add_kernel<<<1024, 256>>>(X, Q, RR*DD);
    }

    final_ln_kernel<<<RR, 256>>>(X, normg, out, DD);
}

// round 9
// speedup vs baseline: 3.3857x; 1.5674x over previous
#include <cuda_runtime.h>
#include <cuda_bf16.h>
#include <math.h>
#include <stdint.h>

// Problem constants
#define BB   4
#define NQ   1024
#define MM   512
#define DD   512
#define PP   256
#define HH   8
#define DH   64
#define LL   6
#define FFI  2048
#define RR   (BB*NQ)        // 4096
#define CR   (BB*MM)        // 2048
#define PADS 1152           // padded kv rows
#define PW   1152           // V^T row stride

// ---------------- scratch (static device globals) --------------------------
__device__ float g_x   [RR*DD];
__device__ float g_ctxn[CR*PP];
__device__ float g_q   [RR*DD];
__device__ float g_kv  [RR*128];
__device__ float g_hg  [(size_t)RR*2*FFI];
__device__ float g_bias[HH*1024];
__device__ __nv_bfloat16 g_AH[(size_t)RR*FFI];   // 8M elems, partitioned
__device__ __nv_bfloat16 g_AL[(size_t)RR*FFI];
__device__ __nv_bfloat16 g_BH[(size_t)2*1024*1024];
__device__ __nv_bfloat16 g_BL[(size_t)2*1024*1024];
__device__ __nv_bfloat16 g_KH[(size_t)BB*PADS*DH];
__device__ __nv_bfloat16 g_KL[(size_t)BB*PADS*DH];
__device__ __nv_bfloat16 g_VTH[(size_t)BB*DH*PW];
__device__ __nv_bfloat16 g_VTL[(size_t)BB*DH*PW];

// ---------------- reductions ------------------------------------------------
__device__ __forceinline__ float warpSum(float v){
    #pragma unroll
    for (int o=16;o;o>>=1) v += __shfl_xor_sync(0xffffffffu, v, o);
    return v;
}
__device__ __forceinline__ float warpMax(float v){
    #pragma unroll
    for (int o=16;o;o>>=1) v = fmaxf(v, __shfl_xor_sync(0xffffffffu, v, o));
    return v;
}
__device__ float blockSum(float v){
    __shared__ float sh[8];
    int lane = threadIdx.x & 31, w = threadIdx.x >> 5;
    v = warpSum(v);
    if (lane == 0) sh[w] = v;
    __syncthreads();
    v = (threadIdx.x < 8) ? sh[threadIdx.x] : 0.f;
    v = warpSum(v);
    if (threadIdx.x == 0) sh[0] = v;
    __syncthreads();
    float r = sh[0];
    __syncthreads();
    return r;
}
__device__ float blockMax(float v){
    __shared__ float sh[8];
    int lane = threadIdx.x & 31, w = threadIdx.x >> 5;
    v = warpMax(v);
    if (lane == 0) sh[w] = v;
    __syncthreads();
    v = (threadIdx.x < 8) ? sh[threadIdx.x] : -3.4e38f;
    v = warpMax(v);
    if (threadIdx.x == 0) sh[0] = v;
    __syncthreads();
    float r = sh[0];
    __syncthreads();
    return r;
}

// ---------------- bf16 split helpers ---------------------------------------
__device__ __forceinline__ void split_bf16(float x, unsigned short& h, unsigned short& l){
    __nv_bfloat16 hb = __float2bfloat16_rn(x);
    __nv_bfloat16 lb = __float2bfloat16_rn(x - __bfloat162float(hb));
    h = __bfloat16_as_ushort(hb);
    l = __bfloat16_as_ushort(lb);
}

// ---------------- elementwise ----------------------------------------------
__global__ void copy_kernel(const float* __restrict__ in, float* __restrict__ out, int n){
    for (int i = blockIdx.x*blockDim.x + threadIdx.x; i < n; i += gridDim.x*blockDim.x)
        out[i] = in[i];
}
__global__ void add_kernel(float* __restrict__ x, const float* __restrict__ y, int n){
    for (int i = blockIdx.x*blockDim.x + threadIdx.x; i < n; i += gridDim.x*blockDim.x)
        x[i] += y[i];
}
// SwiGLU + split: hg [RR,2F] -> hi/lo bf16 [RR,F]
__global__ void glu_split(const float* __restrict__ hg,
                          __nv_bfloat16* __restrict__ hi, __nv_bfloat16* __restrict__ lo){
    long total = (long)RR * FFI;
    for (long i = blockIdx.x*(long)blockDim.x + threadIdx.x; i < total; i += gridDim.x*(long)blockDim.x){
        long r = i / FFI; int c = (int)(i - r*FFI);
        float h = hg[r*(2*FFI) + c];
        float g = hg[r*(2*FFI) + FFI + c];
        float v = h * (g / (1.f + expf(-g)));
        unsigned short hs, ls;
        split_bf16(v, hs, ls);
        hi[i] = __ushort_as_bfloat16(hs);
        lo[i] = __ushort_as_bfloat16(ls);
    }
}
// rel-pos bias table
__global__ void bias_tab_kernel(const float* __restrict__ rel_emb, float* __restrict__ tab){
    int n = blockIdx.x*256 + threadIdx.x;
    if (n >= 1024) return;
    int bucket;
    if (n < 16) bucket = n;
    else {
        int large = 16 + (int)(logf((float)n * 0.0625f) * (16.0f / 2.0794415416798357f));
        bucket = large < 31 ? large : 31;
    }
    #pragma unroll
    for (int h = 0; h < HH; h++)
        tab[h*1024 + n] = rel_emb[bucket*HH + h];
}
// B: fp32 [K][N] -> hi/lo bf16 transposed [N][K]
__global__ __launch_bounds__(256) void convBT(const float* __restrict__ Bm,
                                              __nv_bfloat16* __restrict__ hi,
                                              __nv_bfloat16* __restrict__ lo,
                                              int K, int N){
    __shared__ float tile[32][33];
    int tx = threadIdx.x & 31, ty = threadIdx.x >> 5;
    int n0 = blockIdx.x*32, k0 = blockIdx.y*32;
    #pragma unroll
    for (int i = 0; i < 4; i++)
        tile[ty + 8*i][tx] = Bm[(long)(k0 + ty + 8*i)*N + n0 + tx];
    __syncthreads();
    #pragma unroll
    for (int i = 0; i < 4; i++){
        int n = ty + 8*i;
        float v = tile[tx][n];
        unsigned short h, l;
        split_bf16(v, h, l);
        long off = (long)(n0 + n)*K + k0 + tx;
        hi[off] = __ushort_as_bfloat16(h);
        lo[off] = __ushort_as_bfloat16(l);
    }
}

// ---------------- layernorm family -----------------------------------------
// LN -> hi/lo bf16 split (replaces ln + convA)
__global__ __launch_bounds__(256) void ln_split(const float* __restrict__ in,
                                                const float* __restrict__ g,
                                                __nv_bfloat16* __restrict__ hi,
                                                __nv_bfloat16* __restrict__ lo, int cols){
    long ro = (long)blockIdx.x * cols;
    int t = threadIdx.x;
    float v0 = (t       < cols) ? in[ro + t]       : 0.f;
    float v1 = (t + 256 < cols) ? in[ro + t + 256] : 0.f;
    float mu = blockSum(v0 + v1) / (float)cols;
    float d0 = (t       < cols) ? v0 - mu : 0.f;
    float d1 = (t + 256 < cols) ? v1 - mu : 0.f;
    float var = blockSum(d0*d0 + d1*d1) / (float)cols;
    float inv = 1.f / sqrtf(var + 1e-5f);
    unsigned short h, l;
    if (t < cols){
        split_bf16(d0 * inv * g[t], h, l);
        hi[ro + t] = __ushort_as_bfloat16(h);
        lo[ro + t] = __ushort_as_bfloat16(l);
    }
    if (t + 256 < cols){
        split_bf16(d1 * inv * g[t + 256], h, l);
        hi[ro + t + 256] = __ushort_as_bfloat16(h);
        lo[ro + t + 256] = __ushort_as_bfloat16(l);
    }
}
__global__ __launch_bounds__(256) void ln_res_kernel(const float* __restrict__ in,
                                                     const float* __restrict__ g,
                                                     float* __restrict__ x, int cols){
    long ro = (long)blockIdx.x * cols;
    int t = threadIdx.x;
    float v0 = (t       < cols) ? in[ro + t]       : 0.f;
    float v1 = (t + 256 < cols) ? in[ro + t + 256] : 0.f;
    float mu = blockSum(v0 + v1) / (float)cols;
    float d0 = (t       < cols) ? v0 - mu : 0.f;
    float d1 = (t + 256 < cols) ? v1 - mu : 0.f;
    float var = blockSum(d0*d0 + d1*d1) / (float)cols;
    float inv = 1.f / sqrtf(var + 1e-5f);
    if (t       < cols) x[ro + t]       += d0 * inv * g[t];
    if (t + 256 < cols) x[ro + t + 256] += d1 * inv * g[t + 256];
}
__global__ __launch_bounds__(256) void final_ln_kernel(const float* __restrict__ in,
                                                       const float* __restrict__ g,
                                                       float* __restrict__ out, int cols){
    long ro = (long)blockIdx.x * cols;
    int t = threadIdx.x;
    float v0 = (t       < cols) ? in[ro + t]       : 0.f;
    float v1 = (t + 256 < cols) ? in[ro + t + 256] : 0.f;
    float m0 = (t       < cols) ? v0 : -3.4e38f;
    float m1 = (t + 256 < cols) ? v1 : -3.4e38f;
    float mx = blockMax(fmaxf(m0, m1));
    v0 /= mx; v1 /= mx;
    float s0 = (t       < cols) ? v0 : 0.f;
    float s1 = (t + 256 < cols) ? v1 : 0.f;
    float mu = blockSum(s0 + s1) / (float)cols;
    float d0 = (t       < cols) ? v0 - mu : 0.f;
    float d1 = (t + 256 < cols) ? v1 - mu : 0.f;
    float var = blockSum(d0*d0 + d1*d1) / (float)cols;
    float inv = 1.f / sqrtf(var + 1e-5f);
    if (t       < cols) out[ro + t]       = d0 * inv * g[t];
    if (t + 256 < cols) out[ro + t + 256] = d1 * inv * g[t + 256];
}

// ---------------- rotary / prep --------------------------------------------
__device__ __forceinline__ float inv_freq(int m){
    return powf(10000.f, -(float)m * (1.f/16.f));
}
__global__ __launch_bounds__(256) void qprep_split(const float* __restrict__ q,
                                                   __nv_bfloat16* __restrict__ QH,
                                                   __nv_bfloat16* __restrict__ QL,
                                                   int n, int use_rot){
    int row = blockIdx.x;
    int r = threadIdx.x;
    int h = r >> 5, t = r & 31;
    const float* p = q + (long)row * DD + h * DH;
    long ob = (long)row * DD + h * DH;
    const float sc = 0.125f;
    float va, vb; int ia, ib;
    if (t < 16){
        float a = p[t] * sc, b = p[t+16] * sc;
        if (use_rot){
            float f = (float)(row % n) * inv_freq(t);
            float cf = cosf(f), sf = sinf(f);
            va = a*cf - b*sf; vb = a*sf + b*cf;
        } else { va = a; vb = b; }
        ia = t; ib = t + 16;
    } else {
        va = p[t+16] * sc; vb = p[t+32] * sc;
        ia = t + 16; ib = t + 32;
    }
    unsigned short hh, ll;
    split_bf16(va, hh, ll);
    QH[ob+ia] = __ushort_as_bfloat16(hh); QL[ob+ia] = __ushort_as_bfloat16(ll);
    split_bf16(vb, hh, ll);
    QH[ob+ib] = __ushort_as_bfloat16(hh); QL[ob+ib] = __ushort_as_bfloat16(ll);
}
__global__ __launch_bounds__(64) void kvprep2(const float* __restrict__ kv,
                                              const float* __restrict__ null_kv,
                                              __nv_bfloat16* __restrict__ KH, __nv_bfloat16* __restrict__ KL,
                                              __nv_bfloat16* __restrict__ VTH, __nv_bfloat16* __restrict__ VTL,
                                              int nk, int use_rot, int padK){
    int rblk = blockIdx.x;
    int d = threadIdx.x;
    int nkv = nk + 1;
    int b = rblk / padK, j = rblk % padK;
    long koff = ((long)b * PADS + j) * DH + d;
    long voff = ((long)b * DH + d) * PW + j;
    if (j >= nkv){
        KH[koff] = __ushort_as_bfloat16(0); KL[koff] = __ushort_as_bfloat16(0);
        VTH[voff] = __ushort_as_bfloat16(0); VTL[voff] = __ushort_as_bfloat16(0);
        return;
    }
    float kval, vval;
    if (j == 0){
        kval = null_kv[d];
        vval = null_kv[DH + d];
    } else {
        int i = j - 1;
        const float* src = kv + ((long)b * nk + i) * 128;
        kval = src[d];
        vval = src[DH + d];
        if (use_rot && d < 32){
            int m = d & 15;
            float f = (float)i * inv_freq(m);
            float cf = cosf(f), sf = sinf(f);
            if (d < 16) kval = kval*cf - src[d+16]*sf;
            else        kval = kval*cf + src[d-16]*sf;
        }
    }
    unsigned short h, l;
    split_bf16(kval, h, l);
    KH[koff] = __ushort_as_bfloat16(h); KL[koff] = __ushort_as_bfloat16(l);
    split_bf16(vval, h, l);
    VTH[voff] = __ushort_as_bfloat16(h); VTL[voff] = __ushort_as_bfloat16(l);
}

// ============================================================================
//  mma helpers
// ============================================================================
__device__ __forceinline__ uint32_t smem_u32(const void* p){
    uint32_t a;
    asm("{ .reg .u64 t; cvta.to.shared.u64 t, %1; cvt.u32.u64 %0, t; }" : "=r"(a) : "l"(p));
    return a;
}
__device__ __forceinline__ void cpa(uint32_t sm, const void* g){
    asm volatile("cp.async.ca.shared.global [%0], [%1], 16;" :: "r"(sm), "l"(g));
}
#define CP_COMMIT() asm volatile("cp.async.commit_group;" ::: "memory")
#define CP_WAIT1()  asm volatile("cp.async.wait_group 1;" ::: "memory")
#define CP_WAIT0()  asm volatile("cp.async.wait_group 0;" ::: "memory")
__device__ __forceinline__ void ldsm4(uint32_t* r, uint32_t addr){
    asm volatile("ldmatrix.sync.aligned.m8n8.x4.shared.b16 {%0,%1,%2,%3}, [%4];"
        : "=r"(r[0]),"=r"(r[1]),"=r"(r[2]),"=r"(r[3]) : "r"(addr));
}
__device__ __forceinline__ void mma16816(float* d, const uint32_t* a, uint32_t b0, uint32_t b1){
    asm volatile("mma.sync.aligned.m16n8k16.row.col.f32.bf16.bf16.f32 "
        "{%0,%1,%2,%3}, {%4,%5,%6,%7}, {%8,%9}, {%0,%1,%2,%3};"
        : "+f"(d[0]),"+f"(d[1]),"+f"(d[2]),"+f"(d[3])
        : "r"(a[0]),"r"(a[1]),"r"(a[2]),"r"(a[3]), "r"(b0),"r"(b1));
}
#define SWOFF(r,c)  ((((r)*4 + ((c) ^ (((r)>>1)&3)))) << 4)
#define SWOFF8(r,c) ((((r)*8 + ((c) ^ ((r)&7)))) << 4)

#define COMPUTE_128x128(ss)                                                        \
    _Pragma("unroll")                                                              \
    for (int s = 0; s < 2; s++){                                                   \
        uint32_t ah[4][4], al[4][4], bhf[4][2], blf[4][2];                         \
        _Pragma("unroll")                                                          \
        for (int mt = 0; mt < 4; mt++){                                            \
            int r = wm + mt*16 + (lane & 15);                                      \
            int cl = 2*s + (lane >> 4);                                            \
            uint32_t addr = (ss) + SWOFF(r, cl);                                   \
            ldsm4(ah[mt], addr);                                                   \
            ldsm4(al[mt], addr + 8192);                                            \
        }                                                                          \
        _Pragma("unroll")                                                          \
        for (int g = 0; g < 2; g++){                                               \
            int r = wn + g*16 + (lane & 7) + ((lane >> 4) << 3);                   \
            int cl = 2*s + ((lane >> 3) & 1);                                      \
            uint32_t addr = (ss) + 16384 + SWOFF(r, cl);                           \
            uint32_t tmp[4];                                                       \
            ldsm4(tmp, addr);                                                      \
            bhf[2*g][0]=tmp[0]; bhf[2*g][1]=tmp[1]; bhf[2*g+1][0]=tmp[2]; bhf[2*g+1][1]=tmp[3]; \
            ldsm4(tmp, addr + 8192);                                               \
            blf[2*g][0]=tmp[0]; blf[2*g][1]=tmp[1]; blf[2*g+1][0]=tmp[2]; blf[2*g+1][1]=tmp[3]; \
        }                                                                          \
        _Pragma("unroll")                                                          \
        for (int mt = 0; mt < 4; mt++)                                             \
            _Pragma("unroll")                                                      \
            for (int nt = 0; nt < 4; nt++){                                        \
                mma16816(acc[mt][nt], ah[mt], bhf[nt][0], bhf[nt][1]);             \
                mma16816(acc[mt][nt], ah[mt], blf[nt][0], blf[nt][1]);             \
                mma16816(acc[mt][nt], al[mt], bhf[nt][0], bhf[nt][1]);             \
            }                                                                      \
    }

// ---------------- dense GEMM: C = A[MxK] @ B'[NxK]^T -----------------------
__global__ __launch_bounds__(256, 2) void tgemm3(const __nv_bfloat16* __restrict__ Ah,
                                                 const __nv_bfloat16* __restrict__ Al,
                                                 const __nv_bfloat16* __restrict__ Bh,
                                                 const __nv_bfloat16* __restrict__ Bl,
                                                 float* __restrict__ C,
                                                 int M, int N, int K){
    extern __shared__ __align__(16) char sm[];   // 2 stages * 32768
    uint32_t sb = smem_u32(sm);
    int t = threadIdx.x, lane = t & 31, warp = t >> 5;
    int wm = (warp >> 2) * 64, wn = (warp & 3) * 32;
    long rowBase = (long)blockIdx.y * 128;
    long colBase = (long)blockIdx.x * 128;
    const __nv_bfloat16* srcs[4] = { Ah + rowBase*K, Al + rowBase*K,
                                     Bh + colBase*K, Bl + colBase*K };
    int lr = t >> 2, lc = t & 3;

    float acc[4][4][4];
    #pragma unroll
    for (int i=0;i<4;i++)
        #pragma unroll
        for (int j=0;j<4;j++)
            #pragma unroll
            for (int e=0;e<4;e++) acc[i][j][e] = 0.f;

    #define DLOAD(st, k0) do {                                                  \
        _Pragma("unroll")                                                       \
        for (int tt = 0; tt < 4; tt++){                                         \
            const __nv_bfloat16* s = srcs[tt] + (k0);                           \
            uint32_t so = sb + (st)*32768 + tt*8192;                            \
            cpa(so + SWOFF(lr, lc),      s + (long)lr*K + lc*8);                \
            cpa(so + SWOFF(lr+64, lc),   s + (long)(lr+64)*K + lc*8);           \
        }                                                                       \
        CP_COMMIT(); } while(0)

    int nch = K >> 5;
    DLOAD(0, 0);
    for (int c = 0; c < nch; c++){
        int st = c & 1;
        if (c + 1 < nch){ DLOAD((c+1)&1, (c+1)*32); CP_WAIT1(); }
        else CP_WAIT0();
        __syncthreads();
        uint32_t ss = sb + st*32768;
        COMPUTE_128x128(ss);
        __syncthreads();
    }
    #undef DLOAD

    #pragma unroll
    for (int mt = 0; mt < 4; mt++){
        long r = rowBase + wm + mt*16 + (lane >> 2);
        #pragma unroll
        for (int nt = 0; nt < 4; nt++){
            long cc = colBase + wn + nt*8 + 2*(lane & 3);
            float2 v0; v0.x = acc[mt][nt][0]; v0.y = acc[mt][nt][1];
            float2 v1; v1.x = acc[mt][nt][2]; v1.y = acc[mt][nt][3];
            *(float2*)(C + r*N + cc)     = v0;
            *(float2*)(C + (r+8)*N + cc) = v1;
        }
    }
}

// ============================================================================
//  Fused flash attention (writes hi/lo bf16 split of O directly)
// ============================================================================
#define FSM_Q  0
#define FSM_K  16384
#define FSM_V  32768
#define FSM_B  49152
#define FSM_TOT (49152 + 4096)

__global__ __launch_bounds__(128) void flash_attn(const __nv_bfloat16* __restrict__ Qh,
                                                  const __nv_bfloat16* __restrict__ Ql,
                                                  const __nv_bfloat16* __restrict__ KHp,
                                                  const __nv_bfloat16* __restrict__ KLp,
                                                  const __nv_bfloat16* __restrict__ VTHp,
                                                  const __nv_bfloat16* __restrict__ VTLp,
                                                  const float* __restrict__ bias_tab,
                                                  __nv_bfloat16* __restrict__ OH,
                                                  __nv_bfloat16* __restrict__ OL,
                                                  int nkv, int cb){
    extern __shared__ __align__(16) char sm[];
    uint32_t sb = smem_u32(sm);
    int t = threadIdx.x, lane = t & 31, warp = t >> 5;
    int bh = blockIdx.y, b = bh >> 3, h = bh & 7;
    int i0 = blockIdx.x * 64;

    {
        const __nv_bfloat16* qh = Qh + ((long)(b*NQ + i0))*DD + h*DH;
        const __nv_bfloat16* ql = Ql + ((long)(b*NQ + i0))*DD + h*DH;
        for (int i = t; i < 512; i += 128){
            int r = i >> 3, c = i & 7;
            cpa(sb + FSM_Q        + SWOFF8(r,c), qh + (long)r*DD + c*8);
            cpa(sb + FSM_Q + 8192 + SWOFF8(r,c), ql + (long)r*DD + c*8);
        }
        CP_COMMIT();
    }
    if (cb){
        float* bsm = (float*)(sm + FSM_B);
        for (int i = t; i < 1024; i += 128) bsm[i] = bias_tab[h*1024 + i];
    }
    CP_WAIT0();
    __syncthreads();

    uint32_t qfh[4][4], qfl[4][4];
    #pragma unroll
    for (int s = 0; s < 4; s++){
        int r = warp*16 + (lane & 15);
        int cl = 2*s + (lane >> 4);
        ldsm4(qfh[s], sb + FSM_Q + SWOFF8(r, cl));
        ldsm4(qfl[s], sb + FSM_Q + 8192 + SWOFF8(r, cl));
    }

    float o[8][4];
    #pragma unroll
    for (int i=0;i<8;i++)
        #pragma unroll
        for (int e=0;e<4;e++) o[i][e] = 0.f;
    float mx0 = -3.0e38f, mx1 = -3.0e38f, sum0 = 0.f, sum1 = 0.f;

    int jt_max = (nkv - 1) >> 6;
    if (cb){ int jm = (i0 + 64) >> 6; if (jm < jt_max) jt_max = jm; }
    const __nv_bfloat16* kh = KHp + (long)b*PADS*DH;
    const __nv_bfloat16* kl = KLp + (long)b*PADS*DH;
    const __nv_bfloat16* vh = VTHp + (long)b*DH*PW;
    const __nv_bfloat16* vl = VTLp + (long)b*DH*PW;
    const float* bsm = (const float*)(sm + FSM_B);

    for (int jt = 0; jt <= jt_max; jt++){
        for (int i = t; i < 512; i += 128){
            int r = i >> 3, c = i & 7;
            cpa(sb + FSM_K        + SWOFF8(r,c), kh + ((long)(jt*64 + r))*DH + c*8);
            cpa(sb + FSM_K + 8192 + SWOFF8(r,c), kl + ((long)(jt*64 + r))*DH + c*8);
            cpa(sb + FSM_V        + SWOFF8(r,c), vh + (long)r*PW + jt*64 + c*8);
            cpa(sb + FSM_V + 8192 + SWOFF8(r,c), vl + (long)r*PW + jt*64 + c*8);
        }
        CP_COMMIT(); CP_WAIT0();
        __syncthreads();

        float sacc[8][4];
        #pragma unroll
        for (int i=0;i<8;i++)
            #pragma unroll
            for (int e=0;e<4;e++) sacc[i][e] = 0.f;
        #pragma unroll
        for (int s = 0; s < 4; s++){
            uint32_t bhf[8][2], blf[8][2];
            #pragma unroll
            for (int g = 0; g < 4; g++){
                int r = g*16 + (lane & 7) + ((lane >> 4) << 3);
                int cl = 2*s + ((lane >> 3) & 1);
                uint32_t tmp[4];
                ldsm4(tmp, sb + FSM_K + SWOFF8(r, cl));
                bhf[2*g][0]=tmp[0]; bhf[2*g][1]=tmp[1]; bhf[2*g+1][0]=tmp[2]; bhf[2*g+1][1]=tmp[3];
                ldsm4(tmp, sb + FSM_K + 8192 + SWOFF8(r, cl));
                blf[2*g][0]=tmp[0]; blf[2*g][1]=tmp[1]; blf[2*g+1][0]=tmp[2]; blf[2*g+1][1]=tmp[3];
            }
            #pragma unroll
            for (int nt = 0; nt < 8; nt++){
                mma16816(sacc[nt], qfh[s], bhf[nt][0], bhf[nt][1]);
                mma16816(sacc[nt], qfh[s], blf[nt][0], blf[nt][1]);
                mma16816(sacc[nt], qfl[s], bhf[nt][0], bhf[nt][1]);
            }
        }

        int ibase = i0 + warp*16 + (lane >> 2);
        int jbase = jt*64 + 2*(lane & 3);
        float tmx0 = -3.0e38f, tmx1 = -3.0e38f;
        #pragma unroll
        for (int nt = 0; nt < 8; nt++){
            #pragma unroll
            for (int e = 0; e < 4; e++){
                int i = ibase + ((e >> 1) << 3);
                int j = jbase + nt*8 + (e & 1);
                float s = sacc[nt][e];
                if (cb){
                    int nn = i - j; if (nn < 0) nn = 0;
                    s += bsm[nn];
                    if (j > i + 1) s = -1e30f;
                }
                if (j >= nkv) s = -1e30f;
                sacc[nt][e] = s;
                if (e < 2) tmx0 = fmaxf(tmx0, s); else tmx1 = fmaxf(tmx1, s);
            }
        }
        tmx0 = fmaxf(tmx0, __shfl_xor_sync(0xffffffffu, tmx0, 1));
        tmx0 = fmaxf(tmx0, __shfl_xor_sync(0xffffffffu, tmx0, 2));
        tmx1 = fmaxf(tmx1, __shfl_xor_sync(0xffffffffu, tmx1, 1));
        tmx1 = fmaxf(tmx1, __shfl_xor_sync(0xffffffffu, tmx1, 2));
        float nmx0 = fmaxf(mx0, tmx0), nmx1 = fmaxf(mx1, tmx1);
        float al0 = expf(mx0 - nmx0), al1 = expf(mx1 - nmx1);
        mx0 = nmx0; mx1 = nmx1;
        sum0 *= al0; sum1 *= al1;
        #pragma unroll
        for (int nt = 0; nt < 8; nt++){
            o[nt][0] *= al0; o[nt][1] *= al0;
            o[nt][2] *= al1; o[nt][3] *= al1;
        }

        float ts0 = 0.f, ts1 = 0.f;
        #pragma unroll
        for (int kg = 0; kg < 4; kg++){
            uint32_t phf[4], plf[4];
            #pragma unroll
            for (int half = 0; half < 2; half++){
                int nt = 2*kg + half;
                unsigned short hb[4], lb[4];
                #pragma unroll
                for (int e = 0; e < 4; e++){
                    float pe = expf(sacc[nt][e] - ((e < 2) ? mx0 : mx1));
                    if (e < 2) ts0 += pe; else ts1 += pe;
                    split_bf16(pe, hb[e], lb[e]);
                }
                phf[2*half+0] = (uint32_t)hb[0] | ((uint32_t)hb[1] << 16);
                phf[2*half+1] = (uint32_t)hb[2] | ((uint32_t)hb[3] << 16);
                plf[2*half+0] = (uint32_t)lb[0] | ((uint32_t)lb[1] << 16);
                plf[2*half+1] = (uint32_t)lb[2] | ((uint32_t)lb[3] << 16);
            }
            uint32_t vhf[8][2], vlf[8][2];
            #pragma unroll
            for (int g = 0; g < 4; g++){
                int r = g*16 + (lane & 7) + ((lane >> 4) << 3);
                int cl = 2*kg + ((lane >> 3) & 1);
                uint32_t tmp[4];
                ldsm4(tmp, sb + FSM_V + SWOFF8(r, cl));
                vhf[2*g][0]=tmp[0]; vhf[2*g][1]=tmp[1]; vhf[2*g+1][0]=tmp[2]; vhf[2*g+1][1]=tmp[3];
                ldsm4(tmp, sb + FSM_V + 8192 + SWOFF8(r, cl));
                vlf[2*g][0]=tmp[0]; vlf[2*g][1]=tmp[1]; vlf[2*g+1][0]=tmp[2]; vlf[2*g+1][1]=tmp[3];
            }
            #pragma unroll
            for (int nt = 0; nt < 8; nt++){
                mma16816(o[nt], phf, vhf[nt][0], vhf[nt][1]);
                mma16816(o[nt], phf, vlf[nt][0], vlf[nt][1]);
                mma16816(o[nt], plf, vhf[nt][0], vhf[nt][1]);
            }
        }
        ts0 += __shfl_xor_sync(0xffffffffu, ts0, 1);
        ts0 += __shfl_xor_sync(0xffffffffu, ts0, 2);
        ts1 += __shfl_xor_sync(0xffffffffu, ts1, 1);
        ts1 += __shfl_xor_sync(0xffffffffu, ts1, 2);
        sum0 += ts0; sum1 += ts1;
        __syncthreads();
    }

    // ---- normalize + split + write hi/lo bf16 ----
    float inv0 = 1.f / sum0, inv1 = 1.f / sum1;
    long r0 = (long)b*NQ + i0 + warp*16 + (lane >> 2);
    #pragma unroll
    for (int nt = 0; nt < 8; nt++){
        int c = nt*8 + 2*(lane & 3);
        unsigned short h0,h1,l0,l1;
        split_bf16(o[nt][0]*inv0, h0, l0);
        split_bf16(o[nt][1]*inv0, h1, l1);
        *(uint32_t*)(OH + r0*DD + h*DH + c) = (uint32_t)h0 | ((uint32_t)h1 << 16);
        *(uint32_t*)(OL + r0*DD + h*DH + c) = (uint32_t)l0 | ((uint32_t)l1 << 16);
        split_bf16(o[nt][2]*inv1, h0, l0);
        split_bf16(o[nt][3]*inv1, h1, l1);
        *(uint32_t*)(OH + (r0+8)*DD + h*DH + c) = (uint32_t)h0 | ((uint32_t)h1 << 16);
        *(uint32_t*)(OL + (r0+8)*DD + h*DH + c) = (uint32_t)l0 | ((uint32_t)l1 << 16);
    }
}

// ---------------- orchestration --------------------------------------------
extern "C" void kernel_launch(void* const* d_in, const int* in_sizes, int n_in,
                              void* d_out, int out_size){
    const float* x_in    = (const float*)d_in[0];
    const float* ctx     = (const float*)d_in[1];
    const float* rel_emb = (const float*)d_in[2];
    const float* sa_ng   = (const float*)d_in[3];
    const float* sa_wq   = (const float*)d_in[4];
    const float* sa_wkv  = (const float*)d_in[5];
    const float* sa_null = (const float*)d_in[6];
    const float* sa_wo   = (const float*)d_in[7];
    const float* sa_og   = (const float*)d_in[8];
    const float* ca_ng   = (const float*)d_in[9];
    const float* ca_cg   = (const float*)d_in[10];
    const float* ca_wq   = (const float*)d_in[11];
    const float* ca_wkv  = (const float*)d_in[12];
    const float* ca_null = (const float*)d_in[13];
    const float* ca_wo   = (const float*)d_in[14];
    const float* ca_og   = (const float*)d_in[15];
    const float* ff_ng   = (const float*)d_in[16];
    const float* ff_w1   = (const float*)d_in[17];
    const float* ff_w2   = (const float*)d_in[18];
    const float* normg   = (const float*)d_in[19];
    float* out = (float*)d_out;

    cudaFuncSetAttribute(tgemm3,     cudaFuncAttributeMaxDynamicSharedMemorySize, 65536);
    cudaFuncSetAttribute(flash_attn, cudaFuncAttributeMaxDynamicSharedMemorySize, FSM_TOT);

    float *X,*Q,*KV,*HG,*BT;
    __nv_bfloat16 *AH,*AL,*BH,*BL,*KH,*KL,*VTH,*VTL;
    cudaGetSymbolAddress((void**)&X,    g_x);
    cudaGetSymbolAddress((void**)&Q,    g_q);
    cudaGetSymbolAddress((void**)&KV,   g_kv);
    cudaGetSymbolAddress((void**)&HG,   g_hg);
    cudaGetSymbolAddress((void**)&BT,   g_bias);
    cudaGetSymbolAddress((void**)&AH,   g_AH);
    cudaGetSymbolAddress((void**)&AL,   g_AL);
    cudaGetSymbolAddress((void**)&BH,   g_BH);
    cudaGetSymbolAddress((void**)&BL,   g_BL);
    cudaGetSymbolAddress((void**)&KH,   g_KH);
    cudaGetSymbolAddress((void**)&KL,   g_KL);
    cudaGetSymbolAddress((void**)&VTH,  g_VTH);
    cudaGetSymbolAddress((void**)&VTL,  g_VTL);
    // region partition inside g_AH/g_AL (8M elems each):
    __nv_bfloat16 *XQH = AH,                         *XQL = AL;                      // [0, 2M)  XN / Q split
    __nv_bfloat16 *ATH = AH + (size_t)2*1024*1024,   *ATL = AL + (size_t)2*1024*1024; // [2M, 4M) ATT split
    __nv_bfloat16 *CXH = AH + (size_t)4*1024*1024,   *CXL = AL + (size_t)4*1024*1024; // [4M, 5M) ctx split

    copy_kernel<<<512, 256>>>(x_in, X, RR*DD);
    bias_tab_kernel<<<4, 256>>>(rel_emb, BT);

    for (int l = 0; l < LL; l++){
        // ---------------- self-attention ----------------
        ln_split<<<RR, 256>>>(X, sa_ng + l*DD, XQH, XQL, DD);
        convBT<<<dim3(DD/32, DD/32), 256>>>(sa_wq + (size_t)l*DD*DD, BH, BL, DD, DD);
        tgemm3<<<dim3(DD/128, RR/128), 256, 65536>>>(XQH, XQL, BH, BL, Q, RR, DD, DD);
        convBT<<<dim3(128/32, DD/32), 256>>>(sa_wkv + (size_t)l*DD*128, BH, BL, DD, 128);
        tgemm3<<<dim3(1, RR/128), 256, 65536>>>(XQH, XQL, BH, BL, KV, RR, 128, DD);
        kvprep2<<<BB*PADS, 64>>>(KV, sa_null + l*128, KH, KL, VTH, VTL, NQ, 1, PADS);
        qprep_split<<<RR, 256>>>(Q, XQH, XQL, NQ, 1);
        flash_attn<<<dim3(NQ/64, BB*HH), 128, FSM_TOT>>>(XQH, XQL, KH, KL, VTH, VTL, BT, ATH, ATL, NQ+1, 1);
        convBT<<<dim3(DD/32, DD/32), 256>>>(sa_wo + (size_t)l*DD*DD, BH, BL, DD, DD);
        tgemm3<<<dim3(DD/128, RR/128), 256, 65536>>>(ATH, ATL, BH, BL, Q, RR, DD, DD);
        ln_res_kernel<<<RR, 256>>>(Q, sa_og + l*DD, X, DD);

        // ---------------- cross-attention ----------------
        ln_split<<<RR, 256>>>(X, ca_ng + l*DD, XQH, XQL, DD);
        ln_split<<<CR, 256>>>(ctx, ca_cg + l*PP, CXH, CXL, PP);
        convBT<<<dim3(DD/32, DD/32), 256>>>(ca_wq + (size_t)l*DD*DD, BH, BL, DD, DD);
        tgemm3<<<dim3(DD/128, RR/128), 256, 65536>>>(XQH, XQL, BH, BL, Q, RR, DD, DD);
        convBT<<<dim3(128/32, PP/32), 256>>>(ca_wkv + (size_t)l*PP*128, BH, BL, PP, 128);
        tgemm3<<<dim3(1, CR/128), 256, 65536>>>(CXH, CXL, BH, BL, KV, CR, 128, PP);
        kvprep2<<<BB*640, 64>>>(KV, ca_null + l*128, KH, KL, VTH, VTL, MM, 0, 640);
        qprep_split<<<RR, 256>>>(Q, XQH, XQL, NQ, 0);
        flash_attn<<<dim3(NQ/64, BB*HH), 128, FSM_TOT>>>(XQH, XQL, KH, KL, VTH, VTL, BT, ATH, ATL, MM+1, 0);
        convBT<<<dim3(DD/32, DD/32), 256>>>(ca_wo + (size_t)l*DD*DD, BH, BL, DD, DD);
        tgemm3<<<dim3(DD/128, RR/128), 256, 65536>>>(ATH, ATL, BH, BL, Q, RR, DD, DD);
        ln_res_kernel<<<RR, 256>>>(Q, ca_og + l*DD, X, DD);

        // ---------------- feed-forward (SwiGLU) ----------------
        ln_split<<<RR, 256>>>(X, ff_ng + l*DD, XQH, XQL, DD);
        convBT<<<dim3((2*FFI)/32, DD/32), 256>>>(ff_w1 + (size_t)l*DD*2*FFI, BH, BL, DD, 2*FFI);
        tgemm3<<<dim3((2*FFI)/128, RR/128), 256, 65536>>>(XQH, XQL, BH, BL, HG, RR, 2*FFI, DD);
        glu_split<<<2048, 256>>>(HG, AH, AL);
        convBT<<<dim3(DD/32, FFI/32), 256>>>(ff_w2 + (size_t)l*FFI*DD, BH, BL, FFI, DD);
        tgemm3<<<dim3(DD/128, RR/128), 256, 65536>>>(AH, AL, BH, BL, Q, RR, DD, FFI);
        add_kernel<<<1024, 256>>>(X, Q, RR*DD);
    }

    final_ln_kernel<<<RR, 256>>>(X, normg, out, DD);
}

// round 10
// speedup vs baseline: 3.6431x; 1.0760x over previous
#include <cuda_runtime.h>
#include <cuda_bf16.h>
#include <math.h>
#include <stdint.h>

// Problem constants
#define BB   4
#define NQ   1024
#define MM   512
#define DD   512
#define PP   256
#define HH   8
#define DH   64
#define LL   6
#define FFI  2048
#define RR   (BB*NQ)        // 4096
#define CR   (BB*MM)        // 2048
#define PADS 1152           // padded kv rows
#define PW   1152           // V^T row stride
#define QW   640            // fused QKV row width

// ---------------- scratch (static device globals) --------------------------
__device__ float g_x   [RR*DD];
__device__ float g_q   [RR*QW];          // QKV / Q / wo-out buffer
__device__ float g_kv  [CR*128];
__device__ float g_hg  [(size_t)RR*2*FFI];
__device__ float g_bias[HH*1024];
__device__ __nv_bfloat16 g_AH[(size_t)RR*FFI];   // 8M elems, partitioned
__device__ __nv_bfloat16 g_AL[(size_t)RR*FFI];
__device__ __nv_bfloat16 g_BH[(size_t)2*1024*1024];
__device__ __nv_bfloat16 g_BL[(size_t)2*1024*1024];
__device__ __nv_bfloat16 g_KH[(size_t)BB*PADS*DH];
__device__ __nv_bfloat16 g_KL[(size_t)BB*PADS*DH];
__device__ __nv_bfloat16 g_VTH[(size_t)BB*DH*PW];
__device__ __nv_bfloat16 g_VTL[(size_t)BB*DH*PW];

// ---------------- reductions ------------------------------------------------
__device__ __forceinline__ float warpSum(float v){
    #pragma unroll
    for (int o=16;o;o>>=1) v += __shfl_xor_sync(0xffffffffu, v, o);
    return v;
}
__device__ __forceinline__ float warpMax(float v){
    #pragma unroll
    for (int o=16;o;o>>=1) v = fmaxf(v, __shfl_xor_sync(0xffffffffu, v, o));
    return v;
}
__device__ float blockSum(float v){
    __shared__ float sh[8];
    int lane = threadIdx.x & 31, w = threadIdx.x >> 5;
    v = warpSum(v);
    if (lane == 0) sh[w] = v;
    __syncthreads();
    v = (threadIdx.x < 8) ? sh[threadIdx.x] : 0.f;
    v = warpSum(v);
    if (threadIdx.x == 0) sh[0] = v;
    __syncthreads();
    float r = sh[0];
    __syncthreads();
    return r;
}
__device__ float blockMax(float v){
    __shared__ float sh[8];
    int lane = threadIdx.x & 31, w = threadIdx.x >> 5;
    v = warpMax(v);
    if (lane == 0) sh[w] = v;
    __syncthreads();
    v = (threadIdx.x < 8) ? sh[threadIdx.x] : -3.4e38f;
    v = warpMax(v);
    if (threadIdx.x == 0) sh[0] = v;
    __syncthreads();
    float r = sh[0];
    __syncthreads();
    return r;
}

// ---------------- bf16 split helpers ---------------------------------------
__device__ __forceinline__ void split_bf16(float x, unsigned short& h, unsigned short& l){
    __nv_bfloat16 hb = __float2bfloat16_rn(x);
    __nv_bfloat16 lb = __float2bfloat16_rn(x - __bfloat162float(hb));
    h = __bfloat16_as_ushort(hb);
    l = __bfloat16_as_ushort(lb);
}

// ---------------- elementwise ----------------------------------------------
__global__ void copy_kernel(const float* __restrict__ in, float* __restrict__ out, int n){
    for (int i = blockIdx.x*blockDim.x + threadIdx.x; i < n; i += gridDim.x*blockDim.x)
        out[i] = in[i];
}
// SwiGLU + split: hg [RR,2F] -> hi/lo bf16 [RR,F]
__global__ void glu_split(const float* __restrict__ hg,
                          __nv_bfloat16* __restrict__ hi, __nv_bfloat16* __restrict__ lo){
    long total = (long)RR * FFI;
    for (long i = blockIdx.x*(long)blockDim.x + threadIdx.x; i < total; i += gridDim.x*(long)blockDim.x){
        long r = i / FFI; int c = (int)(i - r*FFI);
        float h = hg[r*(2*FFI) + c];
        float g = hg[r*(2*FFI) + FFI + c];
        float v = h * (g / (1.f + expf(-g)));
        unsigned short hs, ls;
        split_bf16(v, hs, ls);
        hi[i] = __ushort_as_bfloat16(hs);
        lo[i] = __ushort_as_bfloat16(ls);
    }
}
// rel-pos bias table
__global__ void bias_tab_kernel(const float* __restrict__ rel_emb, float* __restrict__ tab){
    int n = blockIdx.x*256 + threadIdx.x;
    if (n >= 1024) return;
    int bucket;
    if (n < 16) bucket = n;
    else {
        int large = 16 + (int)(logf((float)n * 0.0625f) * (16.0f / 2.0794415416798357f));
        bucket = large < 31 ? large : 31;
    }
    #pragma unroll
    for (int h = 0; h < HH; h++)
        tab[h*1024 + n] = rel_emb[bucket*HH + h];
}
// B: fp32 [K][N] -> hi/lo bf16 transposed [N][K]
__global__ __launch_bounds__(256) void convBT(const float* __restrict__ Bm,
                                              __nv_bfloat16* __restrict__ hi,
                                              __nv_bfloat16* __restrict__ lo,
                                              int K, int N){
    __shared__ float tile[32][33];
    int tx = threadIdx.x & 31, ty = threadIdx.x >> 5;
    int n0 = blockIdx.x*32, k0 = blockIdx.y*32;
    #pragma unroll
    for (int i = 0; i < 4; i++)
        tile[ty + 8*i][tx] = Bm[(long)(k0 + ty + 8*i)*N + n0 + tx];
    __syncthreads();
    #pragma unroll
    for (int i = 0; i < 4; i++){
        int n = ty + 8*i;
        float v = tile[tx][n];
        unsigned short h, l;
        split_bf16(v, h, l);
        long off = (long)(n0 + n)*K + k0 + tx;
        hi[off] = __ushort_as_bfloat16(h);
        lo[off] = __ushort_as_bfloat16(l);
    }
}

// ---------------- layernorm family -----------------------------------------
__global__ __launch_bounds__(256) void ln_split(const float* __restrict__ in,
                                                const float* __restrict__ g,
                                                __nv_bfloat16* __restrict__ hi,
                                                __nv_bfloat16* __restrict__ lo, int cols){
    long ro = (long)blockIdx.x * cols;
    int t = threadIdx.x;
    float v0 = (t       < cols) ? in[ro + t]       : 0.f;
    float v1 = (t + 256 < cols) ? in[ro + t + 256] : 0.f;
    float mu = blockSum(v0 + v1) / (float)cols;
    float d0 = (t       < cols) ? v0 - mu : 0.f;
    float d1 = (t + 256 < cols) ? v1 - mu : 0.f;
    float var = blockSum(d0*d0 + d1*d1) / (float)cols;
    float inv = 1.f / sqrtf(var + 1e-5f);
    unsigned short h, l;
    if (t < cols){
        split_bf16(d0 * inv * g[t], h, l);
        hi[ro + t] = __ushort_as_bfloat16(h);
        lo[ro + t] = __ushort_as_bfloat16(l);
    }
    if (t + 256 < cols){
        split_bf16(d1 * inv * g[t + 256], h, l);
        hi[ro + t + 256] = __ushort_as_bfloat16(h);
        lo[ro + t + 256] = __ushort_as_bfloat16(l);
    }
}
// fused: x += LN_g1(qin); then hi/lo = split(LN_g2(x))   (cols == 512)
__global__ __launch_bounds__(256) void ln_res_split(const float* __restrict__ qin,
                                                    const float* __restrict__ g1,
                                                    float* __restrict__ x,
                                                    const float* __restrict__ g2,
                                                    __nv_bfloat16* __restrict__ hi,
                                                    __nv_bfloat16* __restrict__ lo){
    long ro = (long)blockIdx.x * DD;
    int t = threadIdx.x;
    float q0 = qin[ro + t], q1 = qin[ro + t + 256];
    float mu = blockSum(q0 + q1) * (1.f/512.f);
    float d0 = q0 - mu, d1 = q1 - mu;
    float var = blockSum(d0*d0 + d1*d1) * (1.f/512.f);
    float inv = 1.f / sqrtf(var + 1e-5f);
    float x0 = x[ro + t]       + d0 * inv * g1[t];
    float x1 = x[ro + t + 256] + d1 * inv * g1[t + 256];
    x[ro + t]       = x0;
    x[ro + t + 256] = x1;
    float mu2 = blockSum(x0 + x1) * (1.f/512.f);
    float e0 = x0 - mu2, e1 = x1 - mu2;
    float var2 = blockSum(e0*e0 + e1*e1) * (1.f/512.f);
    float inv2 = 1.f / sqrtf(var2 + 1e-5f);
    unsigned short h, l;
    split_bf16(e0 * inv2 * g2[t], h, l);
    hi[ro + t] = __ushort_as_bfloat16(h);
    lo[ro + t] = __ushort_as_bfloat16(l);
    split_bf16(e1 * inv2 * g2[t + 256], h, l);
    hi[ro + t + 256] = __ushort_as_bfloat16(h);
    lo[ro + t + 256] = __ushort_as_bfloat16(l);
}
__global__ __launch_bounds__(256) void final_ln_kernel(const float* __restrict__ in,
                                                       const float* __restrict__ g,
                                                       float* __restrict__ out, int cols){
    long ro = (long)blockIdx.x * cols;
    int t = threadIdx.x;
    float v0 = (t       < cols) ? in[ro + t]       : 0.f;
    float v1 = (t + 256 < cols) ? in[ro + t + 256] : 0.f;
    float m0 = (t       < cols) ? v0 : -3.4e38f;
    float m1 = (t + 256 < cols) ? v1 : -3.4e38f;
    float mx = blockMax(fmaxf(m0, m1));
    v0 /= mx; v1 /= mx;
    float s0 = (t       < cols) ? v0 : 0.f;
    float s1 = (t + 256 < cols) ? v1 : 0.f;
    float mu = blockSum(s0 + s1) / (float)cols;
    float d0 = (t       < cols) ? v0 - mu : 0.f;
    float d1 = (t + 256 < cols) ? v1 - mu : 0.f;
    float var = blockSum(d0*d0 + d1*d1) / (float)cols;
    float inv = 1.f / sqrtf(var + 1e-5f);
    if (t       < cols) out[ro + t]       = d0 * inv * g[t];
    if (t + 256 < cols) out[ro + t + 256] = d1 * inv * g[t + 256];
}

// ---------------- rotary / prep --------------------------------------------
__device__ __forceinline__ float inv_freq(int m){
    return powf(10000.f, -(float)m * (1.f/16.f));
}
__global__ __launch_bounds__(256) void qprep_split(const float* __restrict__ q, int qstride,
                                                   __nv_bfloat16* __restrict__ QH,
                                                   __nv_bfloat16* __restrict__ QL,
                                                   int n, int use_rot){
    int row = blockIdx.x;
    int r = threadIdx.x;
    int h = r >> 5, t = r & 31;
    const float* p = q + (long)row * qstride + h * DH;
    long ob = (long)row * DD + h * DH;
    const float sc = 0.125f;
    float va, vb; int ia, ib;
    if (t < 16){
        float a = p[t] * sc, b = p[t+16] * sc;
        if (use_rot){
            float f = (float)(row % n) * inv_freq(t);
            float cf = cosf(f), sf = sinf(f);
            va = a*cf - b*sf; vb = a*sf + b*cf;
        } else { va = a; vb = b; }
        ia = t; ib = t + 16;
    } else {
        va = p[t+16] * sc; vb = p[t+32] * sc;
        ia = t + 16; ib = t + 32;
    }
    unsigned short hh, ll;
    split_bf16(va, hh, ll);
    QH[ob+ia] = __ushort_as_bfloat16(hh); QL[ob+ia] = __ushort_as_bfloat16(ll);
    split_bf16(vb, hh, ll);
    QH[ob+ib] = __ushort_as_bfloat16(hh); QL[ob+ib] = __ushort_as_bfloat16(ll);
}
__global__ __launch_bounds__(64) void kvprep2(const float* __restrict__ kv, int kvstride,
                                              const float* __restrict__ null_kv,
                                              __nv_bfloat16* __restrict__ KH, __nv_bfloat16* __restrict__ KL,
                                              __nv_bfloat16* __restrict__ VTH, __nv_bfloat16* __restrict__ VTL,
                                              int nk, int use_rot, int padK){
    int rblk = blockIdx.x;
    int d = threadIdx.x;
    int nkv = nk + 1;
    int b = rblk / padK, j = rblk % padK;
    long koff = ((long)b * PADS + j) * DH + d;
    long voff = ((long)b * DH + d) * PW + j;
    if (j >= nkv){
        KH[koff] = __ushort_as_bfloat16(0); KL[koff] = __ushort_as_bfloat16(0);
        VTH[voff] = __ushort_as_bfloat16(0); VTL[voff] = __ushort_as_bfloat16(0);
        return;
    }
    float kval, vval;
    if (j == 0){
        kval = null_kv[d];
        vval = null_kv[DH + d];
    } else {
        int i = j - 1;
        const float* src = kv + ((long)b * nk + i) * kvstride;
        kval = src[d];
        vval = src[DH + d];
        if (use_rot && d < 32){
            int m = d & 15;
            float f = (float)i * inv_freq(m);
            float cf = cosf(f), sf = sinf(f);
            if (d < 16) kval = kval*cf - src[d+16]*sf;
            else        kval = kval*cf + src[d-16]*sf;
        }
    }
    unsigned short h, l;
    split_bf16(kval, h, l);
    KH[koff] = __ushort_as_bfloat16(h); KL[koff] = __ushort_as_bfloat16(l);
    split_bf16(vval, h, l);
    VTH[voff] = __ushort_as_bfloat16(h); VTL[voff] = __ushort_as_bfloat16(l);
}

// ============================================================================
//  mma helpers
// ============================================================================
__device__ __forceinline__ uint32_t smem_u32(const void* p){
    uint32_t a;
    asm("{ .reg .u64 t; cvta.to.shared.u64 t, %1; cvt.u32.u64 %0, t; }" : "=r"(a) : "l"(p));
    return a;
}
__device__ __forceinline__ void cpg(uint32_t sm, const void* g){
    asm volatile("cp.async.cg.shared.global [%0], [%1], 16;" :: "r"(sm), "l"(g));
}
#define CP_COMMIT() asm volatile("cp.async.commit_group;" ::: "memory")
#define CP_WAIT1()  asm volatile("cp.async.wait_group 1;" ::: "memory")
#define CP_WAIT0()  asm volatile("cp.async.wait_group 0;" ::: "memory")
__device__ __forceinline__ void ldsm4(uint32_t* r, uint32_t addr){
    asm volatile("ldmatrix.sync.aligned.m8n8.x4.shared.b16 {%0,%1,%2,%3}, [%4];"
        : "=r"(r[0]),"=r"(r[1]),"=r"(r[2]),"=r"(r[3]) : "r"(addr));
}
__device__ __forceinline__ void mma16816(float* d, const uint32_t* a, uint32_t b0, uint32_t b1){
    asm volatile("mma.sync.aligned.m16n8k16.row.col.f32.bf16.bf16.f32 "
        "{%0,%1,%2,%3}, {%4,%5,%6,%7}, {%8,%9}, {%0,%1,%2,%3};"
        : "+f"(d[0]),"+f"(d[1]),"+f"(d[2]),"+f"(d[3])
        : "r"(a[0]),"r"(a[1]),"r"(a[2]),"r"(a[3]), "r"(b0),"r"(b1));
}
#define SWOFF(r,c)  ((((r)*4 + ((c) ^ (((r)>>1)&3)))) << 4)
#define SWOFF8(r,c) ((((r)*8 + ((c) ^ ((r)&7)))) << 4)

#define COMPUTE_128x128(ss)                                                        \
    _Pragma("unroll")                                                              \
    for (int s = 0; s < 2; s++){                                                   \
        uint32_t ah[4][4], al[4][4], bhf[4][2], blf[4][2];                         \
        _Pragma("unroll")                                                          \
        for (int mt = 0; mt < 4; mt++){                                            \
            int r = wm + mt*16 + (lane & 15);                                      \
            int cl = 2*s + (lane >> 4);                                            \
            uint32_t addr = (ss) + SWOFF(r, cl);                                   \
            ldsm4(ah[mt], addr);                                                   \
            ldsm4(al[mt], addr + 8192);                                            \
        }                                                                          \
        _Pragma("unroll")                                                          \
        for (int g = 0; g < 2; g++){                                               \
            int r = wn + g*16 + (lane & 7) + ((lane >> 4) << 3);                   \
            int cl = 2*s + ((lane >> 3) & 1);                                      \
            uint32_t addr = (ss) + 16384 + SWOFF(r, cl);                           \
            uint32_t tmp[4];                                                       \
            ldsm4(tmp, addr);                                                      \
            bhf[2*g][0]=tmp[0]; bhf[2*g][1]=tmp[1]; bhf[2*g+1][0]=tmp[2]; bhf[2*g+1][1]=tmp[3]; \
            ldsm4(tmp, addr + 8192);                                               \
            blf[2*g][0]=tmp[0]; blf[2*g][1]=tmp[1]; blf[2*g+1][0]=tmp[2]; blf[2*g+1][1]=tmp[3]; \
        }                                                                          \
        _Pragma("unroll")                                                          \
        for (int mt = 0; mt < 4; mt++)                                             \
            _Pragma("unroll")                                                      \
            for (int nt = 0; nt < 4; nt++){                                        \
                mma16816(acc[mt][nt], ah[mt], bhf[nt][0], bhf[nt][1]);             \
                mma16816(acc[mt][nt], ah[mt], blf[nt][0], blf[nt][1]);             \
                mma16816(acc[mt][nt], al[mt], bhf[nt][0], bhf[nt][1]);             \
            }                                                                      \
    }

// ---------------- dense GEMM: C = A[MxK] @ B'[NxK]^T (+=C if addC) ----------
__global__ __launch_bounds__(256, 2) void tgemm3(const __nv_bfloat16* __restrict__ Ah,
                                                 const __nv_bfloat16* __restrict__ Al,
                                                 const __nv_bfloat16* __restrict__ Bh,
                                                 const __nv_bfloat16* __restrict__ Bl,
                                                 float* __restrict__ C,
                                                 int M, int N, int K, int addC){
    extern __shared__ __align__(16) char sm[];   // 2 stages * 32768
    uint32_t sb = smem_u32(sm);
    int t = threadIdx.x, lane = t & 31, warp = t >> 5;
    int wm = (warp >> 2) * 64, wn = (warp & 3) * 32;
    long rowBase = (long)blockIdx.y * 128;
    long colBase = (long)blockIdx.x * 128;
    const __nv_bfloat16* srcs[4] = { Ah + rowBase*K, Al + rowBase*K,
                                     Bh + colBase*K, Bl + colBase*K };
    int lr = t >> 2, lc = t & 3;

    float acc[4][4][4];
    #pragma unroll
    for (int i=0;i<4;i++)
        #pragma unroll
        for (int j=0;j<4;j++)
            #pragma unroll
            for (int e=0;e<4;e++) acc[i][j][e] = 0.f;

    #define DLOAD(st, k0) do {                                                  \
        _Pragma("unroll")                                                       \
        for (int tt = 0; tt < 4; tt++){                                         \
            const __nv_bfloat16* s = srcs[tt] + (k0);                           \
            uint32_t so = sb + (st)*32768 + tt*8192;                            \
            cpg(so + SWOFF(lr, lc),      s + (long)lr*K + lc*8);                \
            cpg(so + SWOFF(lr+64, lc),   s + (long)(lr+64)*K + lc*8);           \
        }                                                                       \
        CP_COMMIT(); } while(0)

    int nch = K >> 5;
    DLOAD(0, 0);
    for (int c = 0; c < nch; c++){
        int st = c & 1;
        if (c + 1 < nch){ DLOAD((c+1)&1, (c+1)*32); CP_WAIT1(); }
        else CP_WAIT0();
        __syncthreads();
        uint32_t ss = sb + st*32768;
        COMPUTE_128x128(ss);
        __syncthreads();
    }
    #undef DLOAD

    #pragma unroll
    for (int mt = 0; mt < 4; mt++){
        long r = rowBase + wm + mt*16 + (lane >> 2);
        #pragma unroll
        for (int nt = 0; nt < 4; nt++){
            long cc = colBase + wn + nt*8 + 2*(lane & 3);
            float2 v0; v0.x = acc[mt][nt][0]; v0.y = acc[mt][nt][1];
            float2 v1; v1.x = acc[mt][nt][2]; v1.y = acc[mt][nt][3];
            float2* p0 = (float2*)(C + r*N + cc);
            float2* p1 = (float2*)(C + (r+8)*N + cc);
            if (addC){
                float2 c0 = *p0, c1 = *p1;
                v0.x += c0.x; v0.y += c0.y;
                v1.x += c1.x; v1.y += c1.y;
            }
            *p0 = v0;
            *p1 = v1;
        }
    }
}

// ============================================================================
//  Fused flash attention (writes hi/lo bf16 split of O directly)
// ============================================================================
#define FSM_Q  0
#define FSM_K  16384
#define FSM_V  32768
#define FSM_B  49152
#define FSM_TOT (49152 + 4096)

__global__ __launch_bounds__(128) void flash_attn(const __nv_bfloat16* __restrict__ Qh,
                                                  const __nv_bfloat16* __restrict__ Ql,
                                                  const __nv_bfloat16* __restrict__ KHp,
                                                  const __nv_bfloat16* __restrict__ KLp,
                                                  const __nv_bfloat16* __restrict__ VTHp,
                                                  const __nv_bfloat16* __restrict__ VTLp,
                                                  const float* __restrict__ bias_tab,
                                                  __nv_bfloat16* __restrict__ OH,
                                                  __nv_bfloat16* __restrict__ OL,
                                                  int nkv, int cb){
    extern __shared__ __align__(16) char sm[];
    uint32_t sb = smem_u32(sm);
    int t = threadIdx.x, lane = t & 31, warp = t >> 5;
    int bh = blockIdx.y, b = bh >> 3, h = bh & 7;
    int i0 = blockIdx.x * 64;

    {
        const __nv_bfloat16* qh = Qh + ((long)(b*NQ + i0))*DD + h*DH;
        const __nv_bfloat16* ql = Ql + ((long)(b*NQ + i0))*DD + h*DH;
        for (int i = t; i < 512; i += 128){
            int r = i >> 3, c = i & 7;
            cpg(sb + FSM_Q        + SWOFF8(r,c), qh + (long)r*DD + c*8);
            cpg(sb + FSM_Q + 8192 + SWOFF8(r,c), ql + (long)r*DD + c*8);
        }
        CP_COMMIT();
    }
    if (cb){
        float* bsm = (float*)(sm + FSM_B);
        for (int i = t; i < 1024; i += 128) bsm[i] = bias_tab[h*1024 + i];
    }
    CP_WAIT0();
    __syncthreads();

    uint32_t qfh[4][4], qfl[4][4];
    #pragma unroll
    for (int s = 0; s < 4; s++){
        int r = warp*16 + (lane & 15);
        int cl = 2*s + (lane >> 4);
        ldsm4(qfh[s], sb + FSM_Q + SWOFF8(r, cl));
        ldsm4(qfl[s], sb + FSM_Q + 8192 + SWOFF8(r, cl));
    }

    float o[8][4];
    #pragma unroll
    for (int i=0;i<8;i++)
        #pragma unroll
        for (int e=0;e<4;e++) o[i][e] = 0.f;
    float mx0 = -3.0e38f, mx1 = -3.0e38f, sum0 = 0.f, sum1 = 0.f;

    int jt_max = (nkv - 1) >> 6;
    if (cb){ int jm = (i0 + 64) >> 6; if (jm < jt_max) jt_max = jm; }
    const __nv_bfloat16* kh = KHp + (long)b*PADS*DH;
    const __nv_bfloat16* kl = KLp + (long)b*PADS*DH;
    const __nv_bfloat16* vh = VTHp + (long)b*DH*PW;
    const __nv_bfloat16* vl = VTLp + (long)b*DH*PW;
    const float* bsm = (const float*)(sm + FSM_B);

    for (int jt = 0; jt <= jt_max; jt++){
        // group 1: K tiles; group 2: V tiles (waited later, overlaps S compute)
        for (int i = t; i < 512; i += 128){
            int r = i >> 3, c = i & 7;
            cpg(sb + FSM_K        + SWOFF8(r,c), kh + ((long)(jt*64 + r))*DH + c*8);
            cpg(sb + FSM_K + 8192 + SWOFF8(r,c), kl + ((long)(jt*64 + r))*DH + c*8);
        }
        CP_COMMIT();
        for (int i = t; i < 512; i += 128){
            int r = i >> 3, c = i & 7;
            cpg(sb + FSM_V        + SWOFF8(r,c), vh + (long)r*PW + jt*64 + c*8);
            cpg(sb + FSM_V + 8192 + SWOFF8(r,c), vl + (long)r*PW + jt*64 + c*8);
        }
        CP_COMMIT();
        CP_WAIT1();         // K ready; V still in flight
        __syncthreads();

        float sacc[8][4];
        #pragma unroll
        for (int i=0;i<8;i++)
            #pragma unroll
            for (int e=0;e<4;e++) sacc[i][e] = 0.f;
        #pragma unroll
        for (int s = 0; s < 4; s++){
            uint32_t bhf[8][2], blf[8][2];
            #pragma unroll
            for (int g = 0; g < 4; g++){
                int r = g*16 + (lane & 7) + ((lane >> 4) << 3);
                int cl = 2*s + ((lane >> 3) & 1);
                uint32_t tmp[4];
                ldsm4(tmp, sb + FSM_K + SWOFF8(r, cl));
                bhf[2*g][0]=tmp[0]; bhf[2*g][1]=tmp[1]; bhf[2*g+1][0]=tmp[2]; bhf[2*g+1][1]=tmp[3];
                ldsm4(tmp, sb + FSM_K + 8192 + SWOFF8(r, cl));
                blf[2*g][0]=tmp[0]; blf[2*g][1]=tmp[1]; blf[2*g+1][0]=tmp[2]; blf[2*g+1][1]=tmp[3];
            }
            #pragma unroll
            for (int nt = 0; nt < 8; nt++){
                mma16816(sacc[nt], qfh[s], bhf[nt][0], bhf[nt][1]);
                mma16816(sacc[nt], qfh[s], blf[nt][0], blf[nt][1]);
                mma16816(sacc[nt], qfl[s], bhf[nt][0], bhf[nt][1]);
            }
        }

        int ibase = i0 + warp*16 + (lane >> 2);
        int jbase = jt*64 + 2*(lane & 3);
        float tmx0 = -3.0e38f, tmx1 = -3.0e38f;
        #pragma unroll
        for (int nt = 0; nt < 8; nt++){
            #pragma unroll
            for (int e = 0; e < 4; e++){
                int i = ibase + ((e >> 1) << 3);
                int j = jbase + nt*8 + (e & 1);
                float s = sacc[nt][e];
                if (cb){
                    int nn = i - j; if (nn < 0) nn = 0;
                    s += bsm[nn];
                    if (j > i + 1) s = -1e30f;
                }
                if (j >= nkv) s = -1e30f;
                sacc[nt][e] = s;
                if (e < 2) tmx0 = fmaxf(tmx0, s); else tmx1 = fmaxf(tmx1, s);
            }
        }
        tmx0 = fmaxf(tmx0, __shfl_xor_sync(0xffffffffu, tmx0, 1));
        tmx0 = fmaxf(tmx0, __shfl_xor_sync(0xffffffffu, tmx0, 2));
        tmx1 = fmaxf(tmx1, __shfl_xor_sync(0xffffffffu, tmx1, 1));
        tmx1 = fmaxf(tmx1, __shfl_xor_sync(0xffffffffu, tmx1, 2));
        float nmx0 = fmaxf(mx0, tmx0), nmx1 = fmaxf(mx1, tmx1);
        float al0 = expf(mx0 - nmx0), al1 = expf(mx1 - nmx1);
        mx0 = nmx0; mx1 = nmx1;
        sum0 *= al0; sum1 *= al1;
        #pragma unroll
        for (int nt = 0; nt < 8; nt++){
            o[nt][0] *= al0; o[nt][1] *= al0;
            o[nt][2] *= al1; o[nt][3] *= al1;
        }

        CP_WAIT0();         // V ready
        __syncthreads();

        float ts0 = 0.f, ts1 = 0.f;
        #pragma unroll
        for (int kg = 0; kg < 4; kg++){
            uint32_t phf[4], plf[4];
            #pragma unroll
            for (int half = 0; half < 2; half++){
                int nt = 2*kg + half;
                unsigned short hb[4], lb[4];
                #pragma unroll
                for (int e = 0; e < 4; e++){
                    float pe = expf(sacc[nt][e] - ((e < 2) ? mx0 : mx1));
                    if (e < 2) ts0 += pe; else ts1 += pe;
                    split_bf16(pe, hb[e], lb[e]);
                }
                phf[2*half+0] = (uint32_t)hb[0] | ((uint32_t)hb[1] << 16);
                phf[2*half+1] = (uint32_t)hb[2] | ((uint32_t)hb[3] << 16);
                plf[2*half+0] = (uint32_t)lb[0] | ((uint32_t)lb[1] << 16);
                plf[2*half+1] = (uint32_t)lb[2] | ((uint32_t)lb[3] << 16);
            }
            uint32_t vhf[8][2], vlf[8][2];
            #pragma unroll
            for (int g = 0; g < 4; g++){
                int r = g*16 + (lane & 7) + ((lane >> 4) << 3);
                int cl = 2*kg + ((lane >> 3) & 1);
                uint32_t tmp[4];
                ldsm4(tmp, sb + FSM_V + SWOFF8(r, cl));
                vhf[2*g][0]=tmp[0]; vhf[2*g][1]=tmp[1]; vhf[2*g+1][0]=tmp[2]; vhf[2*g+1][1]=tmp[3];
                ldsm4(tmp, sb + FSM_V + 8192 + SWOFF8(r, cl));
                vlf[2*g][0]=tmp[0]; vlf[2*g][1]=tmp[1]; vlf[2*g+1][0]=tmp[2]; vlf[2*g+1][1]=tmp[3];
            }
            #pragma unroll
            for (int nt = 0; nt < 8; nt++){
                mma16816(o[nt], phf, vhf[nt][0], vhf[nt][1]);
                mma16816(o[nt], phf, vlf[nt][0], vlf[nt][1]);
                mma16816(o[nt], plf, vhf[nt][0], vhf[nt][1]);
            }
        }
        ts0 += __shfl_xor_sync(0xffffffffu, ts0, 1);
        ts0 += __shfl_xor_sync(0xffffffffu, ts0, 2);
        ts1 += __shfl_xor_sync(0xffffffffu, ts1, 1);
        ts1 += __shfl_xor_sync(0xffffffffu, ts1, 2);
        sum0 += ts0; sum1 += ts1;
        __syncthreads();
    }

    float inv0 = 1.f / sum0, inv1 = 1.f / sum1;
    long r0 = (long)b*NQ + i0 + warp*16 + (lane >> 2);
    #pragma unroll
    for (int nt = 0; nt < 8; nt++){
        int c = nt*8 + 2*(lane & 3);
        unsigned short h0,h1,l0,l1;
        split_bf16(o[nt][0]*inv0, h0, l0);
        split_bf16(o[nt][1]*inv0, h1, l1);
        *(uint32_t*)(OH + r0*DD + h*DH + c) = (uint32_t)h0 | ((uint32_t)h1 << 16);
        *(uint32_t*)(OL + r0*DD + h*DH + c) = (uint32_t)l0 | ((uint32_t)l1 << 16);
        split_bf16(o[nt][2]*inv1, h0, l0);
        split_bf16(o[nt][3]*inv1, h1, l1);
        *(uint32_t*)(OH + (r0+8)*DD + h*DH + c) = (uint32_t)h0 | ((uint32_t)h1 << 16);
        *(uint32_t*)(OL + (r0+8)*DD + h*DH + c) = (uint32_t)l0 | ((uint32_t)l1 << 16);
    }
}

// ---------------- orchestration --------------------------------------------
extern "C" void kernel_launch(void* const* d_in, const int* in_sizes, int n_in,
                              void* d_out, int out_size){
    const float* x_in    = (const float*)d_in[0];
    const float* ctx     = (const float*)d_in[1];
    const float* rel_emb = (const float*)d_in[2];
    const float* sa_ng   = (const float*)d_in[3];
    const float* sa_wq   = (const float*)d_in[4];
    const float* sa_wkv  = (const float*)d_in[5];
    const float* sa_null = (const float*)d_in[6];
    const float* sa_wo   = (const float*)d_in[7];
    const float* sa_og   = (const float*)d_in[8];
    const float* ca_ng   = (const float*)d_in[9];
    const float* ca_cg   = (const float*)d_in[10];
    const float* ca_wq   = (const float*)d_in[11];
    const float* ca_wkv  = (const float*)d_in[12];
    const float* ca_null = (const float*)d_in[13];
    const float* ca_wo   = (const float*)d_in[14];
    const float* ca_og   = (const float*)d_in[15];
    const float* ff_ng   = (const float*)d_in[16];
    const float* ff_w1   = (const float*)d_in[17];
    const float* ff_w2   = (const float*)d_in[18];
    const float* normg   = (const float*)d_in[19];
    float* out = (float*)d_out;

    cudaFuncSetAttribute(tgemm3,     cudaFuncAttributeMaxDynamicSharedMemorySize, 65536);
    cudaFuncSetAttribute(flash_attn, cudaFuncAttributeMaxDynamicSharedMemorySize, FSM_TOT);

    float *X,*QKV,*KV,*HG,*BT;
    __nv_bfloat16 *AH,*AL,*BH,*BL,*KH,*KL,*VTH,*VTL;
    cudaGetSymbolAddress((void**)&X,    g_x);
    cudaGetSymbolAddress((void**)&QKV,  g_q);
    cudaGetSymbolAddress((void**)&KV,   g_kv);
    cudaGetSymbolAddress((void**)&HG,   g_hg);
    cudaGetSymbolAddress((void**)&BT,   g_bias);
    cudaGetSymbolAddress((void**)&AH,   g_AH);
    cudaGetSymbolAddress((void**)&AL,   g_AL);
    cudaGetSymbolAddress((void**)&BH,   g_BH);
    cudaGetSymbolAddress((void**)&BL,   g_BL);
    cudaGetSymbolAddress((void**)&KH,   g_KH);
    cudaGetSymbolAddress((void**)&KL,   g_KL);
    cudaGetSymbolAddress((void**)&VTH,  g_VTH);
    cudaGetSymbolAddress((void**)&VTL,  g_VTL);
    // region partition inside g_AH/g_AL (8M elems each):
    __nv_bfloat16 *XQH = AH,                         *XQL = AL;                        // [0,2M) XN/Q split
    __nv_bfloat16 *ATH = AH + (size_t)2*1024*1024,   *ATL = AL + (size_t)2*1024*1024;  // [2M,4M) ATT split
    __nv_bfloat16 *CXH = AH + (size_t)4*1024*1024,   *CXL = AL + (size_t)4*1024*1024;  // [4M,5M) ctx split

    copy_kernel<<<512, 256>>>(x_in, X, RR*DD);
    bias_tab_kernel<<<4, 256>>>(rel_emb, BT);

    for (int l = 0; l < LL; l++){
        // ---------------- self-attention (fused QKV GEMM, N=640) ----------
        ln_split<<<RR, 256>>>(X, sa_ng + l*DD, XQH, XQL, DD);
        convBT<<<dim3(DD/32, DD/32), 256>>>(sa_wq + (size_t)l*DD*DD, BH, BL, DD, DD);
        convBT<<<dim3(128/32, DD/32), 256>>>(sa_wkv + (size_t)l*DD*128,
                                             BH + (size_t)DD*DD, BL + (size_t)DD*DD, DD, 128);
        tgemm3<<<dim3(QW/128, RR/128), 256, 65536>>>(XQH, XQL, BH, BL, QKV, RR, QW, DD, 0);
        kvprep2<<<BB*PADS, 64>>>(QKV + DD, QW, sa_null + l*128, KH, KL, VTH, VTL, NQ, 1, PADS);
        qprep_split<<<RR, 256>>>(QKV, QW, XQH, XQL, NQ, 1);
        flash_attn<<<dim3(NQ/64, BB*HH), 128, FSM_TOT>>>(XQH, XQL, KH, KL, VTH, VTL, BT, ATH, ATL, NQ+1, 1);
        convBT<<<dim3(DD/32, DD/32), 256>>>(sa_wo + (size_t)l*DD*DD, BH, BL, DD, DD);
        tgemm3<<<dim3(DD/128, RR/128), 256, 65536>>>(ATH, ATL, BH, BL, QKV, RR, DD, DD, 0);
        ln_res_split<<<RR, 256>>>(QKV, sa_og + l*DD, X, ca_ng + l*DD, XQH, XQL);

        // ---------------- cross-attention ----------------
        ln_split<<<CR, 256>>>(ctx, ca_cg + l*PP, CXH, CXL, PP);
        convBT<<<dim3(DD/32, DD/32), 256>>>(ca_wq + (size_t)l*DD*DD, BH, BL, DD, DD);
        tgemm3<<<dim3(DD/128, RR/128), 256, 65536>>>(XQH, XQL, BH, BL, QKV, RR, DD, DD, 0);
        convBT<<<dim3(128/32, PP/32), 256>>>(ca_wkv + (size_t)l*PP*128, BH, BL, PP, 128);
        tgemm3<<<dim3(1, CR/128), 256, 65536>>>(CXH, CXL, BH, BL, KV, CR, 128, PP, 0);
        kvprep2<<<BB*640, 64>>>(KV, 128, ca_null + l*128, KH, KL, VTH, VTL, MM, 0, 640);
        qprep_split<<<RR, 256>>>(QKV, DD, XQH, XQL, NQ, 0);
        flash_attn<<<dim3(NQ/64, BB*HH), 128, FSM_TOT>>>(XQH, XQL, KH, KL, VTH, VTL, BT, ATH, ATL, MM+1, 0);
        convBT<<<dim3(DD/32, DD/32), 256>>>(ca_wo + (size_t)l*DD*DD, BH, BL, DD, DD);
        tgemm3<<<dim3(DD/128, RR/128), 256, 65536>>>(ATH, ATL, BH, BL, QKV, RR, DD, DD, 0);
        ln_res_split<<<RR, 256>>>(QKV, ca_og + l*DD, X, ff_ng + l*DD, XQH, XQL);

        // ---------------- feed-forward (SwiGLU; w2 accumulates into X) -----
        convBT<<<dim3((2*FFI)/32, DD/32), 256>>>(ff_w1 + (size_t)l*DD*2*FFI, BH, BL, DD, 2*FFI);
        tgemm3<<<dim3((2*FFI)/128, RR/128), 256, 65536>>>(XQH, XQL, BH, BL, HG, RR, 2*FFI, DD, 0);
        glu_split<<<2048, 256>>>(HG, AH, AL);
        convBT<<<dim3(DD/32, FFI/32), 256>>>(ff_w2 + (size_t)l*FFI*DD, BH, BL, FFI, DD);
        tgemm3<<<dim3(DD/128, RR/128), 256, 65536>>>(AH, AL, BH, BL, X, RR, DD, FFI, 1);
    }

    final_ln_kernel<<<RR, 256>>>(X, normg, out, DD);
}

// round 11
// speedup vs baseline: 3.8150x; 1.0472x over previous
#include <cuda_runtime.h>
#include <cuda_bf16.h>
#include <math.h>
#include <stdint.h>

// Problem constants
#define BB   4
#define NQ   1024
#define MM   512
#define DD   512
#define PP   256
#define HH   8
#define DH   64
#define LL   6
#define FFI  2048
#define RR   (BB*NQ)        // 4096
#define CR   (BB*MM)        // 2048
#define PADS 1152           // padded kv rows
#define PW   1152           // V^T row stride
#define QW   640            // fused QKV row width
// per-layer converted-weight region (elems) and job offsets
#define WL   4292608L
#define WOF_WQ   0L
#define WOF_WKV  262144L
#define WOF_WO   327680L
#define WOF_CWQ  589824L
#define WOF_CWKV 851968L
#define WOF_CWO  884736L
#define WOF_W1   1146880L
#define WOF_W2   3244032L

// ---------------- scratch (static device globals) --------------------------
__device__ float g_x   [RR*DD];
__device__ float g_q   [RR*QW];          // QKV / Q / wo-out buffer
__device__ float g_kv  [CR*128];
__device__ float g_bias[HH*1024];
__device__ __nv_bfloat16 g_AH[(size_t)RR*2048];  // partitioned act splits
__device__ __nv_bfloat16 g_AL[(size_t)RR*2048];
__device__ __nv_bfloat16 g_GH[(size_t)RR*FFI];   // GLU output split
__device__ __nv_bfloat16 g_GL[(size_t)RR*FFI];
__device__ __nv_bfloat16 g_BH[(size_t)LL*WL];    // all converted weights
__device__ __nv_bfloat16 g_BL[(size_t)LL*WL];
__device__ __nv_bfloat16 g_KH[(size_t)BB*PADS*DH];
__device__ __nv_bfloat16 g_KL[(size_t)BB*PADS*DH];
__device__ __nv_bfloat16 g_VTH[(size_t)BB*DH*PW];
__device__ __nv_bfloat16 g_VTL[(size_t)BB*DH*PW];

// ---------------- reductions ------------------------------------------------
__device__ __forceinline__ float warpSum(float v){
    #pragma unroll
    for (int o=16;o;o>>=1) v += __shfl_xor_sync(0xffffffffu, v, o);
    return v;
}
__device__ __forceinline__ float warpMax(float v){
    #pragma unroll
    for (int o=16;o;o>>=1) v = fmaxf(v, __shfl_xor_sync(0xffffffffu, v, o));
    return v;
}
__device__ float blockSum(float v){
    __shared__ float sh[8];
    int lane = threadIdx.x & 31, w = threadIdx.x >> 5;
    v = warpSum(v);
    if (lane == 0) sh[w] = v;
    __syncthreads();
    v = (threadIdx.x < 8) ? sh[threadIdx.x] : 0.f;
    v = warpSum(v);
    if (threadIdx.x == 0) sh[0] = v;
    __syncthreads();
    float r = sh[0];
    __syncthreads();
    return r;
}
__device__ float blockMax(float v){
    __shared__ float sh[8];
    int lane = threadIdx.x & 31, w = threadIdx.x >> 5;
    v = warpMax(v);
    if (lane == 0) sh[w] = v;
    __syncthreads();
    v = (threadIdx.x < 8) ? sh[threadIdx.x] : -3.4e38f;
    v = warpMax(v);
    if (threadIdx.x == 0) sh[0] = v;
    __syncthreads();
    float r = sh[0];
    __syncthreads();
    return r;
}

// ---------------- bf16 split helpers ---------------------------------------
__device__ __forceinline__ void split_bf16(float x, unsigned short& h, unsigned short& l){
    __nv_bfloat16 hb = __float2bfloat16_rn(x);
    __nv_bfloat16 lb = __float2bfloat16_rn(x - __bfloat162float(hb));
    h = __bfloat16_as_ushort(hb);
    l = __bfloat16_as_ushort(lb);
}

// ---------------- elementwise ----------------------------------------------
__global__ void copy_kernel(const float* __restrict__ in, float* __restrict__ out, int n){
    for (int i = blockIdx.x*blockDim.x + threadIdx.x; i < n; i += gridDim.x*blockDim.x)
        out[i] = in[i];
}
// rel-pos bias table
__global__ void bias_tab_kernel(const float* __restrict__ rel_emb, float* __restrict__ tab){
    int n = blockIdx.x*256 + threadIdx.x;
    if (n >= 1024) return;
    int bucket;
    if (n < 16) bucket = n;
    else {
        int large = 16 + (int)(logf((float)n * 0.0625f) * (16.0f / 2.0794415416798357f));
        bucket = large < 31 ? large : 31;
    }
    #pragma unroll
    for (int h = 0; h < HH; h++)
        tab[h*1024 + n] = rel_emb[bucket*HH + n >= 0 ? bucket*HH + h - bucket*HH + bucket*HH : 0];
}

// ---------------- batched weight conversion (all layers, one launch) --------
// 4192 tiles per layer; job table in compile-time constants.
// w1 is column-permuted: new col n' <- old col (n'>>1) + (n'&1)*FFI, so that
// (h, gate) pairs are adjacent for the fused-GLU GEMM epilogue.
__global__ __launch_bounds__(256) void convBT_all(
    const float* __restrict__ wq,  const float* __restrict__ wkv,
    const float* __restrict__ wo,  const float* __restrict__ cwq,
    const float* __restrict__ cwkv,const float* __restrict__ cwo,
    const float* __restrict__ w1,  const float* __restrict__ w2,
    __nv_bfloat16* __restrict__ hi, __nv_bfloat16* __restrict__ lo){
    int tb = blockIdx.x;
    int layer = tb / 4192;
    int rt = tb - layer*4192;
    const float* src; int K, N, ntx, perm = 0; long dstoff;
    if      (rt < 256 ){           src = wq  + (size_t)layer*512*512;  K=512;  N=512;  ntx=16;  dstoff=WOF_WQ;  }
    else if (rt < 320 ){ rt-=256;  src = wkv + (size_t)layer*512*128;  K=512;  N=128;  ntx=4;   dstoff=WOF_WKV; }
    else if (rt < 576 ){ rt-=320;  src = wo  + (size_t)layer*512*512;  K=512;  N=512;  ntx=16;  dstoff=WOF_WO;  }
    else if (rt < 832 ){ rt-=576;  src = cwq + (size_t)layer*512*512;  K=512;  N=512;  ntx=16;  dstoff=WOF_CWQ; }
    else if (rt < 864 ){ rt-=832;  src = cwkv+ (size_t)layer*256*128;  K=256;  N=128;  ntx=4;   dstoff=WOF_CWKV;}
    else if (rt < 1120){ rt-=864;  src = cwo + (size_t)layer*512*512;  K=512;  N=512;  ntx=16;  dstoff=WOF_CWO; }
    else if (rt < 3168){ rt-=1120; src = w1  + (size_t)layer*512*4096; K=512;  N=4096; ntx=128; dstoff=WOF_W1; perm=1; }
    else               { rt-=3168; src = w2  + (size_t)layer*2048*512; K=2048; N=512;  ntx=16;  dstoff=WOF_W2;  }
    dstoff += (long)layer * WL;
    int n0 = (rt % ntx)*32, k0 = (rt / ntx)*32;

    __shared__ float tile[32][33];
    int tx = threadIdx.x & 31, ty = threadIdx.x >> 5;
    int cc = n0 + tx;
    int scol = perm ? ((cc>>1) + (cc&1)*FFI) : cc;
    #pragma unroll
    for (int i = 0; i < 4; i++)
        tile[ty + 8*i][tx] = src[(long)(k0 + ty + 8*i)*N + scol];
    __syncthreads();
    #pragma unroll
    for (int i = 0; i < 4; i++){
        int n = ty + 8*i;
        float v = tile[tx][n];
        unsigned short h, l;
        split_bf16(v, h, l);
        long off = dstoff + (long)(n0 + n)*K + k0 + tx;
        hi[off] = __ushort_as_bfloat16(h);
        lo[off] = __ushort_as_bfloat16(l);
    }
}

// ---------------- layernorm family -----------------------------------------
__global__ __launch_bounds__(256) void ln_split(const float* __restrict__ in,
                                                const float* __restrict__ g,
                                                __nv_bfloat16* __restrict__ hi,
                                                __nv_bfloat16* __restrict__ lo, int cols){
    long ro = (long)blockIdx.x * cols;
    int t = threadIdx.x;
    float v0 = (t       < cols) ? in[ro + t]       : 0.f;
    float v1 = (t + 256 < cols) ? in[ro + t + 256] : 0.f;
    float mu = blockSum(v0 + v1) / (float)cols;
    float d0 = (t       < cols) ? v0 - mu : 0.f;
    float d1 = (t + 256 < cols) ? v1 - mu : 0.f;
    float var = blockSum(d0*d0 + d1*d1) / (float)cols;
    float inv = 1.f / sqrtf(var + 1e-5f);
    unsigned short h, l;
    if (t < cols){
        split_bf16(d0 * inv * g[t], h, l);
        hi[ro + t] = __ushort_as_bfloat16(h);
        lo[ro + t] = __ushort_as_bfloat16(l);
    }
    if (t + 256 < cols){
        split_bf16(d1 * inv * g[t + 256], h, l);
        hi[ro + t + 256] = __ushort_as_bfloat16(h);
        lo[ro + t + 256] = __ushort_as_bfloat16(l);
    }
}
// fused: x += LN_g1(qin); then hi/lo = split(LN_g2(x))   (cols == 512)
__global__ __launch_bounds__(256) void ln_res_split(const float* __restrict__ qin,
                                                    const float* __restrict__ g1,
                                                    float* __restrict__ x,
                                                    const float* __restrict__ g2,
                                                    __nv_bfloat16* __restrict__ hi,
                                                    __nv_bfloat16* __restrict__ lo){
    long ro = (long)blockIdx.x * DD;
    int t = threadIdx.x;
    float q0 = qin[ro + t], q1 = qin[ro + t + 256];
    float mu = blockSum(q0 + q1) * (1.f/512.f);
    float d0 = q0 - mu, d1 = q1 - mu;
    float var = blockSum(d0*d0 + d1*d1) * (1.f/512.f);
    float inv = 1.f / sqrtf(var + 1e-5f);
    float x0 = x[ro + t]       + d0 * inv * g1[t];
    float x1 = x[ro + t + 256] + d1 * inv * g1[t + 256];
    x[ro + t]       = x0;
    x[ro + t + 256] = x1;
    float mu2 = blockSum(x0 + x1) * (1.f/512.f);
    float e0 = x0 - mu2, e1 = x1 - mu2;
    float var2 = blockSum(e0*e0 + e1*e1) * (1.f/512.f);
    float inv2 = 1.f / sqrtf(var2 + 1e-5f);
    unsigned short h, l;
    split_bf16(e0 * inv2 * g2[t], h, l);
    hi[ro + t] = __ushort_as_bfloat16(h);
    lo[ro + t] = __ushort_as_bfloat16(l);
    split_bf16(e1 * inv2 * g2[t + 256], h, l);
    hi[ro + t + 256] = __ushort_as_bfloat16(h);
    lo[ro + t + 256] = __ushort_as_bfloat16(l);
}
__global__ __launch_bounds__(256) void final_ln_kernel(const float* __restrict__ in,
                                                       const float* __restrict__ g,
                                                       float* __restrict__ out, int cols){
    long ro = (long)blockIdx.x * cols;
    int t = threadIdx.x;
    float v0 = (t       < cols) ? in[ro + t]       : 0.f;
    float v1 = (t + 256 < cols) ? in[ro + t + 256] : 0.f;
    float m0 = (t       < cols) ? v0 : -3.4e38f;
    float m1 = (t + 256 < cols) ? v1 : -3.4e38f;
    float mx = blockMax(fmaxf(m0, m1));
    v0 /= mx; v1 /= mx;
    float s0 = (t       < cols) ? v0 : 0.f;
    float s1 = (t + 256 < cols) ? v1 : 0.f;
    float mu = blockSum(s0 + s1) / (float)cols;
    float d0 = (t       < cols) ? v0 - mu : 0.f;
    float d1 = (t + 256 < cols) ? v1 - mu : 0.f;
    float var = blockSum(d0*d0 + d1*d1) / (float)cols;
    float inv = 1.f / sqrtf(var + 1e-5f);
    if (t       < cols) out[ro + t]       = d0 * inv * g[t];
    if (t + 256 < cols) out[ro + t + 256] = d1 * inv * g[t + 256];
}

// ---------------- rotary / prep --------------------------------------------
__device__ __forceinline__ float inv_freq(int m){
    return powf(10000.f, -(float)m * (1.f/16.f));
}
__global__ __launch_bounds__(256) void qprep_split(const float* __restrict__ q, int qstride,
                                                   __nv_bfloat16* __restrict__ QH,
                                                   __nv_bfloat16* __restrict__ QL,
                                                   int n, int use_rot){
    int row = blockIdx.x;
    int r = threadIdx.x;
    int h = r >> 5, t = r & 31;
    const float* p = q + (long)row * qstride + h * DH;
    long ob = (long)row * DD + h * DH;
    const float sc = 0.125f;
    float va, vb; int ia, ib;
    if (t < 16){
        float a = p[t] * sc, b = p[t+16] * sc;
        if (use_rot){
            float f = (float)(row % n) * inv_freq(t);
            float cf = cosf(f), sf = sinf(f);
            va = a*cf - b*sf; vb = a*sf + b*cf;
        } else { va = a; vb = b; }
        ia = t; ib = t + 16;
    } else {
        va = p[t+16] * sc; vb = p[t+32] * sc;
        ia = t + 16; ib = t + 32;
    }
    unsigned short hh, ll;
    split_bf16(va, hh, ll);
    QH[ob+ia] = __ushort_as_bfloat16(hh); QL[ob+ia] = __ushort_as_bfloat16(ll);
    split_bf16(vb, hh, ll);
    QH[ob+ib] = __ushort_as_bfloat16(hh); QL[ob+ib] = __ushort_as_bfloat16(ll);
}
__global__ __launch_bounds__(64) void kvprep2(const float* __restrict__ kv, int kvstride,
                                              const float* __restrict__ null_kv,
                                              __nv_bfloat16* __restrict__ KH, __nv_bfloat16* __restrict__ KL,
                                              __nv_bfloat16* __restrict__ VTH, __nv_bfloat16* __restrict__ VTL,
                                              int nk, int use_rot, int padK){
    int rblk = blockIdx.x;
    int d = threadIdx.x;
    int nkv = nk + 1;
    int b = rblk / padK, j = rblk % padK;
    long koff = ((long)b * PADS + j) * DH + d;
    long voff = ((long)b * DH + d) * PW + j;
    if (j >= nkv){
        KH[koff] = __ushort_as_bfloat16(0); KL[koff] = __ushort_as_bfloat16(0);
        VTH[voff] = __ushort_as_bfloat16(0); VTL[voff] = __ushort_as_bfloat16(0);
        return;
    }
    float kval, vval;
    if (j == 0){
        kval = null_kv[d];
        vval = null_kv[DH + d];
    } else {
        int i = j - 1;
        const float* src = kv + ((long)b * nk + i) * kvstride;
        kval = src[d];
        vval = src[DH + d];
        if (use_rot && d < 32){
            int m = d & 15;
            float f = (float)i * inv_freq(m);
            float cf = cosf(f), sf = sinf(f);
            if (d < 16) kval = kval*cf - src[d+16]*sf;
            else        kval = kval*cf + src[d-16]*sf;
        }
    }
    unsigned short h, l;
    split_bf16(kval, h, l);
    KH[koff] = __ushort_as_bfloat16(h); KL[koff] = __ushort_as_bfloat16(l);
    split_bf16(vval, h, l);
    VTH[voff] = __ushort_as_bfloat16(h); VTL[voff] = __ushort_as_bfloat16(l);
}

// ============================================================================
//  mma helpers
// ============================================================================
__device__ __forceinline__ uint32_t smem_u32(const void* p){
    uint32_t a;
    asm("{ .reg .u64 t; cvta.to.shared.u64 t, %1; cvt.u32.u64 %0, t; }" : "=r"(a) : "l"(p));
    return a;
}
__device__ __forceinline__ void cpg(uint32_t sm, const void* g){
    asm volatile("cp.async.cg.shared.global [%0], [%1], 16;" :: "r"(sm), "l"(g));
}
#define CP_COMMIT() asm volatile("cp.async.commit_group;" ::: "memory")
#define CP_WAIT1()  asm volatile("cp.async.wait_group 1;" ::: "memory")
#define CP_WAIT0()  asm volatile("cp.async.wait_group 0;" ::: "memory")
__device__ __forceinline__ void ldsm4(uint32_t* r, uint32_t addr){
    asm volatile("ldmatrix.sync.aligned.m8n8.x4.shared.b16 {%0,%1,%2,%3}, [%4];"
        : "=r"(r[0]),"=r"(r[1]),"=r"(r[2]),"=r"(r[3]) : "r"(addr));
}
__device__ __forceinline__ void mma16816(float* d, const uint32_t* a, uint32_t b0, uint32_t b1){
    asm volatile("mma.sync.aligned.m16n8k16.row.col.f32.bf16.bf16.f32 "
        "{%0,%1,%2,%3}, {%4,%5,%6,%7}, {%8,%9}, {%0,%1,%2,%3};"
        : "+f"(d[0]),"+f"(d[1]),"+f"(d[2]),"+f"(d[3])
        : "r"(a[0]),"r"(a[1]),"r"(a[2]),"r"(a[3]), "r"(b0),"r"(b1));
}
#define SWOFF(r,c)  ((((r)*4 + ((c) ^ (((r)>>1)&3)))) << 4)
#define SWOFF8(r,c) ((((r)*8 + ((c) ^ ((r)&7)))) << 4)

#define COMPUTE_128x128(ss)                                                        \
    _Pragma("unroll")                                                              \
    for (int s = 0; s < 2; s++){                                                   \
        uint32_t ah[4][4], al[4][4], bhf[4][2], blf[4][2];                         \
        _Pragma("unroll")                                                          \
        for (int mt = 0; mt < 4; mt++){                                            \
            int r = wm + mt*16 + (lane & 15);                                      \
            int cl = 2*s + (lane >> 4);                                            \
            uint32_t addr = (ss) + SWOFF(r, cl);                                   \
            ldsm4(ah[mt], addr);                                                   \
            ldsm4(al[mt], addr + 8192);                                            \
        }                                                                          \
        _Pragma("unroll")                                                          \
        for (int g = 0; g < 2; g++){                                               \
            int r = wn + g*16 + (lane & 7) + ((lane >> 4) << 3);                   \
            int cl = 2*s + ((lane >> 3) & 1);                                      \
            uint32_t addr = (ss) + 16384 + SWOFF(r, cl);                           \
            uint32_t tmp[4];                                                       \
            ldsm4(tmp, addr);                                                      \
            bhf[2*g][0]=tmp[0]; bhf[2*g][1]=tmp[1]; bhf[2*g+1][0]=tmp[2]; bhf[2*g+1][1]=tmp[3]; \
            ldsm4(tmp, addr + 8192);                                               \
            blf[2*g][0]=tmp[0]; blf[2*g][1]=tmp[1]; blf[2*g+1][0]=tmp[2]; blf[2*g+1][1]=tmp[3]; \
        }                                                                          \
        _Pragma("unroll")                                                          \
        for (int mt = 0; mt < 4; mt++)                                             \
            _Pragma("unroll")                                                      \
            for (int nt = 0; nt < 4; nt++){                                        \
                mma16816(acc[mt][nt], ah[mt], bhf[nt][0], bhf[nt][1]);             \
                mma16816(acc[mt][nt], ah[mt], blf[nt][0], blf[nt][1]);             \
                mma16816(acc[mt][nt], al[mt], bhf[nt][0], bhf[nt][1]);             \
            }                                                                      \
    }

#define GEMM_PREAMBLE                                                              \
    extern __shared__ __align__(16) char sm[];                                     \
    uint32_t sb = smem_u32(sm);                                                    \
    int t = threadIdx.x, lane = t & 31, warp = t >> 5;                             \
    int wm = (warp >> 2) * 64, wn = (warp & 3) * 32;                               \
    long rowBase = (long)blockIdx.y * 128;                                         \
    long colBase = (long)blockIdx.x * 128;                                         \
    const __nv_bfloat16* srcs[4] = { Ah + rowBase*K, Al + rowBase*K,               \
                                     Bh + colBase*K, Bl + colBase*K };             \
    int lr = t >> 2, lc = t & 3;                                                   \
    float acc[4][4][4];                                                            \
    _Pragma("unroll")                                                              \
    for (int i=0;i<4;i++)                                                          \
        _Pragma("unroll")                                                          \
        for (int j=0;j<4;j++)                                                      \
            _Pragma("unroll")                                                      \
            for (int e=0;e<4;e++) acc[i][j][e] = 0.f;

#define GEMM_MAINLOOP                                                              \
    int nch = K >> 5;                                                              \
    DLOAD(0, 0);                                                                   \
    for (int c = 0; c < nch; c++){                                                 \
        int st = c & 1;                                                            \
        if (c + 1 < nch){ DLOAD((c+1)&1, (c+1)*32); CP_WAIT1(); }                  \
        else CP_WAIT0();                                                           \
        __syncthreads();                                                           \
        uint32_t ss = sb + st*32768;                                               \
        COMPUTE_128x128(ss);                                                       \
        __syncthreads();                                                           \
    }

#define DLOAD(st, k0) do {                                                  \
    _Pragma("unroll")                                                       \
    for (int tt = 0; tt < 4; tt++){                                         \
        const __nv_bfloat16* s = srcs[tt] + (k0);                           \
        uint32_t so = sb + (st)*32768 + tt*8192;                            \
        cpg(so + SWOFF(lr, lc),      s + (long)lr*K + lc*8);                \
        cpg(so + SWOFF(lr+64, lc),   s + (long)(lr+64)*K + lc*8);           \
    }                                                                       \
    CP_COMMIT(); } while(0)

// ---------------- dense GEMM: C = A[MxK] @ B'[NxK]^T (+=C if addC) ----------
__global__ __launch_bounds__(256, 2) void tgemm3(const __nv_bfloat16* __restrict__ Ah,
                                                 const __nv_bfloat16* __restrict__ Al,
                                                 const __nv_bfloat16* __restrict__ Bh,
                                                 const __nv_bfloat16* __restrict__ Bl,
                                                 float* __restrict__ C,
                                                 int M, int N, int K, int addC){
    GEMM_PREAMBLE
    GEMM_MAINLOOP
    #pragma unroll
    for (int mt = 0; mt < 4; mt++){
        long r = rowBase + wm + mt*16 + (lane >> 2);
        #pragma unroll
        for (int nt = 0; nt < 4; nt++){
            long cc = colBase + wn + nt*8 + 2*(lane & 3);
            float2 v0; v0.x = acc[mt][nt][0]; v0.y = acc[mt][nt][1];
            float2 v1; v1.x = acc[mt][nt][2]; v1.y = acc[mt][nt][3];
            float2* p0 = (float2*)(C + r*N + cc);
            float2* p1 = (float2*)(C + (r+8)*N + cc);
            if (addC){
                float2 c0 = *p0, c1 = *p1;
                v0.x += c0.x; v0.y += c0.y;
                v1.x += c1.x; v1.y += c1.y;
            }
            *p0 = v0;
            *p1 = v1;
        }
    }
}

// ---------------- GLU-fused GEMM: adjacent (h, gate) column pairs ----------
// B is the column-permuted w1 (N = 2*FFI); epilogue computes h*silu(gate)
// per register pair and writes the hi/lo bf16 split of [M][FFI].
__global__ __launch_bounds__(256, 2) void tgemm3_glu(const __nv_bfloat16* __restrict__ Ah,
                                                     const __nv_bfloat16* __restrict__ Al,
                                                     const __nv_bfloat16* __restrict__ Bh,
                                                     const __nv_bfloat16* __restrict__ Bl,
                                                     __nv_bfloat16* __restrict__ GH,
                                                     __nv_bfloat16* __restrict__ GL,
                                                     int M, int N, int K){
    GEMM_PREAMBLE
    GEMM_MAINLOOP
    #pragma unroll
    for (int mt = 0; mt < 4; mt++){
        long r = rowBase + wm + mt*16 + (lane >> 2);
        #pragma unroll
        for (int nt = 0; nt < 4; nt++){
            long oc = (colBase + wn + nt*8)/2 + (lane & 3);
            float h0 = acc[mt][nt][0], gg0 = acc[mt][nt][1];
            float h1 = acc[mt][nt][2], gg1 = acc[mt][nt][3];
            float v0 = h0 * (gg0 / (1.f + expf(-gg0)));
            float v1 = h1 * (gg1 / (1.f + expf(-gg1)));
            unsigned short hs, ls;
            split_bf16(v0, hs, ls);
            GH[r*FFI + oc] = __ushort_as_bfloat16(hs);
            GL[r*FFI + oc] = __ushort_as_bfloat16(ls);
            split_bf16(v1, hs, ls);
            GH[(r+8)*FFI + oc] = __ushort_as_bfloat16(hs);
            GL[(r+8)*FFI + oc] = __ushort_as_bfloat16(ls);
        }
    }
}
#undef DLOAD

// ============================================================================
//  Fused flash attention (writes hi/lo bf16 split of O directly)
// ============================================================================
#define FSM_Q  0
#define FSM_K  16384
#define FSM_V  32768
#define FSM_B  49152
#define FSM_TOT (49152 + 4096)

__global__ __launch_bounds__(128) void flash_attn(const __nv_bfloat16* __restrict__ Qh,
                                                  const __nv_bfloat16* __restrict__ Ql,
                                                  const __nv_bfloat16* __restrict__ KHp,
                                                  const __nv_bfloat16* __restrict__ KLp,
                                                  const __nv_bfloat16* __restrict__ VTHp,
                                                  const __nv_bfloat16* __restrict__ VTLp,
                                                  const float* __restrict__ bias_tab,
                                                  __nv_bfloat16* __restrict__ OH,
                                                  __nv_bfloat16* __restrict__ OL,
                                                  int nkv, int cb){
    extern __shared__ __align__(16) char sm[];
    uint32_t sb = smem_u32(sm);
    int t = threadIdx.x, lane = t & 31, warp = t >> 5;
    int bh = blockIdx.y, b = bh >> 3, h = bh & 7;
    int i0 = blockIdx.x * 64;

    {
        const __nv_bfloat16* qh = Qh + ((long)(b*NQ + i0))*DD + h*DH;
        const __nv_bfloat16* ql = Ql + ((long)(b*NQ + i0))*DD + h*DH;
        for (int i = t; i < 512; i += 128){
            int r = i >> 3, c = i & 7;
            cpg(sb + FSM_Q        + SWOFF8(r,c), qh + (long)r*DD + c*8);
            cpg(sb + FSM_Q + 8192 + SWOFF8(r,c), ql + (long)r*DD + c*8);
        }
        CP_COMMIT();
    }
    if (cb){
        float* bsm = (float*)(sm + FSM_B);
        for (int i = t; i < 1024; i += 128) bsm[i] = bias_tab[h*1024 + i];
    }
    CP_WAIT0();
    __syncthreads();

    uint32_t qfh[4][4], qfl[4][4];
    #pragma unroll
    for (int s = 0; s < 4; s++){
        int r = warp*16 + (lane & 15);
        int cl = 2*s + (lane >> 4);
        ldsm4(qfh[s], sb + FSM_Q + SWOFF8(r, cl));
        ldsm4(qfl[s], sb + FSM_Q + 8192 + SWOFF8(r, cl));
    }

    float o[8][4];
    #pragma unroll
    for (int i=0;i<8;i++)
        #pragma unroll
        for (int e=0;e<4;e++) o[i][e] = 0.f;
    float mx0 = -3.0e38f, mx1 = -3.0e38f, sum0 = 0.f, sum1 = 0.f;

    int jt_max = (nkv - 1) >> 6;
    if (cb){ int jm = (i0 + 64) >> 6; if (jm < jt_max) jt_max = jm; }
    const __nv_bfloat16* kh = KHp + (long)b*PADS*DH;
    const __nv_bfloat16* kl = KLp + (long)b*PADS*DH;
    const __nv_bfloat16* vh = VTHp + (long)b*DH*PW;
    const __nv_bfloat16* vl = VTLp + (long)b*DH*PW;
    const float* bsm = (const float*)(sm + FSM_B);

    for (int jt = 0; jt <= jt_max; jt++){
        for (int i = t; i < 512; i += 128){
            int r = i >> 3, c = i & 7;
            cpg(sb + FSM_K        + SWOFF8(r,c), kh + ((long)(jt*64 + r))*DH + c*8);
            cpg(sb + FSM_K + 8192 + SWOFF8(r,c), kl + ((long)(jt*64 + r))*DH + c*8);
        }
        CP_COMMIT();
        for (int i = t; i < 512; i += 128){
            int r = i >> 3, c = i & 7;
            cpg(sb + FSM_V        + SWOFF8(r,c), vh + (long)r*PW + jt*64 + c*8);
            cpg(sb + FSM_V + 8192 + SWOFF8(r,c), vl + (long)r*PW + jt*64 + c*8);
        }
        CP_COMMIT();
        CP_WAIT1();
        __syncthreads();

        float sacc[8][4];
        #pragma unroll
        for (int i=0;i<8;i++)
            #pragma unroll
            for (int e=0;e<4;e++) sacc[i][e] = 0.f;
        #pragma unroll
        for (int s = 0; s < 4; s++){
            uint32_t bhf[8][2], blf[8][2];
            #pragma unroll
            for (int g = 0; g < 4; g++){
                int r = g*16 + (lane & 7) + ((lane >> 4) << 3);
                int cl = 2*s + ((lane >> 3) & 1);
                uint32_t tmp[4];
                ldsm4(tmp, sb + FSM_K + SWOFF8(r, cl));
                bhf[2*g][0]=tmp[0]; bhf[2*g][1]=tmp[1]; bhf[2*g+1][0]=tmp[2]; bhf[2*g+1][1]=tmp[3];
                ldsm4(tmp, sb + FSM_K + 8192 + SWOFF8(r, cl));
                blf[2*g][0]=tmp[0]; blf[2*g][1]=tmp[1]; blf[2*g+1][0]=tmp[2]; blf[2*g+1][1]=tmp[3];
            }
            #pragma unroll
            for (int nt = 0; nt < 8; nt++){
                mma16816(sacc[nt], qfh[s], bhf[nt][0], bhf[nt][1]);
                mma16816(sacc[nt], qfh[s], blf[nt][0], blf[nt][1]);
                mma16816(sacc[nt], qfl[s], bhf[nt][0], bhf[nt][1]);
            }
        }

        int ibase = i0 + warp*16 + (lane >> 2);
        int jbase = jt*64 + 2*(lane & 3);
        float tmx0 = -3.0e38f, tmx1 = -3.0e38f;
        #pragma unroll
        for (int nt = 0; nt < 8; nt++){
            #pragma unroll
            for (int e = 0; e < 4; e++){
                int i = ibase + ((e >> 1) << 3);
                int j = jbase + nt*8 + (e & 1);
                float s = sacc[nt][e];
                if (cb){
                    int nn = i - j; if (nn < 0) nn = 0;
                    s += bsm[nn];
                    if (j > i + 1) s = -1e30f;
                }
                if (j >= nkv) s = -1e30f;
                sacc[nt][e] = s;
                if (e < 2) tmx0 = fmaxf(tmx0, s); else tmx1 = fmaxf(tmx1, s);
            }
        }
        tmx0 = fmaxf(tmx0, __shfl_xor_sync(0xffffffffu, tmx0, 1));
        tmx0 = fmaxf(tmx0, __shfl_xor_sync(0xffffffffu, tmx0, 2));
        tmx1 = fmaxf(tmx1, __shfl_xor_sync(0xffffffffu, tmx1, 1));
        tmx1 = fmaxf(tmx1, __shfl_xor_sync(0xffffffffu, tmx1, 2));
        float nmx0 = fmaxf(mx0, tmx0), nmx1 = fmaxf(mx1, tmx1);
        float al0 = expf(mx0 - nmx0), al1 = expf(mx1 - nmx1);
        mx0 = nmx0; mx1 = nmx1;
        sum0 *= al0; sum1 *= al1;
        #pragma unroll
        for (int nt = 0; nt < 8; nt++){
            o[nt][0] *= al0; o[nt][1] *= al0;
            o[nt][2] *= al1; o[nt][3] *= al1;
        }

        CP_WAIT0();
        __syncthreads();

        float ts0 = 0.f, ts1 = 0.f;
        #pragma unroll
        for (int kg = 0; kg < 4; kg++){
            uint32_t phf[4], plf[4];
            #pragma unroll
            for (int half = 0; half < 2; half++){
                int nt = 2*kg + half;
                unsigned short hb[4], lb[4];
                #pragma unroll
                for (int e = 0; e < 4; e++){
                    float pe = expf(sacc[nt][e] - ((e < 2) ? mx0 : mx1));
                    if (e < 2) ts0 += pe; else ts1 += pe;
                    split_bf16(pe, hb[e], lb[e]);
                }
                phf[2*half+0] = (uint32_t)hb[0] | ((uint32_t)hb[1] << 16);
                phf[2*half+1] = (uint32_t)hb[2] | ((uint32_t)hb[3] << 16);
                plf[2*half+0] = (uint32_t)lb[0] | ((uint32_t)lb[1] << 16);
                plf[2*half+1] = (uint32_t)lb[2] | ((uint32_t)lb[3] << 16);
            }
            uint32_t vhf[8][2], vlf[8][2];
            #pragma unroll
            for (int g = 0; g < 4; g++){
                int r = g*16 + (lane & 7) + ((lane >> 4) << 3);
                int cl = 2*kg + ((lane >> 3) & 1);
                uint32_t tmp[4];
                ldsm4(tmp, sb + FSM_V + SWOFF8(r, cl));
                vhf[2*g][0]=tmp[0]; vhf[2*g][1]=tmp[1]; vhf[2*g+1][0]=tmp[2]; vhf[2*g+1][1]=tmp[3];
                ldsm4(tmp, sb + FSM_V + 8192 + SWOFF8(r, cl));
                vlf[2*g][0]=tmp[0]; vlf[2*g][1]=tmp[1]; vlf[2*g+1][0]=tmp[2]; vlf[2*g+1][1]=tmp[3];
            }
            #pragma unroll
            for (int nt = 0; nt < 8; nt++){
                mma16816(o[nt], phf, vhf[nt][0], vhf[nt][1]);
                mma16816(o[nt], phf, vlf[nt][0], vlf[nt][1]);
                mma16816(o[nt], plf, vhf[nt][0], vhf[nt][1]);
            }
        }
        ts0 += __shfl_xor_sync(0xffffffffu, ts0, 1);
        ts0 += __shfl_xor_sync(0xffffffffu, ts0, 2);
        ts1 += __shfl_xor_sync(0xffffffffu, ts1, 1);
        ts1 += __shfl_xor_sync(0xffffffffu, ts1, 2);
        sum0 += ts0; sum1 += ts1;
        __syncthreads();
    }

    float inv0 = 1.f / sum0, inv1 = 1.f / sum1;
    long r0 = (long)b*NQ + i0 + warp*16 + (lane >> 2);
    #pragma unroll
    for (int nt = 0; nt < 8; nt++){
        int c = nt*8 + 2*(lane & 3);
        unsigned short h0,h1,l0,l1;
        split_bf16(o[nt][0]*inv0, h0, l0);
        split_bf16(o[nt][1]*inv0, h1, l1);
        *(uint32_t*)(OH + r0*DD + h*DH + c) = (uint32_t)h0 | ((uint32_t)h1 << 16);
        *(uint32_t*)(OL + r0*DD + h*DH + c) = (uint32_t)l0 | ((uint32_t)l1 << 16);
        split_bf16(o[nt][2]*inv1, h0, l0);
        split_bf16(o[nt][3]*inv1, h1, l1);
        *(uint32_t*)(OH + (r0+8)*DD + h*DH + c) = (uint32_t)h0 | ((uint32_t)h1 << 16);
        *(uint32_t*)(OL + (r0+8)*DD + h*DH + c) = (uint32_t)l0 | ((uint32_t)l1 << 16);
    }
}

// ---------------- orchestration --------------------------------------------
extern "C" void kernel_launch(void* const* d_in, const int* in_sizes, int n_in,
                              void* d_out, int out_size){
    const float* x_in    = (const float*)d_in[0];
    const float* ctx     = (const float*)d_in[1];
    const float* rel_emb = (const float*)d_in[2];
    const float* sa_ng   = (const float*)d_in[3];
    const float* sa_wq   = (const float*)d_in[4];
    const float* sa_wkv  = (const float*)d_in[5];
    const float* sa_null = (const float*)d_in[6];
    const float* sa_wo   = (const float*)d_in[7];
    const float* sa_og   = (const float*)d_in[8];
    const float* ca_ng   = (const float*)d_in[9];
    const float* ca_cg   = (const float*)d_in[10];
    const float* ca_wq   = (const float*)d_in[11];
    const float* ca_wkv  = (const float*)d_in[12];
    const float* ca_null = (const float*)d_in[13];
    const float* ca_wo   = (const float*)d_in[14];
    const float* ca_og   = (const float*)d_in[15];
    const float* ff_ng   = (const float*)d_in[16];
    const float* ff_w1   = (const float*)d_in[17];
    const float* ff_w2   = (const float*)d_in[18];
    const float* normg   = (const float*)d_in[19];
    float* out = (float*)d_out;

    cudaFuncSetAttribute(tgemm3,     cudaFuncAttributeMaxDynamicSharedMemorySize, 65536);
    cudaFuncSetAttribute(tgemm3_glu, cudaFuncAttributeMaxDynamicSharedMemorySize, 65536);
    cudaFuncSetAttribute(flash_attn, cudaFuncAttributeMaxDynamicSharedMemorySize, FSM_TOT);

    float *X,*QKV,*KV,*BT;
    __nv_bfloat16 *AH,*AL,*GH,*GL,*BH,*BL,*KH,*KL,*VTH,*VTL;
    cudaGetSymbolAddress((void**)&X,    g_x);
    cudaGetSymbolAddress((void**)&QKV,  g_q);
    cudaGetSymbolAddress((void**)&KV,   g_kv);
    cudaGetSymbolAddress((void**)&BT,   g_bias);
    cudaGetSymbolAddress((void**)&AH,   g_AH);
    cudaGetSymbolAddress((void**)&AL,   g_AL);
    cudaGetSymbolAddress((void**)&GH,   g_GH);
    cudaGetSymbolAddress((void**)&GL,   g_GL);
    cudaGetSymbolAddress((void**)&BH,   g_BH);
    cudaGetSymbolAddress((void**)&BL,   g_BL);
    cudaGetSymbolAddress((void**)&KH,   g_KH);
    cudaGetSymbolAddress((void**)&KL,   g_KL);
    cudaGetSymbolAddress((void**)&VTH,  g_VTH);
    cudaGetSymbolAddress((void**)&VTL,  g_VTL);
    // activation split regions inside g_AH/g_AL (8M elems each):
    __nv_bfloat16 *XQH = AH,                         *XQL = AL;                        // [0,2M) XN/Q split
    __nv_bfloat16 *ATH = AH + (size_t)2*1024*1024,   *ATL = AL + (size_t)2*1024*1024;  // [2M,4M) ATT split
    __nv_bfloat16 *CXH = AH + (size_t)4*1024*1024,   *CXL = AL + (size_t)4*1024*1024;  // [4M,5M) ctx split

    copy_kernel<<<512, 256>>>(x_in, X, RR*DD);
    bias_tab_kernel<<<4, 256>>>(rel_emb, BT);
    // all weight conversions for all layers, one launch, off the critical path
    convBT_all<<<LL*4192, 256>>>(sa_wq, sa_wkv, sa_wo, ca_wq, ca_wkv, ca_wo,
                                 ff_w1, ff_w2, BH, BL);

    for (int l = 0; l < LL; l++){
        const __nv_bfloat16 *WBH = BH + (size_t)l*WL, *WBL = BL + (size_t)l*WL;

        // ---------------- self-attention (fused QKV GEMM, N=640) ----------
        ln_split<<<RR, 256>>>(X, sa_ng + l*DD, XQH, XQL, DD);
        tgemm3<<<dim3(QW/128, RR/128), 256, 65536>>>(XQH, XQL, WBH + WOF_WQ, WBL + WOF_WQ, QKV, RR, QW, DD, 0);
        kvprep2<<<BB*PADS, 64>>>(QKV + DD, QW, sa_null + l*128, KH, KL, VTH, VTL, NQ, 1, PADS);
        qprep_split<<<RR, 256>>>(QKV, QW, XQH, XQL, NQ, 1);
        flash_attn<<<dim3(NQ/64, BB*HH), 128, FSM_TOT>>>(XQH, XQL, KH, KL, VTH, VTL, BT, ATH, ATL, NQ+1, 1);
        tgemm3<<<dim3(DD/128, RR/128), 256, 65536>>>(ATH, ATL, WBH + WOF_WO, WBL + WOF_WO, QKV, RR, DD, DD, 0);
        ln_res_split<<<RR, 256>>>(QKV, sa_og + l*DD, X, ca_ng + l*DD, XQH, XQL);

        // ---------------- cross-attention ----------------
        ln_split<<<CR, 256>>>(ctx, ca_cg + l*PP, CXH, CXL, PP);
        tgemm3<<<dim3(DD/128, RR/128), 256, 65536>>>(XQH, XQL, WBH + WOF_CWQ, WBL + WOF_CWQ, QKV, RR, DD, DD, 0);
        tgemm3<<<dim3(1, CR/128), 256, 65536>>>(CXH, CXL, WBH + WOF_CWKV, WBL + WOF_CWKV, KV, CR, 128, PP, 0);
        kvprep2<<<BB*640, 64>>>(KV, 128, ca_null + l*128, KH, KL, VTH, VTL, MM, 0, 640);
        qprep_split<<<RR, 256>>>(QKV, DD, XQH, XQL, NQ, 0);
        flash_attn<<<dim3(NQ/64, BB*HH), 128, FSM_TOT>>>(XQH, XQL, KH, KL, VTH, VTL, BT, ATH, ATL, MM+1, 0);
        tgemm3<<<dim3(DD/128, RR/128), 256, 65536>>>(ATH, ATL, WBH + WOF_CWO, WBL + WOF_CWO, QKV, RR, DD, DD, 0);
        ln_res_split<<<RR, 256>>>(QKV, ca_og + l*DD, X, ff_ng + l*DD, XQH, XQL);

        // ---------------- feed-forward (GLU fused into w1 GEMM) ------------
        tgemm3_glu<<<dim3((2*FFI)/128, RR/128), 256, 65536>>>(XQH, XQL, WBH + WOF_W1, WBL + WOF_W1,
                                                              GH, GL, RR, 2*FFI, DD);
        tgemm3<<<dim3(DD/128, RR/128), 256, 65536>>>(GH, GL, WBH + WOF_W2, WBL + WOF_W2, X, RR, DD, FFI, 1);
    }

    final_ln_kernel<<<RR, 256>>>(X, normg, out, DD);
}

// round 12
// speedup vs baseline: 4.0124x; 1.0518x over previous
#include <cuda_runtime.h>
#include <cuda_bf16.h>
#include <math.h>
#include <stdint.h>

// Problem constants
#define BB   4
#define NQ   1024
#define MM   512
#define DD   512
#define PP   256
#define HH   8
#define DH   64
#define LL   6
#define FFI  2048
#define RR   (BB*NQ)        // 4096
#define CR   (BB*MM)        // 2048
#define PADS 1152           // padded kv rows
#define PW   1152           // V^T row stride
#define QW   640            // fused QKV row width
// per-layer converted-weight region (elems) and job offsets
#define WL   4292608L
#define WOF_WQ   0L
#define WOF_WKV  262144L
#define WOF_WO   327680L
#define WOF_CWQ  589824L
#define WOF_CWKV 851968L
#define WOF_CWO  884736L
#define WOF_W1   1146880L
#define WOF_W2   3244032L

// ---------------- scratch (static device globals) --------------------------
__device__ float g_x   [RR*DD];
__device__ float g_q   [RR*DD];          // wo / ca_wq fp32 out buffer
__device__ float g_kv  [CR*128];
__device__ float g_bias[HH*1024];
__device__ float g_rotc[1024*16];
__device__ float g_rots[1024*16];
__device__ __nv_bfloat16 g_AH[(size_t)RR*2048];  // partitioned act splits
__device__ __nv_bfloat16 g_AL[(size_t)RR*2048];
__device__ __nv_bfloat16 g_GH[(size_t)RR*FFI];   // GLU output split
__device__ __nv_bfloat16 g_GL[(size_t)RR*FFI];
__device__ __nv_bfloat16 g_BH[(size_t)LL*WL];    // all converted weights
__device__ __nv_bfloat16 g_BL[(size_t)LL*WL];
__device__ __nv_bfloat16 g_KH[(size_t)BB*PADS*DH];
__device__ __nv_bfloat16 g_KL[(size_t)BB*PADS*DH];
__device__ __nv_bfloat16 g_VTH[(size_t)BB*DH*PW];
__device__ __nv_bfloat16 g_VTL[(size_t)BB*DH*PW];

// ---------------- reductions ------------------------------------------------
__device__ __forceinline__ float warpSum(float v){
    #pragma unroll
    for (int o=16;o;o>>=1) v += __shfl_xor_sync(0xffffffffu, v, o);
    return v;
}
__device__ __forceinline__ float warpMax(float v){
    #pragma unroll
    for (int o=16;o;o>>=1) v = fmaxf(v, __shfl_xor_sync(0xffffffffu, v, o));
    return v;
}

// ---------------- bf16 split helpers ---------------------------------------
__device__ __forceinline__ void split_bf16(float x, unsigned short& h, unsigned short& l){
    __nv_bfloat16 hb = __float2bfloat16_rn(x);
    __nv_bfloat16 lb = __float2bfloat16_rn(x - __bfloat162float(hb));
    h = __bfloat16_as_ushort(hb);
    l = __bfloat16_as_ushort(lb);
}
__device__ __forceinline__ uint32_t splitpack_hi(float a, float b){
    unsigned short h0,l0,h1,l1;
    split_bf16(a,h0,l0); split_bf16(b,h1,l1);
    return (uint32_t)h0 | ((uint32_t)h1 << 16);
}
__device__ __forceinline__ void splitpack(float a, float b, uint32_t& hp, uint32_t& lp){
    unsigned short h0,l0,h1,l1;
    split_bf16(a,h0,l0); split_bf16(b,h1,l1);
    hp = (uint32_t)h0 | ((uint32_t)h1 << 16);
    lp = (uint32_t)l0 | ((uint32_t)l1 << 16);
}

// ---------------- elementwise ----------------------------------------------
__global__ void copy_kernel(const float* __restrict__ in, float* __restrict__ out, int n){
    for (int i = blockIdx.x*blockDim.x + threadIdx.x; i < n; i += gridDim.x*blockDim.x)
        out[i] = in[i];
}
// rel-pos bias table
__global__ void bias_tab_kernel(const float* __restrict__ rel_emb, float* __restrict__ tab){
    int n = blockIdx.x*256 + threadIdx.x;
    if (n >= 1024) return;
    int bucket;
    if (n < 16) bucket = n;
    else {
        int large = 16 + (int)(logf((float)n * 0.0625f) * (16.0f / 2.0794415416798357f));
        bucket = large < 31 ? large : 31;
    }
    #pragma unroll
    for (int h = 0; h < HH; h++)
        tab[h*1024 + n] = rel_emb[bucket*HH + h];
}
// rotary cos/sin table: [pos][m], f = pos * 10000^{-m/16}
__global__ void rot_tab_kernel(float* __restrict__ rc, float* __restrict__ rs){
    int idx = blockIdx.x*256 + threadIdx.x;
    if (idx >= 1024*16) return;
    int pos = idx >> 4, m = idx & 15;
    float f = (float)pos * powf(10000.f, -(float)m * (1.f/16.f));
    rc[idx] = cosf(f);
    rs[idx] = sinf(f);
}
// null kv row (j=0) for self-attention
__global__ void nullkv_kernel(const float* __restrict__ null_kv,
                              __nv_bfloat16* __restrict__ KH, __nv_bfloat16* __restrict__ KL,
                              __nv_bfloat16* __restrict__ VTH, __nv_bfloat16* __restrict__ VTL){
    int b = blockIdx.x, d = threadIdx.x;
    unsigned short h, l;
    split_bf16(null_kv[d], h, l);
    KH[(long)b*PADS*DH + d] = __ushort_as_bfloat16(h);
    KL[(long)b*PADS*DH + d] = __ushort_as_bfloat16(l);
    split_bf16(null_kv[DH + d], h, l);
    VTH[((long)b*DH + d)*PW] = __ushort_as_bfloat16(h);
    VTL[((long)b*DH + d)*PW] = __ushort_as_bfloat16(l);
}

// ---------------- batched weight conversion (all layers, one launch) --------
__global__ __launch_bounds__(256) void convBT_all(
    const float* __restrict__ wq,  const float* __restrict__ wkv,
    const float* __restrict__ wo,  const float* __restrict__ cwq,
    const float* __restrict__ cwkv,const float* __restrict__ cwo,
    const float* __restrict__ w1,  const float* __restrict__ w2,
    __nv_bfloat16* __restrict__ hi, __nv_bfloat16* __restrict__ lo){
    int tb = blockIdx.x;
    int layer = tb / 4192;
    int rt = tb - layer*4192;
    const float* src; int K, N, ntx, perm = 0; long dstoff;
    if      (rt < 256 ){           src = wq  + (size_t)layer*512*512;  K=512;  N=512;  ntx=16;  dstoff=WOF_WQ;  }
    else if (rt < 320 ){ rt-=256;  src = wkv + (size_t)layer*512*128;  K=512;  N=128;  ntx=4;   dstoff=WOF_WKV; }
    else if (rt < 576 ){ rt-=320;  src = wo  + (size_t)layer*512*512;  K=512;  N=512;  ntx=16;  dstoff=WOF_WO;  }
    else if (rt < 832 ){ rt-=576;  src = cwq + (size_t)layer*512*512;  K=512;  N=512;  ntx=16;  dstoff=WOF_CWQ; }
    else if (rt < 864 ){ rt-=832;  src = cwkv+ (size_t)layer*256*128;  K=256;  N=128;  ntx=4;   dstoff=WOF_CWKV;}
    else if (rt < 1120){ rt-=864;  src = cwo + (size_t)layer*512*512;  K=512;  N=512;  ntx=16;  dstoff=WOF_CWO; }
    else if (rt < 3168){ rt-=1120; src = w1  + (size_t)layer*512*4096; K=512;  N=4096; ntx=128; dstoff=WOF_W1; perm=1; }
    else               { rt-=3168; src = w2  + (size_t)layer*2048*512; K=2048; N=512;  ntx=16;  dstoff=WOF_W2;  }
    dstoff += (long)layer * WL;
    int n0 = (rt % ntx)*32, k0 = (rt / ntx)*32;

    __shared__ float tile[32][33];
    int tx = threadIdx.x & 31, ty = threadIdx.x >> 5;
    int cc = n0 + tx;
    int scol = perm ? ((cc>>1) + (cc&1)*FFI) : cc;
    #pragma unroll
    for (int i = 0; i < 4; i++)
        tile[ty + 8*i][tx] = src[(long)(k0 + ty + 8*i)*N + scol];
    __syncthreads();
    #pragma unroll
    for (int i = 0; i < 4; i++){
        int n = ty + 8*i;
        float v = tile[tx][n];
        unsigned short h, l;
        split_bf16(v, h, l);
        long off = dstoff + (long)(n0 + n)*K + k0 + tx;
        hi[off] = __ushort_as_bfloat16(h);
        lo[off] = __ushort_as_bfloat16(l);
    }
}

// ---------------- warp-per-row layernorm family -----------------------------
// 8 warps/block, one row each; cols in {256, 512}
__global__ __launch_bounds__(256) void ln_split_w(const float* __restrict__ in,
                                                  const float* __restrict__ g,
                                                  __nv_bfloat16* __restrict__ hi,
                                                  __nv_bfloat16* __restrict__ lo, int cols){
    int wid = threadIdx.x >> 5, lane = threadIdx.x & 31;
    long row = (long)blockIdx.x*8 + wid;
    const float* p = in + row*cols;
    int nc = cols >> 7;            // float4 chunks per lane (2 or 4)
    float v[16];
    float s = 0.f;
    for (int c = 0; c < nc; c++){
        float4 q = *(const float4*)(p + c*128 + lane*4);
        v[c*4+0]=q.x; v[c*4+1]=q.y; v[c*4+2]=q.z; v[c*4+3]=q.w;
        s += q.x + q.y + q.z + q.w;
    }
    float mu = warpSum(s) / (float)cols;
    float s2 = 0.f;
    for (int c = 0; c < nc*4; c++){ v[c] -= mu; s2 += v[c]*v[c]; }
    float inv = rsqrtf(warpSum(s2) / (float)cols + 1e-5f);
    for (int c = 0; c < nc; c++){
        int col = c*128 + lane*4;
        uint32_t hp0, lp0, hp1, lp1;
        splitpack(v[c*4+0]*inv*g[col],   v[c*4+1]*inv*g[col+1], hp0, lp0);
        splitpack(v[c*4+2]*inv*g[col+2], v[c*4+3]*inv*g[col+3], hp1, lp1);
        uint2 hh; hh.x = hp0; hh.y = hp1;
        uint2 ll; ll.x = lp0; ll.y = lp1;
        *(uint2*)(hi + row*cols + col) = hh;
        *(uint2*)(lo + row*cols + col) = ll;
    }
}
// fused: x += LN_g1(qin); then hi/lo = split(LN_g2(x))  (cols == 512)
__global__ __launch_bounds__(256) void ln_res_split_w(const float* __restrict__ qin,
                                                      const float* __restrict__ g1,
                                                      float* __restrict__ x,
                                                      const float* __restrict__ g2,
                                                      __nv_bfloat16* __restrict__ hi,
                                                      __nv_bfloat16* __restrict__ lo){
    int wid = threadIdx.x >> 5, lane = threadIdx.x & 31;
    long row = (long)blockIdx.x*8 + wid;
    const float* p = qin + row*DD;
    float* px = x + row*DD;
    float v[16];
    float s = 0.f;
    #pragma unroll
    for (int c = 0; c < 4; c++){
        float4 q = *(const float4*)(p + c*128 + lane*4);
        v[c*4+0]=q.x; v[c*4+1]=q.y; v[c*4+2]=q.z; v[c*4+3]=q.w;
        s += q.x + q.y + q.z + q.w;
    }
    float mu = warpSum(s) * (1.f/512.f);
    float s2 = 0.f;
    #pragma unroll
    for (int c = 0; c < 16; c++){ v[c] -= mu; s2 += v[c]*v[c]; }
    float inv = rsqrtf(warpSum(s2) * (1.f/512.f) + 1e-5f);
    float s3 = 0.f;
    #pragma unroll
    for (int c = 0; c < 4; c++){
        int col = c*128 + lane*4;
        float4 xa = *(const float4*)(px + col);
        float4 ga = *(const float4*)(g1 + col);
        xa.x += v[c*4+0]*inv*ga.x; xa.y += v[c*4+1]*inv*ga.y;
        xa.z += v[c*4+2]*inv*ga.z; xa.w += v[c*4+3]*inv*ga.w;
        *(float4*)(px + col) = xa;
        v[c*4+0]=xa.x; v[c*4+1]=xa.y; v[c*4+2]=xa.z; v[c*4+3]=xa.w;
        s3 += xa.x + xa.y + xa.z + xa.w;
    }
    float mu2 = warpSum(s3) * (1.f/512.f);
    float s4 = 0.f;
    #pragma unroll
    for (int c = 0; c < 16; c++){ v[c] -= mu2; s4 += v[c]*v[c]; }
    float inv2 = rsqrtf(warpSum(s4) * (1.f/512.f) + 1e-5f);
    #pragma unroll
    for (int c = 0; c < 4; c++){
        int col = c*128 + lane*4;
        float4 ga = *(const float4*)(g2 + col);
        uint32_t hp0, lp0, hp1, lp1;
        splitpack(v[c*4+0]*inv2*ga.x, v[c*4+1]*inv2*ga.y, hp0, lp0);
        splitpack(v[c*4+2]*inv2*ga.z, v[c*4+3]*inv2*ga.w, hp1, lp1);
        uint2 hh; hh.x = hp0; hh.y = hp1;
        uint2 ll; ll.x = lp0; ll.y = lp1;
        *(uint2*)(hi + row*DD + col) = hh;
        *(uint2*)(lo + row*DD + col) = ll;
    }
}
__global__ __launch_bounds__(256) void final_ln_w(const float* __restrict__ in,
                                                  const float* __restrict__ g,
                                                  float* __restrict__ out){
    int wid = threadIdx.x >> 5, lane = threadIdx.x & 31;
    long row = (long)blockIdx.x*8 + wid;
    const float* p = in + row*DD;
    float v[16];
    float mxl = -3.4e38f;
    #pragma unroll
    for (int c = 0; c < 4; c++){
        float4 q = *(const float4*)(p + c*128 + lane*4);
        v[c*4+0]=q.x; v[c*4+1]=q.y; v[c*4+2]=q.z; v[c*4+3]=q.w;
        mxl = fmaxf(mxl, fmaxf(fmaxf(q.x,q.y), fmaxf(q.z,q.w)));
    }
    float mx = warpMax(mxl);
    float s = 0.f;
    #pragma unroll
    for (int c = 0; c < 16; c++){ v[c] /= mx; s += v[c]; }
    float mu = warpSum(s) * (1.f/512.f);
    float s2 = 0.f;
    #pragma unroll
    for (int c = 0; c < 16; c++){ v[c] -= mu; s2 += v[c]*v[c]; }
    float inv = rsqrtf(warpSum(s2) * (1.f/512.f) + 1e-5f);
    #pragma unroll
    for (int c = 0; c < 4; c++){
        int col = c*128 + lane*4;
        float4 ga = *(const float4*)(g + col);
        float4 o;
        o.x = v[c*4+0]*inv*ga.x; o.y = v[c*4+1]*inv*ga.y;
        o.z = v[c*4+2]*inv*ga.z; o.w = v[c*4+3]*inv*ga.w;
        *(float4*)(out + row*DD + col) = o;
    }
}

// ---------------- cross-attn kv prep (unchanged) ---------------------------
__device__ __forceinline__ float inv_freq(int m){
    return powf(10000.f, -(float)m * (1.f/16.f));
}
__global__ __launch_bounds__(64) void kvprep2(const float* __restrict__ kv, int kvstride,
                                              const float* __restrict__ null_kv,
                                              __nv_bfloat16* __restrict__ KH, __nv_bfloat16* __restrict__ KL,
                                              __nv_bfloat16* __restrict__ VTH, __nv_bfloat16* __restrict__ VTL,
                                              int nk, int use_rot, int padK){
    int rblk = blockIdx.x;
    int d = threadIdx.x;
    int nkv = nk + 1;
    int b = rblk / padK, j = rblk % padK;
    long koff = ((long)b * PADS + j) * DH + d;
    long voff = ((long)b * DH + d) * PW + j;
    if (j >= nkv){
        KH[koff] = __ushort_as_bfloat16(0); KL[koff] = __ushort_as_bfloat16(0);
        VTH[voff] = __ushort_as_bfloat16(0); VTL[voff] = __ushort_as_bfloat16(0);
        return;
    }
    float kval, vval;
    if (j == 0){
        kval = null_kv[d];
        vval = null_kv[DH + d];
    } else {
        int i = j - 1;
        const float* src = kv + ((long)b * nk + i) * kvstride;
        kval = src[d];
        vval = src[DH + d];
        if (use_rot && d < 32){
            int m = d & 15;
            float f = (float)i * inv_freq(m);
            float cf = cosf(f), sf = sinf(f);
            if (d < 16) kval = kval*cf - src[d+16]*sf;
            else        kval = kval*cf + src[d-16]*sf;
        }
    }
    unsigned short h, l;
    split_bf16(kval, h, l);
    KH[koff] = __ushort_as_bfloat16(h); KL[koff] = __ushort_as_bfloat16(l);
    split_bf16(vval, h, l);
    VTH[voff] = __ushort_as_bfloat16(h); VTL[voff] = __ushort_as_bfloat16(l);
}

// ============================================================================
//  mma helpers
// ============================================================================
__device__ __forceinline__ uint32_t smem_u32(const void* p){
    uint32_t a;
    asm("{ .reg .u64 t; cvta.to.shared.u64 t, %1; cvt.u32.u64 %0, t; }" : "=r"(a) : "l"(p));
    return a;
}
__device__ __forceinline__ void cpg(uint32_t sm, const void* g){
    asm volatile("cp.async.cg.shared.global [%0], [%1], 16;" :: "r"(sm), "l"(g));
}
#define CP_COMMIT() asm volatile("cp.async.commit_group;" ::: "memory")
#define CP_WAIT1()  asm volatile("cp.async.wait_group 1;" ::: "memory")
#define CP_WAIT0()  asm volatile("cp.async.wait_group 0;" ::: "memory")
__device__ __forceinline__ void ldsm4(uint32_t* r, uint32_t addr){
    asm volatile("ldmatrix.sync.aligned.m8n8.x4.shared.b16 {%0,%1,%2,%3}, [%4];"
        : "=r"(r[0]),"=r"(r[1]),"=r"(r[2]),"=r"(r[3]) : "r"(addr));
}
__device__ __forceinline__ void mma16816(float* d, const uint32_t* a, uint32_t b0, uint32_t b1){
    asm volatile("mma.sync.aligned.m16n8k16.row.col.f32.bf16.bf16.f32 "
        "{%0,%1,%2,%3}, {%4,%5,%6,%7}, {%8,%9}, {%0,%1,%2,%3};"
        : "+f"(d[0]),"+f"(d[1]),"+f"(d[2]),"+f"(d[3])
        : "r"(a[0]),"r"(a[1]),"r"(a[2]),"r"(a[3]), "r"(b0),"r"(b1));
}
#define SWOFF(r,c)  ((((r)*4 + ((c) ^ (((r)>>1)&3)))) << 4)
#define SWOFF8(r,c) ((((r)*8 + ((c) ^ ((r)&7)))) << 4)

#define COMPUTE_128x128(ss)                                                        \
    _Pragma("unroll")                                                              \
    for (int s = 0; s < 2; s++){                                                   \
        uint32_t ah[4][4], al[4][4], bhf[4][2], blf[4][2];                         \
        _Pragma("unroll")                                                          \
        for (int mt = 0; mt < 4; mt++){                                            \
            int r = wm + mt*16 + (lane & 15);                                      \
            int cl = 2*s + (lane >> 4);                                            \
            uint32_t addr = (ss) + SWOFF(r, cl);                                   \
            ldsm4(ah[mt], addr);                                                   \
            ldsm4(al[mt], addr + 8192);                                            \
        }                                                                          \
        _Pragma("unroll")                                                          \
        for (int g = 0; g < 2; g++){                                               \
            int r = wn + g*16 + (lane & 7) + ((lane >> 4) << 3);                   \
            int cl = 2*s + ((lane >> 3) & 1);                                      \
            uint32_t addr = (ss) + 16384 + SWOFF(r, cl);                           \
            uint32_t tmp[4];                                                       \
            ldsm4(tmp, addr);                                                      \
            bhf[2*g][0]=tmp[0]; bhf[2*g][1]=tmp[1]; bhf[2*g+1][0]=tmp[2]; bhf[2*g+1][1]=tmp[3]; \
            ldsm4(tmp, addr + 8192);                                               \
            blf[2*g][0]=tmp[0]; blf[2*g][1]=tmp[1]; blf[2*g+1][0]=tmp[2]; blf[2*g+1][1]=tmp[3]; \
        }                                                                          \
        _Pragma("unroll")                                                          \
        for (int mt = 0; mt < 4; mt++)                                             \
            _Pragma("unroll")                                                      \
            for (int nt = 0; nt < 4; nt++){                                        \
                mma16816(acc[mt][nt], ah[mt], bhf[nt][0], bhf[nt][1]);             \
                mma16816(acc[mt][nt], ah[mt], blf[nt][0], blf[nt][1]);             \
                mma16816(acc[mt][nt], al[mt], bhf[nt][0], bhf[nt][1]);             \
            }                                                                      \
    }

#define GEMM_PREAMBLE                                                              \
    extern __shared__ __align__(16) char sm[];                                     \
    uint32_t sb = smem_u32(sm);                                                    \
    int t = threadIdx.x, lane = t & 31, warp = t >> 5;                             \
    int wm = (warp >> 2) * 64, wn = (warp & 3) * 32;                               \
    long rowBase = (long)blockIdx.y * 128;                                         \
    long colBase = (long)blockIdx.x * 128;                                         \
    const __nv_bfloat16* srcs[4] = { Ah + rowBase*K, Al + rowBase*K,               \
                                     Bh + colBase*K, Bl + colBase*K };             \
    int lr = t >> 2, lc = t & 3;                                                   \
    float acc[4][4][4];                                                            \
    _Pragma("unroll")                                                              \
    for (int i=0;i<4;i++)                                                          \
        _Pragma("unroll")                                                          \
        for (int j=0;j<4;j++)                                                      \
            _Pragma("unroll")                                                      \
            for (int e=0;e<4;e++) acc[i][j][e] = 0.f;

#define GEMM_MAINLOOP                                                              \
    int nch = K >> 5;                                                              \
    DLOAD(0, 0);                                                                   \
    for (int c = 0; c < nch; c++){                                                 \
        int st = c & 1;                                                            \
        if (c + 1 < nch){ DLOAD((c+1)&1, (c+1)*32); CP_WAIT1(); }                  \
        else CP_WAIT0();                                                           \
        __syncthreads();                                                           \
        uint32_t ss = sb + st*32768;                                               \
        COMPUTE_128x128(ss);                                                       \
        __syncthreads();                                                           \
    }

#define DLOAD(st, k0) do {                                                  \
    _Pragma("unroll")                                                       \
    for (int tt = 0; tt < 4; tt++){                                         \
        const __nv_bfloat16* s = srcs[tt] + (k0);                           \
        uint32_t so = sb + (st)*32768 + tt*8192;                            \
        cpg(so + SWOFF(lr, lc),      s + (long)lr*K + lc*8);                \
        cpg(so + SWOFF(lr+64, lc),   s + (long)(lr+64)*K + lc*8);           \
    }                                                                       \
    CP_COMMIT(); } while(0)

// ---------------- dense GEMM: C = A[MxK] @ B'[NxK]^T (+=C if addC) ----------
__global__ __launch_bounds__(256, 2) void tgemm3(const __nv_bfloat16* __restrict__ Ah,
                                                 const __nv_bfloat16* __restrict__ Al,
                                                 const __nv_bfloat16* __restrict__ Bh,
                                                 const __nv_bfloat16* __restrict__ Bl,
                                                 float* __restrict__ C,
                                                 int M, int N, int K, int addC){
    GEMM_PREAMBLE
    GEMM_MAINLOOP
    #pragma unroll
    for (int mt = 0; mt < 4; mt++){
        long r = rowBase + wm + mt*16 + (lane >> 2);
        #pragma unroll
        for (int nt = 0; nt < 4; nt++){
            long cc = colBase + wn + nt*8 + 2*(lane & 3);
            float2 v0; v0.x = acc[mt][nt][0]; v0.y = acc[mt][nt][1];
            float2 v1; v1.x = acc[mt][nt][2]; v1.y = acc[mt][nt][3];
            float2* p0 = (float2*)(C + r*N + cc);
            float2* p1 = (float2*)(C + (r+8)*N + cc);
            if (addC){
                float2 c0 = *p0, c1 = *p1;
                v0.x += c0.x; v0.y += c0.y;
                v1.x += c1.x; v1.y += c1.y;
            }
            *p0 = v0;
            *p1 = v1;
        }
    }
}

// ---------------- GLU-fused GEMM -------------------------------------------
__global__ __launch_bounds__(256, 2) void tgemm3_glu(const __nv_bfloat16* __restrict__ Ah,
                                                     const __nv_bfloat16* __restrict__ Al,
                                                     const __nv_bfloat16* __restrict__ Bh,
                                                     const __nv_bfloat16* __restrict__ Bl,
                                                     __nv_bfloat16* __restrict__ GH,
                                                     __nv_bfloat16* __restrict__ GL,
                                                     int M, int N, int K){
    GEMM_PREAMBLE
    GEMM_MAINLOOP
    #pragma unroll
    for (int mt = 0; mt < 4; mt++){
        long r = rowBase + wm + mt*16 + (lane >> 2);
        #pragma unroll
        for (int nt = 0; nt < 4; nt++){
            long oc = (colBase + wn + nt*8)/2 + (lane & 3);
            float h0 = acc[mt][nt][0], gg0 = acc[mt][nt][1];
            float h1 = acc[mt][nt][2], gg1 = acc[mt][nt][3];
            float v0 = h0 * (gg0 / (1.f + expf(-gg0)));
            float v1 = h1 * (gg1 / (1.f + expf(-gg1)));
            unsigned short hs, ls;
            split_bf16(v0, hs, ls);
            GH[r*FFI + oc] = __ushort_as_bfloat16(hs);
            GL[r*FFI + oc] = __ushort_as_bfloat16(ls);
            split_bf16(v1, hs, ls);
            GH[(r+8)*FFI + oc] = __ushort_as_bfloat16(hs);
            GL[(r+8)*FFI + oc] = __ushort_as_bfloat16(ls);
        }
    }
}

// ---------------- cross-attn Q GEMM: scale + split epilogue -----------------
__global__ __launch_bounds__(256, 2) void tgemm3_qsplit(const __nv_bfloat16* __restrict__ Ah,
                                                        const __nv_bfloat16* __restrict__ Al,
                                                        const __nv_bfloat16* __restrict__ Bh,
                                                        const __nv_bfloat16* __restrict__ Bl,
                                                        __nv_bfloat16* __restrict__ QH,
                                                        __nv_bfloat16* __restrict__ QL,
                                                        int M, int N, int K){
    GEMM_PREAMBLE
    GEMM_MAINLOOP
    const float sc = 0.125f;
    #pragma unroll
    for (int mt = 0; mt < 4; mt++){
        long r = rowBase + wm + mt*16 + (lane >> 2);
        #pragma unroll
        for (int nt = 0; nt < 4; nt++){
            long cc = colBase + wn + nt*8 + 2*(lane & 3);
            uint32_t hp, lp;
            splitpack(acc[mt][nt][0]*sc, acc[mt][nt][1]*sc, hp, lp);
            *(uint32_t*)(QH + r*N + cc) = hp;
            *(uint32_t*)(QL + r*N + cc) = lp;
            splitpack(acc[mt][nt][2]*sc, acc[mt][nt][3]*sc, hp, lp);
            *(uint32_t*)(QH + (r+8)*N + cc) = hp;
            *(uint32_t*)(QL + (r+8)*N + cc) = lp;
        }
    }
}

// ---------------- self-attn QKV GEMM: rotary/scale/split epilogue -----------
// N = 640: cols [0,512) Q (scale+rot), [512,576) K (rot), [576,640) V^T.
__global__ __launch_bounds__(256, 2) void tgemm3_qkv(const __nv_bfloat16* __restrict__ Ah,
                                                     const __nv_bfloat16* __restrict__ Al,
                                                     const __nv_bfloat16* __restrict__ Bh,
                                                     const __nv_bfloat16* __restrict__ Bl,
                                                     __nv_bfloat16* __restrict__ QH,
                                                     __nv_bfloat16* __restrict__ QL,
                                                     __nv_bfloat16* __restrict__ KHp,
                                                     __nv_bfloat16* __restrict__ KLp,
                                                     __nv_bfloat16* __restrict__ VTH,
                                                     __nv_bfloat16* __restrict__ VTL,
                                                     const float* __restrict__ rotc,
                                                     const float* __restrict__ rots,
                                                     int M, int N, int K){
    GEMM_PREAMBLE
    GEMM_MAINLOOP
    int ccb = (int)colBase + wn;            // warp's 32-col strip base
    int rothalf = ((ccb & 32) == 0);
    #pragma unroll
    for (int mt = 0; mt < 4; mt++){
        long row = rowBase + wm + mt*16 + (lane >> 2);
        int b = (int)(row >> 10);
        int pos = (int)(row & 1023);
        if (ccb < 512){
            const float sc = 0.125f;
            if (rothalf){
                #pragma unroll
                for (int nt = 0; nt < 2; nt++){
                    int cc0 = ccb + nt*8 + 2*(lane & 3);
                    int d0  = nt*8 + 2*(lane & 3);       // < 16
                    #pragma unroll
                    for (int half = 0; half < 2; half++){
                        long rr = row + half*8;
                        int pp = pos + half*8;
                        float a0 = acc[mt][nt][half*2+0]*sc, b0 = acc[mt][nt+2][half*2+0]*sc;
                        float a1 = acc[mt][nt][half*2+1]*sc, b1 = acc[mt][nt+2][half*2+1]*sc;
                        float c0 = rotc[pp*16 + d0],   s0 = rots[pp*16 + d0];
                        float c1 = rotc[pp*16 + d0+1], s1 = rots[pp*16 + d0+1];
                        uint32_t hp, lp;
                        splitpack(a0*c0 - b0*s0, a1*c1 - b1*s1, hp, lp);
                        *(uint32_t*)(QH + rr*DD + cc0) = hp;
                        *(uint32_t*)(QL + rr*DD + cc0) = lp;
                        splitpack(a0*s0 + b0*c0, a1*s1 + b1*c1, hp, lp);
                        *(uint32_t*)(QH + rr*DD + cc0 + 16) = hp;
                        *(uint32_t*)(QL + rr*DD + cc0 + 16) = lp;
                    }
                }
            } else {
                #pragma unroll
                for (int nt = 0; nt < 4; nt++){
                    int cc0 = ccb + nt*8 + 2*(lane & 3);
                    uint32_t hp, lp;
                    splitpack(acc[mt][nt][0]*sc, acc[mt][nt][1]*sc, hp, lp);
                    *(uint32_t*)(QH + row*DD + cc0) = hp;
                    *(uint32_t*)(QL + row*DD + cc0) = lp;
                    splitpack(acc[mt][nt][2]*sc, acc[mt][nt][3]*sc, hp, lp);
                    *(uint32_t*)(QH + (row+8)*DD + cc0) = hp;
                    *(uint32_t*)(QL + (row+8)*DD + cc0) = lp;
                }
            }
        } else if (ccb < 576){
            // K: dest row j = pos+1 (+8 for half=1); no scale
            if (rothalf){
                #pragma unroll
                for (int nt = 0; nt < 2; nt++){
                    int d0 = nt*8 + 2*(lane & 3);        // < 16
                    #pragma unroll
                    for (int half = 0; half < 2; half++){
                        int pp = pos + half*8;
                        long ko = ((long)b*PADS + pp + 1)*DH;
                        float a0 = acc[mt][nt][half*2+0], b0 = acc[mt][nt+2][half*2+0];
                        float a1 = acc[mt][nt][half*2+1], b1 = acc[mt][nt+2][half*2+1];
                        float c0 = rotc[pp*16 + d0],   s0 = rots[pp*16 + d0];
                        float c1 = rotc[pp*16 + d0+1], s1 = rots[pp*16 + d0+1];
                        uint32_t hp, lp;
                        splitpack(a0*c0 - b0*s0, a1*c1 - b1*s1, hp, lp);
                        *(uint32_t*)(KHp + ko + d0) = hp;
                        *(uint32_t*)(KLp + ko + d0) = lp;
                        splitpack(a0*s0 + b0*c0, a1*s1 + b1*c1, hp, lp);
                        *(uint32_t*)(KHp + ko + d0 + 16) = hp;
                        *(uint32_t*)(KLp + ko + d0 + 16) = lp;
                    }
                }
            } else {
                #pragma unroll
                for (int nt = 0; nt < 4; nt++){
                    int d0 = 32 + nt*8 + 2*(lane & 3);
                    #pragma unroll
                    for (int half = 0; half < 2; half++){
                        long ko = ((long)b*PADS + pos + half*8 + 1)*DH;
                        uint32_t hp, lp;
                        splitpack(acc[mt][nt][half*2+0], acc[mt][nt][half*2+1], hp, lp);
                        *(uint32_t*)(KHp + ko + d0) = hp;
                        *(uint32_t*)(KLp + ko + d0) = lp;
                    }
                }
            }
        } else {
            // V^T: VT[(b*64+d)*PW + j], j = pos+1 (+8)
            #pragma unroll
            for (int nt = 0; nt < 4; nt++){
                int d0 = (ccb - 576) + nt*8 + 2*(lane & 3);
                #pragma unroll
                for (int e = 0; e < 4; e++){
                    int d = d0 + (e & 1);
                    long j = pos + (e >> 1)*8 + 1;
                    unsigned short h, l;
                    split_bf16(acc[mt][nt][e], h, l);
                    VTH[((long)b*DH + d)*PW + j] = __ushort_as_bfloat16(h);
                    VTL[((long)b*DH + d)*PW + j] = __ushort_as_bfloat16(l);
                }
            }
        }
    }
}
#undef DLOAD

// ============================================================================
//  Fused flash attention (writes hi/lo bf16 split of O directly)
// ============================================================================
#define FSM_Q  0
#define FSM_K  16384
#define FSM_V  32768
#define FSM_B  49152
#define FSM_TOT (49152 + 4096)

__global__ __launch_bounds__(128) void flash_attn(const __nv_bfloat16* __restrict__ Qh,
                                                  const __nv_bfloat16* __restrict__ Ql,
                                                  const __nv_bfloat16* __restrict__ KHp,
                                                  const __nv_bfloat16* __restrict__ KLp,
                                                  const __nv_bfloat16* __restrict__ VTHp,
                                                  const __nv_bfloat16* __restrict__ VTLp,
                                                  const float* __restrict__ bias_tab,
                                                  __nv_bfloat16* __restrict__ OH,
                                                  __nv_bfloat16* __restrict__ OL,
                                                  int nkv, int cb){
    extern __shared__ __align__(16) char sm[];
    uint32_t sb = smem_u32(sm);
    int t = threadIdx.x, lane = t & 31, warp = t >> 5;
    int bh = blockIdx.y, b = bh >> 3, h = bh & 7;
    int i0 = blockIdx.x * 64;

    {
        const __nv_bfloat16* qh = Qh + ((long)(b*NQ + i0))*DD + h*DH;
        const __nv_bfloat16* ql = Ql + ((long)(b*NQ + i0))*DD + h*DH;
        for (int i = t; i < 512; i += 128){
            int r = i >> 3, c = i & 7;
            cpg(sb + FSM_Q        + SWOFF8(r,c), qh + (long)r*DD + c*8);
            cpg(sb + FSM_Q + 8192 + SWOFF8(r,c), ql + (long)r*DD + c*8);
        }
        CP_COMMIT();
    }
    if (cb){
        float* bsm = (float*)(sm + FSM_B);
        for (int i = t; i < 1024; i += 128) bsm[i] = bias_tab[h*1024 + i];
    }
    CP_WAIT0();
    __syncthreads();

    uint32_t qfh[4][4], qfl[4][4];
    #pragma unroll
    for (int s = 0; s < 4; s++){
        int r = warp*16 + (lane & 15);
        int cl = 2*s + (lane >> 4);
        ldsm4(qfh[s], sb + FSM_Q + SWOFF8(r, cl));
        ldsm4(qfl[s], sb + FSM_Q + 8192 + SWOFF8(r, cl));
    }

    float o[8][4];
    #pragma unroll
    for (int i=0;i<8;i++)
        #pragma unroll
        for (int e=0;e<4;e++) o[i][e] = 0.f;
    float mx0 = -3.0e38f, mx1 = -3.0e38f, sum0 = 0.f, sum1 = 0.f;

    int jt_max = (nkv - 1) >> 6;
    if (cb){ int jm = (i0 + 64) >> 6; if (jm < jt_max) jt_max = jm; }
    const __nv_bfloat16* kh = KHp + (long)b*PADS*DH;
    const __nv_bfloat16* kl = KLp + (long)b*PADS*DH;
    const __nv_bfloat16* vh = VTHp + (long)b*DH*PW;
    const __nv_bfloat16* vl = VTLp + (long)b*DH*PW;
    const float* bsm = (const float*)(sm + FSM_B);

    for (int jt = 0; jt <= jt_max; jt++){
        for (int i = t; i < 512; i += 128){
            int r = i >> 3, c = i & 7;
            cpg(sb + FSM_K        + SWOFF8(r,c), kh + ((long)(jt*64 + r))*DH + c*8);
            cpg(sb + FSM_K + 8192 + SWOFF8(r,c), kl + ((long)(jt*64 + r))*DH + c*8);
        }
        CP_COMMIT();
        for (int i = t; i < 512; i += 128){
            int r = i >> 3, c = i & 7;
            cpg(sb + FSM_V        + SWOFF8(r,c), vh + (long)r*PW + jt*64 + c*8);
            cpg(sb + FSM_V + 8192 + SWOFF8(r,c), vl + (long)r*PW + jt*64 + c*8);
        }
        CP_COMMIT();
        CP_WAIT1();
        __syncthreads();

        float sacc[8][4];
        #pragma unroll
        for (int i=0;i<8;i++)
            #pragma unroll
            for (int e=0;e<4;e++) sacc[i][e] = 0.f;
        #pragma unroll
        for (int s = 0; s < 4; s++){
            uint32_t bhf[8][2], blf[8][2];
            #pragma unroll
            for (int g = 0; g < 4; g++){
                int r = g*16 + (lane & 7) + ((lane >> 4) << 3);
                int cl = 2*s + ((lane >> 3) & 1);
                uint32_t tmp[4];
                ldsm4(tmp, sb + FSM_K + SWOFF8(r, cl));
                bhf[2*g][0]=tmp[0]; bhf[2*g][1]=tmp[1]; bhf[2*g+1][0]=tmp[2]; bhf[2*g+1][1]=tmp[3];
                ldsm4(tmp, sb + FSM_K + 8192 + SWOFF8(r, cl));
                blf[2*g][0]=tmp[0]; blf[2*g][1]=tmp[1]; blf[2*g+1][0]=tmp[2]; blf[2*g+1][1]=tmp[3];
            }
            #pragma unroll
            for (int nt = 0; nt < 8; nt++){
                mma16816(sacc[nt], qfh[s], bhf[nt][0], bhf[nt][1]);
                mma16816(sacc[nt], qfh[s], blf[nt][0], blf[nt][1]);
                mma16816(sacc[nt], qfl[s], bhf[nt][0], bhf[nt][1]);
            }
        }

        int ibase = i0 + warp*16 + (lane >> 2);
        int jbase = jt*64 + 2*(lane & 3);
        float tmx0 = -3.0e38f, tmx1 = -3.0e38f;
        #pragma unroll
        for (int nt = 0; nt < 8; nt++){
            #pragma unroll
            for (int e = 0; e < 4; e++){
                int i = ibase + ((e >> 1) << 3);
                int j = jbase + nt*8 + (e & 1);
                float s = sacc[nt][e];
                if (cb){
                    int nn = i - j; if (nn < 0) nn = 0;
                    s += bsm[nn];
                    if (j > i + 1) s = -1e30f;
                }
                if (j >= nkv) s = -1e30f;
                sacc[nt][e] = s;
                if (e < 2) tmx0 = fmaxf(tmx0, s); else tmx1 = fmaxf(tmx1, s);
            }
        }
        tmx0 = fmaxf(tmx0, __shfl_xor_sync(0xffffffffu, tmx0, 1));
        tmx0 = fmaxf(tmx0, __shfl_xor_sync(0xffffffffu, tmx0, 2));
        tmx1 = fmaxf(tmx1, __shfl_xor_sync(0xffffffffu, tmx1, 1));
        tmx1 = fmaxf(tmx1, __shfl_xor_sync(0xffffffffu, tmx1, 2));
        float nmx0 = fmaxf(mx0, tmx0), nmx1 = fmaxf(mx1, tmx1);
        float al0 = expf(mx0 - nmx0), al1 = expf(mx1 - nmx1);
        mx0 = nmx0; mx1 = nmx1;
        sum0 *= al0; sum1 *= al1;
        #pragma unroll
        for (int nt = 0; nt < 8; nt++){
            o[nt][0] *= al0; o[nt][1] *= al0;
            o[nt][2] *= al1; o[nt][3] *= al1;
        }

        CP_WAIT0();
        __syncthreads();

        float ts0 = 0.f, ts1 = 0.f;
        #pragma unroll
        for (int kg = 0; kg < 4; kg++){
            uint32_t phf[4], plf[4];
            #pragma unroll
            for (int half = 0; half < 2; half++){
                int nt = 2*kg + half;
                unsigned short hb[4], lb[4];
                #pragma unroll
                for (int e = 0; e < 4; e++){
                    float pe = expf(sacc[nt][e] - ((e < 2) ? mx0 : mx1));
                    if (e < 2) ts0 += pe; else ts1 += pe;
                    split_bf16(pe, hb[e], lb[e]);
                }
                phf[2*half+0] = (uint32_t)hb[0] | ((uint32_t)hb[1] << 16);
                phf[2*half+1] = (uint32_t)hb[2] | ((uint32_t)hb[3] << 16);
                plf[2*half+0] = (uint32_t)lb[0] | ((uint32_t)lb[1] << 16);
                plf[2*half+1] = (uint32_t)lb[2] | ((uint32_t)lb[3] << 16);
            }
            uint32_t vhf[8][2], vlf[8][2];
            #pragma unroll
            for (int g = 0; g < 4; g++){
                int r = g*16 + (lane & 7) + ((lane >> 4) << 3);
                int cl = 2*kg + ((lane >> 3) & 1);
                uint32_t tmp[4];
                ldsm4(tmp, sb + FSM_V + SWOFF8(r, cl));
                vhf[2*g][0]=tmp[0]; vhf[2*g][1]=tmp[1]; vhf[2*g+1][0]=tmp[2]; vhf[2*g+1][1]=tmp[3];
                ldsm4(tmp, sb + FSM_V + 8192 + SWOFF8(r, cl));
                vlf[2*g][0]=tmp[0]; vlf[2*g][1]=tmp[1]; vlf[2*g+1][0]=tmp[2]; vlf[2*g+1][1]=tmp[3];
            }
            #pragma unroll
            for (int nt = 0; nt < 8; nt++){
                mma16816(o[nt], phf, vhf[nt][0], vhf[nt][1]);
                mma16816(o[nt], phf, vlf[nt][0], vlf[nt][1]);
                mma16816(o[nt], plf, vhf[nt][0], vhf[nt][1]);
            }
        }
        ts0 += __shfl_xor_sync(0xffffffffu, ts0, 1);
        ts0 += __shfl_xor_sync(0xffffffffu, ts0, 2);
        ts1 += __shfl_xor_sync(0xffffffffu, ts1, 1);
        ts1 += __shfl_xor_sync(0xffffffffu, ts1, 2);
        sum0 += ts0; sum1 += ts1;
        __syncthreads();
    }

    float inv0 = 1.f / sum0, inv1 = 1.f / sum1;
    long r0 = (long)b*NQ + i0 + warp*16 + (lane >> 2);
    #pragma unroll
    for (int nt = 0; nt < 8; nt++){
        int c = nt*8 + 2*(lane & 3);
        uint32_t hp, lp;
        splitpack(o[nt][0]*inv0, o[nt][1]*inv0, hp, lp);
        *(uint32_t*)(OH + r0*DD + h*DH + c) = hp;
        *(uint32_t*)(OL + r0*DD + h*DH + c) = lp;
        splitpack(o[nt][2]*inv1, o[nt][3]*inv1, hp, lp);
        *(uint32_t*)(OH + (r0+8)*DD + h*DH + c) = hp;
        *(uint32_t*)(OL + (r0+8)*DD + h*DH + c) = lp;
    }
}

// ---------------- orchestration --------------------------------------------
extern "C" void kernel_launch(void* const* d_in, const int* in_sizes, int n_in,
                              void* d_out, int out_size){
    const float* x_in    = (const float*)d_in[0];
    const float* ctx     = (const float*)d_in[1];
    const float* rel_emb = (const float*)d_in[2];
    const float* sa_ng   = (const float*)d_in[3];
    const float* sa_wq   = (const float*)d_in[4];
    const float* sa_wkv  = (const float*)d_in[5];
    const float* sa_null = (const float*)d_in[6];
    const float* sa_wo   = (const float*)d_in[7];
    const float* sa_og   = (const float*)d_in[8];
    const float* ca_ng   = (const float*)d_in[9];
    const float* ca_cg   = (const float*)d_in[10];
    const float* ca_wq   = (const float*)d_in[11];
    const float* ca_wkv  = (const float*)d_in[12];
    const float* ca_null = (const float*)d_in[13];
    const float* ca_wo   = (const float*)d_in[14];
    const float* ca_og   = (const float*)d_in[15];
    const float* ff_ng   = (const float*)d_in[16];
    const float* ff_w1   = (const float*)d_in[17];
    const float* ff_w2   = (const float*)d_in[18];
    const float* normg   = (const float*)d_in[19];
    float* out = (float*)d_out;

    cudaFuncSetAttribute(tgemm3,        cudaFuncAttributeMaxDynamicSharedMemorySize, 65536);
    cudaFuncSetAttribute(tgemm3_glu,    cudaFuncAttributeMaxDynamicSharedMemorySize, 65536);
    cudaFuncSetAttribute(tgemm3_qsplit, cudaFuncAttributeMaxDynamicSharedMemorySize, 65536);
    cudaFuncSetAttribute(tgemm3_qkv,    cudaFuncAttributeMaxDynamicSharedMemorySize, 65536);
    cudaFuncSetAttribute(flash_attn,    cudaFuncAttributeMaxDynamicSharedMemorySize, FSM_TOT);

    float *X,*QO,*KV,*BT,*RC,*RS;
    __nv_bfloat16 *AH,*AL,*GH,*GL,*BH,*BL,*KH,*KL,*VTH,*VTL;
    cudaGetSymbolAddress((void**)&X,    g_x);
    cudaGetSymbolAddress((void**)&QO,   g_q);
    cudaGetSymbolAddress((void**)&KV,   g_kv);
    cudaGetSymbolAddress((void**)&BT,   g_bias);
    cudaGetSymbolAddress((void**)&RC,   g_rotc);
    cudaGetSymbolAddress((void**)&RS,   g_rots);
    cudaGetSymbolAddress((void**)&AH,   g_AH);
    cudaGetSymbolAddress((void**)&AL,   g_AL);
    cudaGetSymbolAddress((void**)&GH,   g_GH);
    cudaGetSymbolAddress((void**)&GL,   g_GL);
    cudaGetSymbolAddress((void**)&BH,   g_BH);
    cudaGetSymbolAddress((void**)&BL,   g_BL);
    cudaGetSymbolAddress((void**)&KH,   g_KH);
    cudaGetSymbolAddress((void**)&KL,   g_KL);
    cudaGetSymbolAddress((void**)&VTH,  g_VTH);
    cudaGetSymbolAddress((void**)&VTL,  g_VTL);
    // activation split regions inside g_AH/g_AL (8M elems each):
    __nv_bfloat16 *XQH = AH,                         *XQL = AL;                        // [0,2M)  LN(x) split
    __nv_bfloat16 *ATH = AH + (size_t)2*1024*1024,   *ATL = AL + (size_t)2*1024*1024;  // [2M,4M) ATT split
    __nv_bfloat16 *CXH = AH + (size_t)4*1024*1024,   *CXL = AL + (size_t)4*1024*1024;  // [4M,5M) ctx split
    __nv_bfloat16 *QSH = AH + (size_t)5*1024*1024,   *QSL = AL + (size_t)5*1024*1024;  // [5M,7M) Q split

    copy_kernel<<<512, 256>>>(x_in, X, RR*DD);
    bias_tab_kernel<<<4, 256>>>(rel_emb, BT);
    rot_tab_kernel<<<64, 256>>>(RC, RS);
    convBT_all<<<LL*4192, 256>>>(sa_wq, sa_wkv, sa_wo, ca_wq, ca_wkv, ca_wo,
                                 ff_w1, ff_w2, BH, BL);

    for (int l = 0; l < LL; l++){
        const __nv_bfloat16 *WBH = BH + (size_t)l*WL, *WBL = BL + (size_t)l*WL;

        // ---------------- self-attention (fully fused QKV prep) -----------
        ln_split_w<<<RR/8, 256>>>(X, sa_ng + l*DD, XQH, XQL, DD);
        tgemm3_qkv<<<dim3(QW/128, RR/128), 256, 65536>>>(XQH, XQL, WBH + WOF_WQ, WBL + WOF_WQ,
                                                         QSH, QSL, KH, KL, VTH, VTL, RC, RS, RR, QW, DD);
        nullkv_kernel<<<BB, 64>>>(sa_null + l*128, KH, KL, VTH, VTL);
        flash_attn<<<dim3(NQ/64, BB*HH), 128, FSM_TOT>>>(QSH, QSL, KH, KL, VTH, VTL, BT, ATH, ATL, NQ+1, 1);
        tgemm3<<<dim3(DD/128, RR/128), 256, 65536>>>(ATH, ATL, WBH + WOF_WO, WBL + WOF_WO, QO, RR, DD, DD, 0);
        ln_res_split_w<<<RR/8, 256>>>(QO, sa_og + l*DD, X, ca_ng + l*DD, XQH, XQL);

        // ---------------- cross-attention ----------------
        ln_split_w<<<CR/8, 256>>>(ctx, ca_cg + l*PP, CXH, CXL, PP);
        tgemm3_qsplit<<<dim3(DD/128, RR/128), 256, 65536>>>(XQH, XQL, WBH + WOF_CWQ, WBL + WOF_CWQ,
                                                            QSH, QSL, RR, DD, DD);
        tgemm3<<<dim3(1, CR/128), 256, 65536>>>(CXH, CXL, WBH + WOF_CWKV, WBL + WOF_CWKV, KV, CR, 128, PP, 0);
        kvprep2<<<BB*640, 64>>>(KV, 128, ca_null + l*128, KH, KL, VTH, VTL, MM, 0, 640);
        flash_attn<<<dim3(NQ/64, BB*HH), 128, FSM_TOT>>>(QSH, QSL, KH, KL, VTH, VTL, BT, ATH, ATL, MM+1, 0);
        tgemm3<<<dim3(DD/128, RR/128), 256, 65536>>>(ATH, ATL, WBH + WOF_CWO, WBL + WOF_CWO, QO, RR, DD, DD, 0);
        ln_res_split_w<<<RR/8, 256>>>(QO, ca_og + l*DD, X, ff_ng + l*DD, XQH, XQL);

        // ---------------- feed-forward (GLU fused into w1 GEMM) ------------
        tgemm3_glu<<<dim3((2*FFI)/128, RR/128), 256, 65536>>>(XQH, XQL, WBH + WOF_W1, WBL + WOF_W1,
                                                              GH, GL, RR, 2*FFI, DD);
        tgemm3<<<dim3(DD/128, RR/128), 256, 65536>>>(GH, GL, WBH + WOF_W2, WBL + WOF_W2, X, RR, DD, FFI, 1);
    }

    final_ln_w<<<RR/8, 256>>>(X, normg, out);
}